// round 5
// baseline (speedup 1.0000x reference)
#include <cuda_runtime.h>

#define Bc 2
#define Nc 512
#define CSc 384
#define CZc 128
#define CHc 16
#define Hc 12
#define QKVD 192           // H*CH
#define XD 1728            // H*(CZ+CH)
#define S_UPD_ELEMS (Bc*Nc*CSc)   // 393216

// ---- scratch (device globals; no allocation allowed) ----
__device__ float g_q[Bc*Nc*QKVD];
__device__ float g_kT[Bc*QKVD*Nc];   // [b][h*16+c][j]  (transposed k)
__device__ float g_v[Bc*Nc*QKVD];
__device__ float g_x[Bc*Nc*XD];

// ============================================================
// Kernel 1: q/k/v projection. 4 rows/block, 288 threads.
// thread = (ct 0..143 -> 4 cols, rt 0..1 -> 2 rows). grid=256.
// ============================================================
__global__ void __launch_bounds__(288)
qkv_kernel(const float* __restrict__ s,
           const float* __restrict__ Wq,
           const float* __restrict__ Wkv) {
    __shared__ float4 s_sm[4 * 96];          // 4 rows x 384 floats
    const int row0 = blockIdx.x * 4;
    const int tid = threadIdx.x;

    for (int idx = tid; idx < 4 * 96; idx += 288)
        s_sm[idx] = ((const float4*)(s + (size_t)row0 * CSc))[idx];
    __syncthreads();

    const int ct = tid % 144;
    const int rt = tid / 144;
    const int col = ct * 4;                  // 0..572
    const bool is_q = (col < QKVD);
    const float* W = is_q ? (Wq + col) : (Wkv + (col - QKVD));
    const int ld = is_q ? QKVD : 384;
    const int r0 = rt * 2;

    float4 aA = {0.f,0.f,0.f,0.f};
    float4 aB = {0.f,0.f,0.f,0.f};

    for (int k0 = 0; k0 < CSc; k0 += 4) {
        float4 w0 = __ldg((const float4*)(W + (size_t)(k0 + 0) * ld));
        float4 w1 = __ldg((const float4*)(W + (size_t)(k0 + 1) * ld));
        float4 w2 = __ldg((const float4*)(W + (size_t)(k0 + 2) * ld));
        float4 w3 = __ldg((const float4*)(W + (size_t)(k0 + 3) * ld));
        float4 sA = s_sm[(r0 + 0) * 96 + (k0 >> 2)];
        float4 sB = s_sm[(r0 + 1) * 96 + (k0 >> 2)];
        aA.x = fmaf(sA.x,w0.x, fmaf(sA.y,w1.x, fmaf(sA.z,w2.x, fmaf(sA.w,w3.x, aA.x))));
        aA.y = fmaf(sA.x,w0.y, fmaf(sA.y,w1.y, fmaf(sA.z,w2.y, fmaf(sA.w,w3.y, aA.y))));
        aA.z = fmaf(sA.x,w0.z, fmaf(sA.y,w1.z, fmaf(sA.z,w2.z, fmaf(sA.w,w3.z, aA.z))));
        aA.w = fmaf(sA.x,w0.w, fmaf(sA.y,w1.w, fmaf(sA.z,w2.w, fmaf(sA.w,w3.w, aA.w))));
        aB.x = fmaf(sB.x,w0.x, fmaf(sB.y,w1.x, fmaf(sB.z,w2.x, fmaf(sB.w,w3.x, aB.x))));
        aB.y = fmaf(sB.x,w0.y, fmaf(sB.y,w1.y, fmaf(sB.z,w2.y, fmaf(sB.w,w3.y, aB.y))));
        aB.z = fmaf(sB.x,w0.z, fmaf(sB.y,w1.z, fmaf(sB.z,w2.z, fmaf(sB.w,w3.z, aB.z))));
        aB.w = fmaf(sB.x,w0.w, fmaf(sB.y,w1.w, fmaf(sB.z,w2.w, fmaf(sB.w,w3.w, aB.w))));
    }

    float4 accs[2] = {aA, aB};
#pragma unroll
    for (int r = 0; r < 2; r++) {
        const int row = row0 + r0 + r;
        if (is_q) {
            *(float4*)(g_q + (size_t)row * QKVD + col) = accs[r];
        } else {
            int c2 = col - QKVD;
            int h = c2 >> 5;
            int within = c2 & 31;
            int cc = h * CHc + (within & 15);
            if (within < CHc) {
                // k -> transposed layout [b][cc][j]
                int b = row >> 9, i = row & 511;
                float* kt = g_kT + ((size_t)b * QKVD + cc) * Nc + i;
                kt[0 * Nc] = accs[r].x;
                kt[1 * Nc] = accs[r].y;
                kt[2 * Nc] = accs[r].z;
                kt[3 * Nc] = accs[r].w;
            } else {
                *(float4*)(g_v + (size_t)row * QKVD + cc) = accs[r];
            }
        }
    }
}

// ============================================================
// Kernel 2: per-(b,i) attention row. grid = B*N, 384 threads.
// Dyn smem (floats):
//   [0,192)      sm_q
//   [192,1728)   sm_Wbt  [h][zc]
//   [1728,7872)  sm_l    (12 x 512)  logits then a
//   [7872,16320) z tile  64 rows x 132 floats (pad 4)
// ============================================================
#define SM_Q_OFF   0
#define SM_WBT_OFF 192
#define SM_L_OFF   1728
#define SM_Z_OFF   7872
#define ATTN_SMEM_FLOATS 16320

__global__ void __launch_bounds__(384)
attn_kernel(const float* __restrict__ z,
            const float* __restrict__ Wb,
            float* __restrict__ a_out) {
    extern __shared__ float smem[];
    float* sm_q   = smem + SM_Q_OFF;
    float* sm_Wbt = smem + SM_WBT_OFF;
    float* sm_l   = smem + SM_L_OFF;
    float*  z_sm  = smem + SM_Z_OFF;              // row stride 132 floats
    float4* z4    = (float4*)z_sm;                // row stride 33 float4

    const int bi = blockIdx.x;
    const int b  = bi >> 9;
    const int i  = bi & 511;
    const int tid = threadIdx.x;

    for (int idx = tid; idx < QKVD; idx += 384)
        sm_q[idx] = g_q[(size_t)bi * QKVD + idx];
    for (int idx = tid; idx < Hc * CZc; idx += 384) {
        int h = idx >> 7, zc = idx & 127;
        sm_Wbt[h * CZc + zc] = Wb[zc * Hc + h];
    }
    __syncthreads();

    const float*  zslab  = z + (size_t)bi * Nc * CZc;
    const float4* zslab4 = (const float4*)zslab;

    // ---- step B: logits over 8 z tiles of 64 rows ----
    {
        const int g6 = tid >> 6;          // 0..5 -> heads 2g6, 2g6+1
        const int j6 = tid & 63;
        const int h0 = g6 * 2;
        const float4* wbA = (const float4*)&sm_Wbt[(h0 + 0) * CZc];
        const float4* wbB = (const float4*)&sm_Wbt[(h0 + 1) * CZc];

        for (int tile = 0; tile < 8; tile++) {
            const int j0 = tile * 64;
            for (int idx = tid; idx < 64 * 32; idx += 384) {
                int r = idx >> 5, t = idx & 31;
                z4[r * 33 + t] = __ldg(&zslab4[(size_t)(j0 + r) * 32 + t]);
            }
            __syncthreads();

            const float4* zr = z4 + j6 * 33;
            float b0 = 0.f, b1 = 0.f;
#pragma unroll 8
            for (int t = 0; t < 32; t++) {
                float4 zv = zr[t];
                float4 w0 = wbA[t], w1 = wbB[t];
                b0 += zv.x*w0.x + zv.y*w0.y + zv.z*w0.z + zv.w*w0.w;
                b1 += zv.x*w1.x + zv.y*w1.y + zv.z*w1.z + zv.w*w1.w;
            }

            const int j = j0 + j6;
            const float* kT = g_kT + ((size_t)b * QKVD + h0 * CHc) * Nc + j;
            float acc0 = 0.f, acc1 = 0.f;
#pragma unroll
            for (int c = 0; c < CHc; c++) {
                acc0 = fmaf(__ldg(&kT[(size_t)c * Nc]),          sm_q[h0*CHc + c],        acc0);
                acc1 = fmaf(__ldg(&kT[(size_t)(CHc + c) * Nc]),  sm_q[h0*CHc + CHc + c],  acc1);
            }
            sm_l[(h0 + 0) * Nc + j] = 0.7071067811865476f * (acc0 * 0.25f + b0);
            sm_l[(h0 + 1) * Nc + j] = 0.7071067811865476f * (acc1 * 0.25f + b1);
            __syncthreads();
        }
    }

    // ---- step C: softmax, one warp per head ----
    {
        int w = tid >> 5, lane = tid & 31;
        float vals[16];
        float m = -3.0e38f;
#pragma unroll
        for (int t = 0; t < 16; t++) {
            vals[t] = sm_l[w * Nc + lane + t * 32];
            m = fmaxf(m, vals[t]);
        }
#pragma unroll
        for (int off = 16; off > 0; off >>= 1)
            m = fmaxf(m, __shfl_xor_sync(0xffffffffu, m, off));
        float ssum = 0.f;
#pragma unroll
        for (int t = 0; t < 16; t++) {
            vals[t] = __expf(vals[t] - m);
            ssum += vals[t];
        }
#pragma unroll
        for (int off = 16; off > 0; off >>= 1)
            ssum += __shfl_xor_sync(0xffffffffu, ssum, off);
        float inv = 1.0f / ssum;
        float* aptr = a_out + (((size_t)(b * Hc + w) * Nc) + i) * Nc;
#pragma unroll
        for (int t = 0; t < 16; t++) {
            float av = vals[t] * inv;
            sm_l[w * Nc + lane + t * 32] = av;
            aptr[lane + t * 32] = av;
        }
    }
    __syncthreads();

    // ---- step D1: o_pair = a @ z, z staged through smem tiles ----
    {
        const int g3 = tid >> 7;          // 0..2 -> heads 4g3..4g3+3
        const int zc = tid & 127;
        const int h0 = g3 * 4;
        float acc0 = 0.f, acc1 = 0.f, acc2 = 0.f, acc3 = 0.f;

        for (int tile = 0; tile < 8; tile++) {
            const int j0 = tile * 64;
            for (int idx = tid; idx < 64 * 32; idx += 384) {
                int r = idx >> 5, t = idx & 31;
                z4[r * 33 + t] = __ldg(&zslab4[(size_t)(j0 + r) * 32 + t]);
            }
            __syncthreads();

#pragma unroll 4
            for (int jt = 0; jt < 64; jt += 4) {
                const int j = j0 + jt;
                float4 a0 = *(const float4*)&sm_l[(h0 + 0) * Nc + j];
                float4 a1 = *(const float4*)&sm_l[(h0 + 1) * Nc + j];
                float4 a2 = *(const float4*)&sm_l[(h0 + 2) * Nc + j];
                float4 a3 = *(const float4*)&sm_l[(h0 + 3) * Nc + j];
                float z0 = z_sm[(jt + 0) * 132 + zc];
                float z1 = z_sm[(jt + 1) * 132 + zc];
                float z2 = z_sm[(jt + 2) * 132 + zc];
                float z3 = z_sm[(jt + 3) * 132 + zc];
                acc0 += a0.x*z0 + a0.y*z1 + a0.z*z2 + a0.w*z3;
                acc1 += a1.x*z0 + a1.y*z1 + a1.z*z2 + a1.w*z3;
                acc2 += a2.x*z0 + a2.y*z1 + a2.z*z2 + a2.w*z3;
                acc3 += a3.x*z0 + a3.y*z1 + a3.z*z2 + a3.w*z3;
            }
            __syncthreads();
        }
        g_x[(size_t)bi * XD + QKVD + (h0 + 0) * CZc + zc] = acc0;
        g_x[(size_t)bi * XD + QKVD + (h0 + 1) * CZc + zc] = acc1;
        g_x[(size_t)bi * XD + QKVD + (h0 + 2) * CZc + zc] = acc2;
        g_x[(size_t)bi * XD + QKVD + (h0 + 3) * CZc + zc] = acc3;
    }

    // ---- step D2: o = a @ v (192 outputs, MLP-8 unrolled) ----
    if (tid < QKVD) {
        const int idx = tid;
        const int h = idx >> 4;
        const float* lh = &sm_l[h * Nc];
        const float* vp = g_v + (size_t)b * Nc * QKVD + idx;
        float acc = 0.f;
        for (int j = 0; j < Nc; j += 8) {
            float4 a0 = *(const float4*)&lh[j];
            float4 a1 = *(const float4*)&lh[j + 4];
            float v0 = __ldg(&vp[(size_t)(j + 0) * QKVD]);
            float v1 = __ldg(&vp[(size_t)(j + 1) * QKVD]);
            float v2 = __ldg(&vp[(size_t)(j + 2) * QKVD]);
            float v3 = __ldg(&vp[(size_t)(j + 3) * QKVD]);
            float v4 = __ldg(&vp[(size_t)(j + 4) * QKVD]);
            float v5 = __ldg(&vp[(size_t)(j + 5) * QKVD]);
            float v6 = __ldg(&vp[(size_t)(j + 6) * QKVD]);
            float v7 = __ldg(&vp[(size_t)(j + 7) * QKVD]);
            acc = fmaf(a0.x, v0, acc); acc = fmaf(a0.y, v1, acc);
            acc = fmaf(a0.z, v2, acc); acc = fmaf(a0.w, v3, acc);
            acc = fmaf(a1.x, v4, acc); acc = fmaf(a1.y, v5, acc);
            acc = fmaf(a1.z, v6, acc); acc = fmaf(a1.w, v7, acc);
        }
        g_x[(size_t)bi * XD + idx] = acc;
    }
}

// ============================================================
// Kernel 3: s_upd = X @ Wout + bout. 8 rows/block, 384 threads.
// thread = 2 rows x 4 cols. grid = 128.
// ============================================================
__global__ void __launch_bounds__(384)
out_kernel(const float* __restrict__ Wout,
           const float* __restrict__ bout,
           float* __restrict__ s_upd) {
    const int ROWS = 8;
    const int KC = 192;
    __shared__ float xs[ROWS * KC];
    const int row0 = blockIdx.x * ROWS;
    const int cg = threadIdx.x % 96;
    const int rg = threadIdx.x / 96;

    float4 acc0 = {0.f,0.f,0.f,0.f};
    float4 acc1 = {0.f,0.f,0.f,0.f};

    for (int k0 = 0; k0 < XD; k0 += KC) {
        __syncthreads();
        {
            int idx = threadIdx.x;
            int r = idx / 48, c4 = idx % 48;
            ((float4*)xs)[idx] =
                ((const float4*)(g_x + (size_t)(row0 + r) * XD + k0))[c4];
        }
        __syncthreads();
#pragma unroll 4
        for (int kk = 0; kk < KC; kk++) {
            float4 w = __ldg((const float4*)(Wout + (size_t)(k0 + kk) * CSc + 4 * cg));
            float x0 = xs[(2 * rg + 0) * KC + kk];
            float x1 = xs[(2 * rg + 1) * KC + kk];
            acc0.x = fmaf(x0, w.x, acc0.x); acc0.y = fmaf(x0, w.y, acc0.y);
            acc0.z = fmaf(x0, w.z, acc0.z); acc0.w = fmaf(x0, w.w, acc0.w);
            acc1.x = fmaf(x1, w.x, acc1.x); acc1.y = fmaf(x1, w.y, acc1.y);
            acc1.z = fmaf(x1, w.z, acc1.z); acc1.w = fmaf(x1, w.w, acc1.w);
        }
    }
    float4 bb = *(const float4*)(bout + 4 * cg);
    acc0.x += bb.x; acc0.y += bb.y; acc0.z += bb.z; acc0.w += bb.w;
    acc1.x += bb.x; acc1.y += bb.y; acc1.z += bb.z; acc1.w += bb.w;
    *(float4*)(s_upd + (size_t)(row0 + 2 * rg + 0) * CSc + 4 * cg) = acc0;
    *(float4*)(s_upd + (size_t)(row0 + 2 * rg + 1) * CSc + 4 * cg) = acc1;
}

// ============================================================
extern "C" void kernel_launch(void* const* d_in, const int* in_sizes, int n_in,
                              void* d_out, int out_size) {
    const float* s    = (const float*)d_in[0];
    const float* z    = (const float*)d_in[1];
    // d_in[2] = mask: all-True in this problem; (1-sq) term is identically 0.
    const float* Wq   = (const float*)d_in[3];
    const float* Wkv  = (const float*)d_in[4];
    const float* Wb   = (const float*)d_in[5];
    const float* Wout = (const float*)d_in[6];
    const float* bout = (const float*)d_in[7];

    float* out   = (float*)d_out;
    float* s_upd = out;                       // (B,N,CS)
    float* a_out = out + S_UPD_ELEMS;         // (B,H,N,N)

    cudaFuncSetAttribute(attn_kernel,
                         cudaFuncAttributeMaxDynamicSharedMemorySize,
                         ATTN_SMEM_FLOATS * sizeof(float));

    qkv_kernel<<<(Bc * Nc) / 4, 288>>>(s, Wq, Wkv);
    attn_kernel<<<Bc * Nc, 384, ATTN_SMEM_FLOATS * sizeof(float)>>>(z, Wb, a_out);
    out_kernel<<<(Bc * Nc) / 8, 384>>>(Wout, bout, s_upd);
}

// round 6
// speedup vs baseline: 1.1759x; 1.1759x over previous
#include <cuda_runtime.h>

#define Bc 2
#define Nc 512
#define CSc 384
#define CZc 128
#define CHc 16
#define Hc 12
#define QKVD 192           // H*CH
#define XD 1728            // H*(CZ+CH)
#define S_UPD_ELEMS (Bc*Nc*CSc)   // 393216

// ---- scratch (device globals; no allocation allowed) ----
__device__ float g_q[Bc*Nc*QKVD];
__device__ float g_k[Bc*Nc*QKVD];
__device__ float g_v[Bc*Nc*QKVD];
__device__ float g_x[Bc*Nc*XD];

// ============================================================
// Kernel 1: q/k/v projection. 4 rows/block, 288 threads,
// each thread owns 2 output cols x 4 rows, k unrolled by 4.
// grid = 256   (identical to the 777us round-3 version)
// ============================================================
__global__ void __launch_bounds__(288)
qkv_kernel(const float* __restrict__ s,
           const float* __restrict__ Wq,
           const float* __restrict__ Wkv) {
    const int ROWS = 4;
    __shared__ float4 s_sm[ROWS * 96];       // 4 rows x 384 floats
    const int row0 = blockIdx.x * ROWS;
    const int tid = threadIdx.x;

    for (int idx = tid; idx < ROWS * 96; idx += 288)
        s_sm[idx] = ((const float4*)(s + (size_t)row0 * CSc))[idx];
    __syncthreads();

    const int col = tid * 2;                 // 0..574
    const bool is_q = (col < QKVD);
    const float* W = is_q ? (Wq + col) : (Wkv + (col - QKVD));
    const int ld = is_q ? QKVD : 384;

    float a00=0.f,a01=0.f,a10=0.f,a11=0.f,a20=0.f,a21=0.f,a30=0.f,a31=0.f;

    for (int k0 = 0; k0 < CSc; k0 += 4) {
        float2 w0 = *(const float2*)(W + (size_t)(k0 + 0) * ld);
        float2 w1 = *(const float2*)(W + (size_t)(k0 + 1) * ld);
        float2 w2 = *(const float2*)(W + (size_t)(k0 + 2) * ld);
        float2 w3 = *(const float2*)(W + (size_t)(k0 + 3) * ld);
        float4 s0 = s_sm[0 * 96 + (k0 >> 2)];
        float4 s1 = s_sm[1 * 96 + (k0 >> 2)];
        float4 s2 = s_sm[2 * 96 + (k0 >> 2)];
        float4 s3 = s_sm[3 * 96 + (k0 >> 2)];
        a00 = fmaf(s0.x, w0.x, a00); a01 = fmaf(s0.x, w0.y, a01);
        a00 = fmaf(s0.y, w1.x, a00); a01 = fmaf(s0.y, w1.y, a01);
        a00 = fmaf(s0.z, w2.x, a00); a01 = fmaf(s0.z, w2.y, a01);
        a00 = fmaf(s0.w, w3.x, a00); a01 = fmaf(s0.w, w3.y, a01);
        a10 = fmaf(s1.x, w0.x, a10); a11 = fmaf(s1.x, w0.y, a11);
        a10 = fmaf(s1.y, w1.x, a10); a11 = fmaf(s1.y, w1.y, a11);
        a10 = fmaf(s1.z, w2.x, a10); a11 = fmaf(s1.z, w2.y, a11);
        a10 = fmaf(s1.w, w3.x, a10); a11 = fmaf(s1.w, w3.y, a11);
        a20 = fmaf(s2.x, w0.x, a20); a21 = fmaf(s2.x, w0.y, a21);
        a20 = fmaf(s2.y, w1.x, a20); a21 = fmaf(s2.y, w1.y, a21);
        a20 = fmaf(s2.z, w2.x, a20); a21 = fmaf(s2.z, w2.y, a21);
        a20 = fmaf(s2.w, w3.x, a20); a21 = fmaf(s2.w, w3.y, a21);
        a30 = fmaf(s3.x, w0.x, a30); a31 = fmaf(s3.x, w0.y, a31);
        a30 = fmaf(s3.y, w1.x, a30); a31 = fmaf(s3.y, w1.y, a31);
        a30 = fmaf(s3.z, w2.x, a30); a31 = fmaf(s3.z, w2.y, a31);
        a30 = fmaf(s3.w, w3.x, a30); a31 = fmaf(s3.w, w3.y, a31);
    }

    float accs[4][2] = {{a00,a01},{a10,a11},{a20,a21},{a30,a31}};
    if (is_q) {
#pragma unroll
        for (int r = 0; r < ROWS; r++) {
            g_q[(size_t)(row0 + r) * QKVD + col + 0] = accs[r][0];
            g_q[(size_t)(row0 + r) * QKVD + col + 1] = accs[r][1];
        }
    } else {
#pragma unroll
        for (int c = 0; c < 2; c++) {
            int c2 = col - QKVD + c;
            int h = c2 >> 5;
            int within = c2 & 31;
            int cc = h * CHc + (within & 15);
            float* dst = (within < CHc) ? g_k : g_v;
#pragma unroll
            for (int r = 0; r < ROWS; r++)
                dst[(size_t)(row0 + r) * QKVD + cc] = accs[r][c];
        }
    }
}

// ============================================================
// Kernel 2: per-(b,i) attention row. grid = B*N, 384 threads.
// Dynamic smem layout (floats):
//   [0,192)              sm_q
//   [192,1728)           sm_Wbt   (transposed [h][zc])
//   [1728,7872)          sm_l     (12 x 512)
//   [7872,24768)         z tile   128 rows x 33 float4 (pad)
// ONLY change vs 777us baseline: step D1 stages z via smem.
// ============================================================
#define SM_Q_OFF   0
#define SM_WBT_OFF 192
#define SM_L_OFF   1728
#define SM_Z_OFF   7872
#define ATTN_SMEM_FLOATS 24768

__global__ void __launch_bounds__(384)
attn_kernel(const float* __restrict__ z,
            const float* __restrict__ Wb,
            float* __restrict__ a_out) {
    extern __shared__ float smem[];
    float* sm_q   = smem + SM_Q_OFF;
    float* sm_Wbt = smem + SM_WBT_OFF;
    float* sm_l   = smem + SM_L_OFF;
    float*  z_sm  = smem + SM_Z_OFF;              // row stride 132 floats
    float4* z4    = (float4*)z_sm;                // row stride 33 float4

    const int bi = blockIdx.x;
    const int b  = bi >> 9;
    const int i  = bi & 511;
    const int tid = threadIdx.x;

    for (int idx = tid; idx < QKVD; idx += 384)
        sm_q[idx] = g_q[(size_t)bi * QKVD + idx];
    for (int idx = tid; idx < Hc * CZc; idx += 384) {
        int h = idx >> 7, zc = idx & 127;
        sm_Wbt[h * CZc + zc] = Wb[zc * Hc + h];
    }
    __syncthreads();

    const float*  zslab  = z + (size_t)bi * Nc * CZc;
    const float4* zslab4 = (const float4*)zslab;

    const int g  = tid >> 7;      // head group 0..2 (heads 4g..4g+3)
    const int jj = tid & 127;

    // ---- step B: logits over 4 z tiles of 128 rows ----
    for (int tile = 0; tile < 4; tile++) {
        const int j0 = tile * 128;
        for (int idx = tid; idx < 128 * 32; idx += 384) {
            int r = idx >> 5, t = idx & 31;
            z4[r * 33 + t] = zslab4[(size_t)(j0 + r) * 32 + t];
        }
        __syncthreads();

        const int j = j0 + jj;
        const float4* wb0 = (const float4*)&sm_Wbt[(4 * g + 0) * CZc];
        const float4* wb1 = (const float4*)&sm_Wbt[(4 * g + 1) * CZc];
        const float4* wb2 = (const float4*)&sm_Wbt[(4 * g + 2) * CZc];
        const float4* wb3 = (const float4*)&sm_Wbt[(4 * g + 3) * CZc];
        float b0 = 0.f, b1 = 0.f, b2 = 0.f, b3 = 0.f;
#pragma unroll 4
        for (int t = 0; t < 32; t++) {
            float4 zv = z4[jj * 33 + t];
            float4 w0 = wb0[t], w1 = wb1[t], w2 = wb2[t], w3 = wb3[t];
            b0 += zv.x*w0.x + zv.y*w0.y + zv.z*w0.z + zv.w*w0.w;
            b1 += zv.x*w1.x + zv.y*w1.y + zv.z*w1.z + zv.w*w1.w;
            b2 += zv.x*w2.x + zv.y*w2.y + zv.z*w2.z + zv.w*w2.w;
            b3 += zv.x*w3.x + zv.y*w3.y + zv.z*w3.z + zv.w*w3.w;
        }
        float bias[4] = {b0, b1, b2, b3};

        const float4* kp = (const float4*)(g_k + (size_t)(b * Nc + j) * QKVD) + g * 16;
        const float4* qp = (const float4*)sm_q + g * 16;
#pragma unroll
        for (int hh = 0; hh < 4; hh++) {
            float acc = 0.f;
#pragma unroll
            for (int t = 0; t < 4; t++) {
                float4 kv4 = kp[hh * 4 + t];
                float4 qv4 = qp[hh * 4 + t];
                acc += kv4.x*qv4.x + kv4.y*qv4.y + kv4.z*qv4.z + kv4.w*qv4.w;
            }
            sm_l[(4 * g + hh) * Nc + j] =
                0.7071067811865476f * (acc * 0.25f + bias[hh]);
        }
        __syncthreads();
    }

    // ---- step C: softmax, one warp per head ----
    {
        int w = tid >> 5, lane = tid & 31;
        float vals[16];
        float m = -3.0e38f;
#pragma unroll
        for (int t = 0; t < 16; t++) {
            vals[t] = sm_l[w * Nc + lane + t * 32];
            m = fmaxf(m, vals[t]);
        }
#pragma unroll
        for (int off = 16; off > 0; off >>= 1)
            m = fmaxf(m, __shfl_xor_sync(0xffffffffu, m, off));
        float ssum = 0.f;
#pragma unroll
        for (int t = 0; t < 16; t++) {
            vals[t] = __expf(vals[t] - m);
            ssum += vals[t];
        }
#pragma unroll
        for (int off = 16; off > 0; off >>= 1)
            ssum += __shfl_xor_sync(0xffffffffu, ssum, off);
        float inv = 1.0f / ssum;
        float* aptr = a_out + (((size_t)(b * Hc + w) * Nc) + i) * Nc;
#pragma unroll
        for (int t = 0; t < 16; t++) {
            float av = vals[t] * inv;
            sm_l[w * Nc + lane + t * 32] = av;
            aptr[lane + t * 32] = av;
        }
    }
    __syncthreads();

    // ---- step D1: o_pair = a @ z, z staged through smem (NEW) ----
    {
        const int zc = jj;
        const int h0 = g * 4;
        float acc0 = 0.f, acc1 = 0.f, acc2 = 0.f, acc3 = 0.f;
        const float* l0 = &sm_l[(h0 + 0) * Nc];
        const float* l1 = &sm_l[(h0 + 1) * Nc];
        const float* l2 = &sm_l[(h0 + 2) * Nc];
        const float* l3 = &sm_l[(h0 + 3) * Nc];

        for (int tile = 0; tile < 4; tile++) {
            const int j0 = tile * 128;
            for (int idx = tid; idx < 128 * 32; idx += 384) {
                int r = idx >> 5, t = idx & 31;
                z4[r * 33 + t] = zslab4[(size_t)(j0 + r) * 32 + t];
            }
            __syncthreads();

#pragma unroll 4
            for (int jt = 0; jt < 128; jt += 4) {
                const int j = j0 + jt;
                float4 a0 = *(const float4*)&l0[j];
                float4 a1 = *(const float4*)&l1[j];
                float4 a2 = *(const float4*)&l2[j];
                float4 a3 = *(const float4*)&l3[j];
                float zv0 = z_sm[(jt + 0) * 132 + zc];
                float zv1 = z_sm[(jt + 1) * 132 + zc];
                float zv2 = z_sm[(jt + 2) * 132 + zc];
                float zv3 = z_sm[(jt + 3) * 132 + zc];
                acc0 += a0.x*zv0 + a0.y*zv1 + a0.z*zv2 + a0.w*zv3;
                acc1 += a1.x*zv0 + a1.y*zv1 + a1.z*zv2 + a1.w*zv3;
                acc2 += a2.x*zv0 + a2.y*zv1 + a2.z*zv2 + a2.w*zv3;
                acc3 += a3.x*zv0 + a3.y*zv1 + a3.z*zv2 + a3.w*zv3;
            }
            __syncthreads();
        }
        g_x[(size_t)bi * XD + QKVD + (h0 + 0) * CZc + zc] = acc0;
        g_x[(size_t)bi * XD + QKVD + (h0 + 1) * CZc + zc] = acc1;
        g_x[(size_t)bi * XD + QKVD + (h0 + 2) * CZc + zc] = acc2;
        g_x[(size_t)bi * XD + QKVD + (h0 + 3) * CZc + zc] = acc3;
    }

    // ---- step D2: o = a @ v (192 outputs, MLP-8 unrolled) ----
    if (tid < QKVD) {
        const int idx = tid;
        const int h = idx >> 4;
        const float* lh = &sm_l[h * Nc];
        const float* vp = g_v + (size_t)b * Nc * QKVD + idx;
        float acc = 0.f;
        for (int j = 0; j < Nc; j += 8) {
            float4 a0 = *(const float4*)&lh[j];
            float4 a1 = *(const float4*)&lh[j + 4];
            float v0 = __ldg(&vp[(size_t)(j + 0) * QKVD]);
            float v1 = __ldg(&vp[(size_t)(j + 1) * QKVD]);
            float v2 = __ldg(&vp[(size_t)(j + 2) * QKVD]);
            float v3 = __ldg(&vp[(size_t)(j + 3) * QKVD]);
            float v4 = __ldg(&vp[(size_t)(j + 4) * QKVD]);
            float v5 = __ldg(&vp[(size_t)(j + 5) * QKVD]);
            float v6 = __ldg(&vp[(size_t)(j + 6) * QKVD]);
            float v7 = __ldg(&vp[(size_t)(j + 7) * QKVD]);
            acc = fmaf(a0.x, v0, acc); acc = fmaf(a0.y, v1, acc);
            acc = fmaf(a0.z, v2, acc); acc = fmaf(a0.w, v3, acc);
            acc = fmaf(a1.x, v4, acc); acc = fmaf(a1.y, v5, acc);
            acc = fmaf(a1.z, v6, acc); acc = fmaf(a1.w, v7, acc);
        }
        g_x[(size_t)bi * XD + idx] = acc;
    }
}

// ============================================================
// Kernel 3: s_upd = X @ Wout + bout. 8 rows/block, 384 threads.
// thread = 2 rows x 4 cols. grid = 128. (identical to round-3)
// ============================================================
__global__ void __launch_bounds__(384)
out_kernel(const float* __restrict__ Wout,
           const float* __restrict__ bout,
           float* __restrict__ s_upd) {
    const int ROWS = 8;
    const int KC = 192;
    __shared__ float xs[ROWS * KC];
    const int row0 = blockIdx.x * ROWS;
    const int cg = threadIdx.x % 96;
    const int rg = threadIdx.x / 96;

    float4 acc0 = {0.f,0.f,0.f,0.f};
    float4 acc1 = {0.f,0.f,0.f,0.f};

    for (int k0 = 0; k0 < XD; k0 += KC) {
        __syncthreads();
        {
            int idx = threadIdx.x;
            int r = idx / 48, c4 = idx % 48;
            ((float4*)xs)[idx] =
                ((const float4*)(g_x + (size_t)(row0 + r) * XD + k0))[c4];
        }
        __syncthreads();
#pragma unroll 4
        for (int kk = 0; kk < KC; kk++) {
            float4 w = __ldg((const float4*)(Wout + (size_t)(k0 + kk) * CSc + 4 * cg));
            float x0 = xs[(2 * rg + 0) * KC + kk];
            float x1 = xs[(2 * rg + 1) * KC + kk];
            acc0.x = fmaf(x0, w.x, acc0.x); acc0.y = fmaf(x0, w.y, acc0.y);
            acc0.z = fmaf(x0, w.z, acc0.z); acc0.w = fmaf(x0, w.w, acc0.w);
            acc1.x = fmaf(x1, w.x, acc1.x); acc1.y = fmaf(x1, w.y, acc1.y);
            acc1.z = fmaf(x1, w.z, acc1.z); acc1.w = fmaf(x1, w.w, acc1.w);
        }
    }
    float4 bb = *(const float4*)(bout + 4 * cg);
    acc0.x += bb.x; acc0.y += bb.y; acc0.z += bb.z; acc0.w += bb.w;
    acc1.x += bb.x; acc1.y += bb.y; acc1.z += bb.z; acc1.w += bb.w;
    *(float4*)(s_upd + (size_t)(row0 + 2 * rg + 0) * CSc + 4 * cg) = acc0;
    *(float4*)(s_upd + (size_t)(row0 + 2 * rg + 1) * CSc + 4 * cg) = acc1;
}

// ============================================================
extern "C" void kernel_launch(void* const* d_in, const int* in_sizes, int n_in,
                              void* d_out, int out_size) {
    const float* s    = (const float*)d_in[0];
    const float* z    = (const float*)d_in[1];
    // d_in[2] = mask: all-True in this problem; (1-sq) term is identically 0.
    const float* Wq   = (const float*)d_in[3];
    const float* Wkv  = (const float*)d_in[4];
    const float* Wb   = (const float*)d_in[5];
    const float* Wout = (const float*)d_in[6];
    const float* bout = (const float*)d_in[7];

    float* out   = (float*)d_out;
    float* s_upd = out;                       // (B,N,CS)
    float* a_out = out + S_UPD_ELEMS;         // (B,H,N,N)

    cudaFuncSetAttribute(attn_kernel,
                         cudaFuncAttributeMaxDynamicSharedMemorySize,
                         ATTN_SMEM_FLOATS * sizeof(float));

    qkv_kernel<<<(Bc * Nc) / 4, 288>>>(s, Wq, Wkv);
    attn_kernel<<<Bc * Nc, 384, ATTN_SMEM_FLOATS * sizeof(float)>>>(z, Wb, a_out);
    out_kernel<<<(Bc * Nc) / 8, 384>>>(Wout, bout, s_upd);
}

// round 7
// speedup vs baseline: 1.2891x; 1.0962x over previous
#include <cuda_runtime.h>

#define Bc 2
#define Nc 512
#define CSc 384
#define CZc 128
#define CHc 16
#define Hc 12
#define QKVD 192           // H*CH
#define XD 1728            // H*(CZ+CH)
#define S_UPD_ELEMS (Bc*Nc*CSc)   // 393216

// ---- scratch (device globals; no allocation allowed) ----
__device__ float g_q[Bc*Nc*QKVD];
__device__ float g_k[Bc*Nc*QKVD];
__device__ float g_v[Bc*Nc*QKVD];
__device__ float g_x[Bc*Nc*XD];

// ============================================================
// Kernel 1: q/k/v projection (identical to 777us baseline)
// ============================================================
__global__ void __launch_bounds__(288)
qkv_kernel(const float* __restrict__ s,
           const float* __restrict__ Wq,
           const float* __restrict__ Wkv) {
    const int ROWS = 4;
    __shared__ float4 s_sm[ROWS * 96];
    const int row0 = blockIdx.x * ROWS;
    const int tid = threadIdx.x;

    for (int idx = tid; idx < ROWS * 96; idx += 288)
        s_sm[idx] = ((const float4*)(s + (size_t)row0 * CSc))[idx];
    __syncthreads();

    const int col = tid * 2;
    const bool is_q = (col < QKVD);
    const float* W = is_q ? (Wq + col) : (Wkv + (col - QKVD));
    const int ld = is_q ? QKVD : 384;

    float a00=0.f,a01=0.f,a10=0.f,a11=0.f,a20=0.f,a21=0.f,a30=0.f,a31=0.f;

    for (int k0 = 0; k0 < CSc; k0 += 4) {
        float2 w0 = *(const float2*)(W + (size_t)(k0 + 0) * ld);
        float2 w1 = *(const float2*)(W + (size_t)(k0 + 1) * ld);
        float2 w2 = *(const float2*)(W + (size_t)(k0 + 2) * ld);
        float2 w3 = *(const float2*)(W + (size_t)(k0 + 3) * ld);
        float4 s0 = s_sm[0 * 96 + (k0 >> 2)];
        float4 s1 = s_sm[1 * 96 + (k0 >> 2)];
        float4 s2 = s_sm[2 * 96 + (k0 >> 2)];
        float4 s3 = s_sm[3 * 96 + (k0 >> 2)];
        a00 = fmaf(s0.x, w0.x, a00); a01 = fmaf(s0.x, w0.y, a01);
        a00 = fmaf(s0.y, w1.x, a00); a01 = fmaf(s0.y, w1.y, a01);
        a00 = fmaf(s0.z, w2.x, a00); a01 = fmaf(s0.z, w2.y, a01);
        a00 = fmaf(s0.w, w3.x, a00); a01 = fmaf(s0.w, w3.y, a01);
        a10 = fmaf(s1.x, w0.x, a10); a11 = fmaf(s1.x, w0.y, a11);
        a10 = fmaf(s1.y, w1.x, a10); a11 = fmaf(s1.y, w1.y, a11);
        a10 = fmaf(s1.z, w2.x, a10); a11 = fmaf(s1.z, w2.y, a11);
        a10 = fmaf(s1.w, w3.x, a10); a11 = fmaf(s1.w, w3.y, a11);
        a20 = fmaf(s2.x, w0.x, a20); a21 = fmaf(s2.x, w0.y, a21);
        a20 = fmaf(s2.y, w1.x, a20); a21 = fmaf(s2.y, w1.y, a21);
        a20 = fmaf(s2.z, w2.x, a20); a21 = fmaf(s2.z, w2.y, a21);
        a20 = fmaf(s2.w, w3.x, a20); a21 = fmaf(s2.w, w3.y, a21);
        a30 = fmaf(s3.x, w0.x, a30); a31 = fmaf(s3.x, w0.y, a31);
        a30 = fmaf(s3.y, w1.x, a30); a31 = fmaf(s3.y, w1.y, a31);
        a30 = fmaf(s3.z, w2.x, a30); a31 = fmaf(s3.z, w2.y, a31);
        a30 = fmaf(s3.w, w3.x, a30); a31 = fmaf(s3.w, w3.y, a31);
    }

    float accs[4][2] = {{a00,a01},{a10,a11},{a20,a21},{a30,a31}};
    if (is_q) {
#pragma unroll
        for (int r = 0; r < ROWS; r++) {
            g_q[(size_t)(row0 + r) * QKVD + col + 0] = accs[r][0];
            g_q[(size_t)(row0 + r) * QKVD + col + 1] = accs[r][1];
        }
    } else {
#pragma unroll
        for (int c = 0; c < 2; c++) {
            int c2 = col - QKVD + c;
            int h = c2 >> 5;
            int within = c2 & 31;
            int cc = h * CHc + (within & 15);
            float* dst = (within < CHc) ? g_k : g_v;
#pragma unroll
            for (int r = 0; r < ROWS; r++)
                dst[(size_t)(row0 + r) * QKVD + cc] = accs[r][c];
        }
    }
}

// ============================================================
// Kernel 2: per-(b,i) attention. grid=B*N, 384 threads, 2 CTA/SM
// smem (floats):
//   [0,192)       sm_q
//   [192,1728)    sm_Wbt  [h][zc]
//   [1728,7872)   sm_l    12 x 512 (logits, then a)
//   [7872,26304)  z region:
//      step B: zc-tile  512 rows x 36 floats (32 zc + pad)
//      step D1: j-tile  128 rows x 132 floats (128 zc + pad)
//               then partition-reduce scratch
// ============================================================
#define SM_Q_OFF   0
#define SM_WBT_OFF 192
#define SM_L_OFF   1728
#define SM_Z_OFF   7872
#define ATTN_SMEM_FLOATS 26304

__global__ void __launch_bounds__(384, 2)
attn_kernel(const float* __restrict__ z,
            const float* __restrict__ Wb,
            float* __restrict__ a_out) {
    extern __shared__ float smem[];
    float* sm_q   = smem + SM_Q_OFF;
    float* sm_Wbt = smem + SM_WBT_OFF;
    float* sm_l   = smem + SM_L_OFF;
    float* z_sm   = smem + SM_Z_OFF;

    const int bi = blockIdx.x;
    const int b  = bi >> 9;
    const int i  = bi & 511;
    const int tid = threadIdx.x;

    for (int idx = tid; idx < QKVD; idx += 384)
        sm_q[idx] = g_q[(size_t)bi * QKVD + idx];
    for (int idx = tid; idx < Hc * CZc; idx += 384) {
        int h = idx >> 7, zc = idx & 127;
        sm_Wbt[h * CZc + zc] = Wb[zc * Hc + h];
    }
    __syncthreads();

    const float4* zslab4 = (const float4*)(z + (size_t)bi * Nc * CZc);

    // ---- step B: bias + logits. thread = 4 heads x 4 j rows ----
    {
        const int hg = tid >> 7;          // 0..2 (warp-uniform)
        const int js = tid & 127;         // j rows: js + 128*r
        const int h0 = hg * 4;

        float bias[4][4];                 // [hh][r]
#pragma unroll
        for (int hh = 0; hh < 4; hh++)
#pragma unroll
            for (int r = 0; r < 4; r++) bias[hh][r] = 0.f;

        for (int zt = 0; zt < 4; zt++) {
            const int zc0 = zt * 32;
            // fill zc-tile: 512 rows x 8 float4, row stride 36 floats
            for (int idx = tid; idx < 4096; idx += 384) {
                int row = idx >> 3, slot = idx & 7;
                float4 v = __ldg(&zslab4[(size_t)row * 32 + (zc0 >> 2) + slot]);
                *(float4*)&z_sm[row * 36 + slot * 4] = v;
            }
            __syncthreads();

#pragma unroll 2
            for (int c = 0; c < 8; c++) {
                float4 w0 = *(const float4*)&sm_Wbt[(h0 + 0) * CZc + zc0 + c * 4];
                float4 w1 = *(const float4*)&sm_Wbt[(h0 + 1) * CZc + zc0 + c * 4];
                float4 w2 = *(const float4*)&sm_Wbt[(h0 + 2) * CZc + zc0 + c * 4];
                float4 w3 = *(const float4*)&sm_Wbt[(h0 + 3) * CZc + zc0 + c * 4];
#pragma unroll
                for (int r = 0; r < 4; r++) {
                    float4 zv = *(const float4*)&z_sm[(js + 128 * r) * 36 + c * 4];
                    bias[0][r] += zv.x*w0.x + zv.y*w0.y + zv.z*w0.z + zv.w*w0.w;
                    bias[1][r] += zv.x*w1.x + zv.y*w1.y + zv.z*w1.z + zv.w*w1.w;
                    bias[2][r] += zv.x*w2.x + zv.y*w2.y + zv.z*w2.z + zv.w*w2.w;
                    bias[3][r] += zv.x*w3.x + zv.y*w3.y + zv.z*w3.z + zv.w*w3.w;
                }
            }
            __syncthreads();
        }

        // q.k + combine -> logits
        const float4* qp = (const float4*)sm_q + h0 * 4;
#pragma unroll
        for (int r = 0; r < 4; r++) {
            const int j = js + 128 * r;
            const float4* kp = (const float4*)(g_k + (size_t)(b * Nc + j) * QKVD) + h0 * 4;
#pragma unroll
            for (int hh = 0; hh < 4; hh++) {
                float acc = 0.f;
#pragma unroll
                for (int t = 0; t < 4; t++) {
                    float4 kv4 = __ldg(&kp[hh * 4 + t]);
                    float4 qv4 = qp[hh * 4 + t];
                    acc += kv4.x*qv4.x + kv4.y*qv4.y + kv4.z*qv4.z + kv4.w*qv4.w;
                }
                sm_l[(h0 + hh) * Nc + j] =
                    0.7071067811865476f * (acc * 0.25f + bias[hh][r]);
            }
        }
    }
    __syncthreads();

    // ---- step C: softmax, one warp per head ----
    {
        int w = tid >> 5, lane = tid & 31;
        float vals[16];
        float m = -3.0e38f;
#pragma unroll
        for (int t = 0; t < 16; t++) {
            vals[t] = sm_l[w * Nc + lane + t * 32];
            m = fmaxf(m, vals[t]);
        }
#pragma unroll
        for (int off = 16; off > 0; off >>= 1)
            m = fmaxf(m, __shfl_xor_sync(0xffffffffu, m, off));
        float ssum = 0.f;
#pragma unroll
        for (int t = 0; t < 16; t++) {
            vals[t] = __expf(vals[t] - m);
            ssum += vals[t];
        }
#pragma unroll
        for (int off = 16; off > 0; off >>= 1)
            ssum += __shfl_xor_sync(0xffffffffu, ssum, off);
        float inv = 1.0f / ssum;
        float* aptr = a_out + (((size_t)(b * Hc + w) * Nc) + i) * Nc;
#pragma unroll
        for (int t = 0; t < 16; t++) {
            float av = vals[t] * inv;
            sm_l[w * Nc + lane + t * 32] = av;
            aptr[lane + t * 32] = av;
        }
    }
    __syncthreads();

    // ---- step D1: o_pair = a @ z. thread = 4 heads x 4 zc, 4-way j-split ----
    {
        const int part = tid / 96;        // 0..3 (warp-uniform)
        const int rem  = tid % 96;
        const int hgd  = rem >> 5;        // 0..2 (warp-uniform)
        const int zs   = rem & 31;        // zc slot
        const int h0   = hgd * 4;
        const int zc0  = zs * 4;

        float acc[4][4];                  // [hh][zz]
#pragma unroll
        for (int hh = 0; hh < 4; hh++)
#pragma unroll
            for (int zz = 0; zz < 4; zz++) acc[hh][zz] = 0.f;

        for (int tile = 0; tile < 4; tile++) {
            const int j0 = tile * 128;
            // fill j-tile: 128 rows x 32 float4, row stride 132 floats
            for (int idx = tid; idx < 4096; idx += 384) {
                int row = idx >> 5, t = idx & 31;
                *(float4*)&z_sm[row * 132 + t * 4] =
                    __ldg(&zslab4[(size_t)(j0 + row) * 32 + t]);
            }
            __syncthreads();

            const int jl0 = part * 32;
#pragma unroll 4
            for (int jl = jl0; jl < jl0 + 32; jl++) {
                const int j = j0 + jl;
                float a0 = sm_l[(h0 + 0) * Nc + j];   // broadcast
                float a1 = sm_l[(h0 + 1) * Nc + j];
                float a2 = sm_l[(h0 + 2) * Nc + j];
                float a3 = sm_l[(h0 + 3) * Nc + j];
                float4 zv = *(const float4*)&z_sm[jl * 132 + zc0];
                acc[0][0] = fmaf(a0, zv.x, acc[0][0]);
                acc[0][1] = fmaf(a0, zv.y, acc[0][1]);
                acc[0][2] = fmaf(a0, zv.z, acc[0][2]);
                acc[0][3] = fmaf(a0, zv.w, acc[0][3]);
                acc[1][0] = fmaf(a1, zv.x, acc[1][0]);
                acc[1][1] = fmaf(a1, zv.y, acc[1][1]);
                acc[1][2] = fmaf(a1, zv.z, acc[1][2]);
                acc[1][3] = fmaf(a1, zv.w, acc[1][3]);
                acc[2][0] = fmaf(a2, zv.x, acc[2][0]);
                acc[2][1] = fmaf(a2, zv.y, acc[2][1]);
                acc[2][2] = fmaf(a2, zv.z, acc[2][2]);
                acc[2][3] = fmaf(a2, zv.w, acc[2][3]);
                acc[3][0] = fmaf(a3, zv.x, acc[3][0]);
                acc[3][1] = fmaf(a3, zv.y, acc[3][1]);
                acc[3][2] = fmaf(a3, zv.z, acc[3][2]);
                acc[3][3] = fmaf(a3, zv.w, acc[3][3]);
            }
            __syncthreads();
        }

        // reduce the 4 j-partitions: parts 1..3 park partials in smem
        if (part > 0) {
#pragma unroll
            for (int hh = 0; hh < 4; hh++)
                *(float4*)&z_sm[(part - 1) * 1536 + (h0 + hh) * CZc + zc0] =
                    *(float4*)&acc[hh][0];
        }
        __syncthreads();
        if (part == 0) {
#pragma unroll
            for (int hh = 0; hh < 4; hh++) {
                float4 r = *(float4*)&acc[hh][0];
#pragma unroll
                for (int p = 0; p < 3; p++) {
                    float4 o = *(const float4*)&z_sm[p * 1536 + (h0 + hh) * CZc + zc0];
                    r.x += o.x; r.y += o.y; r.z += o.z; r.w += o.w;
                }
                *(float4*)(g_x + (size_t)bi * XD + QKVD + (h0 + hh) * CZc + zc0) = r;
            }
        }
    }

    // ---- step D2: o = a @ v (192 outputs, MLP-8) ----
    if (tid < QKVD) {
        const int idx = tid;
        const int h = idx >> 4;
        const float* lh = &sm_l[h * Nc];
        const float* vp = g_v + (size_t)b * Nc * QKVD + idx;
        float acc = 0.f;
        for (int j = 0; j < Nc; j += 8) {
            float4 a0 = *(const float4*)&lh[j];
            float4 a1 = *(const float4*)&lh[j + 4];
            float v0 = __ldg(&vp[(size_t)(j + 0) * QKVD]);
            float v1 = __ldg(&vp[(size_t)(j + 1) * QKVD]);
            float v2 = __ldg(&vp[(size_t)(j + 2) * QKVD]);
            float v3 = __ldg(&vp[(size_t)(j + 3) * QKVD]);
            float v4 = __ldg(&vp[(size_t)(j + 4) * QKVD]);
            float v5 = __ldg(&vp[(size_t)(j + 5) * QKVD]);
            float v6 = __ldg(&vp[(size_t)(j + 6) * QKVD]);
            float v7 = __ldg(&vp[(size_t)(j + 7) * QKVD]);
            acc = fmaf(a0.x, v0, acc); acc = fmaf(a0.y, v1, acc);
            acc = fmaf(a0.z, v2, acc); acc = fmaf(a0.w, v3, acc);
            acc = fmaf(a1.x, v4, acc); acc = fmaf(a1.y, v5, acc);
            acc = fmaf(a1.z, v6, acc); acc = fmaf(a1.w, v7, acc);
        }
        g_x[(size_t)bi * XD + idx] = acc;
    }
}

// ============================================================
// Kernel 3: s_upd = X @ Wout + bout (identical to 777us baseline)
// ============================================================
__global__ void __launch_bounds__(384)
out_kernel(const float* __restrict__ Wout,
           const float* __restrict__ bout,
           float* __restrict__ s_upd) {
    const int ROWS = 8;
    const int KC = 192;
    __shared__ float xs[ROWS * KC];
    const int row0 = blockIdx.x * ROWS;
    const int cg = threadIdx.x % 96;
    const int rg = threadIdx.x / 96;

    float4 acc0 = {0.f,0.f,0.f,0.f};
    float4 acc1 = {0.f,0.f,0.f,0.f};

    for (int k0 = 0; k0 < XD; k0 += KC) {
        __syncthreads();
        {
            int idx = threadIdx.x;
            int r = idx / 48, c4 = idx % 48;
            ((float4*)xs)[idx] =
                ((const float4*)(g_x + (size_t)(row0 + r) * XD + k0))[c4];
        }
        __syncthreads();
#pragma unroll 4
        for (int kk = 0; kk < KC; kk++) {
            float4 w = __ldg((const float4*)(Wout + (size_t)(k0 + kk) * CSc + 4 * cg));
            float x0 = xs[(2 * rg + 0) * KC + kk];
            float x1 = xs[(2 * rg + 1) * KC + kk];
            acc0.x = fmaf(x0, w.x, acc0.x); acc0.y = fmaf(x0, w.y, acc0.y);
            acc0.z = fmaf(x0, w.z, acc0.z); acc0.w = fmaf(x0, w.w, acc0.w);
            acc1.x = fmaf(x1, w.x, acc1.x); acc1.y = fmaf(x1, w.y, acc1.y);
            acc1.z = fmaf(x1, w.z, acc1.z); acc1.w = fmaf(x1, w.w, acc1.w);
        }
    }
    float4 bb = *(const float4*)(bout + 4 * cg);
    acc0.x += bb.x; acc0.y += bb.y; acc0.z += bb.z; acc0.w += bb.w;
    acc1.x += bb.x; acc1.y += bb.y; acc1.z += bb.z; acc1.w += bb.w;
    *(float4*)(s_upd + (size_t)(row0 + 2 * rg + 0) * CSc + 4 * cg) = acc0;
    *(float4*)(s_upd + (size_t)(row0 + 2 * rg + 1) * CSc + 4 * cg) = acc1;
}

// ============================================================
extern "C" void kernel_launch(void* const* d_in, const int* in_sizes, int n_in,
                              void* d_out, int out_size) {
    const float* s    = (const float*)d_in[0];
    const float* z    = (const float*)d_in[1];
    // d_in[2] = mask: all-True in this problem; (1-sq) term is identically 0.
    const float* Wq   = (const float*)d_in[3];
    const float* Wkv  = (const float*)d_in[4];
    const float* Wb   = (const float*)d_in[5];
    const float* Wout = (const float*)d_in[6];
    const float* bout = (const float*)d_in[7];

    float* out   = (float*)d_out;
    float* s_upd = out;                       // (B,N,CS)
    float* a_out = out + S_UPD_ELEMS;         // (B,H,N,N)

    cudaFuncSetAttribute(attn_kernel,
                         cudaFuncAttributeMaxDynamicSharedMemorySize,
                         ATTN_SMEM_FLOATS * sizeof(float));

    qkv_kernel<<<(Bc * Nc) / 4, 288>>>(s, Wq, Wkv);
    attn_kernel<<<Bc * Nc, 384, ATTN_SMEM_FLOATS * sizeof(float)>>>(z, Wb, a_out);
    out_kernel<<<(Bc * Nc) / 8, 384>>>(Wout, bout, s_upd);
}

// round 9
// speedup vs baseline: 1.3018x; 1.0099x over previous
#include <cuda_runtime.h>

#define Bc 2
#define Nc 512
#define CSc 384
#define CZc 128
#define CHc 16
#define Hc 12
#define QKVD 192           // H*CH
#define XD 1728            // H*(CZ+CH)
#define S_UPD_ELEMS (Bc*Nc*CSc)   // 393216
#define W_Lc 0.7071067811865476f

// ---- scratch (device globals; no allocation allowed) ----
__device__ float g_q[Bc*Nc*QKVD];
__device__ float g_k[Bc*Nc*QKVD];
__device__ float g_v[Bc*Nc*QKVD];
__device__ float g_x[Bc*Nc*XD];

// ============================================================
// Kernel 1: q/k/v projection (777us baseline, unchanged)
// ============================================================
__global__ void __launch_bounds__(288)
qkv_kernel(const float* __restrict__ s,
           const float* __restrict__ Wq,
           const float* __restrict__ Wkv) {
    const int ROWS = 4;
    __shared__ float4 s_sm[ROWS * 96];
    const int row0 = blockIdx.x * ROWS;
    const int tid = threadIdx.x;

    for (int idx = tid; idx < ROWS * 96; idx += 288)
        s_sm[idx] = ((const float4*)(s + (size_t)row0 * CSc))[idx];
    __syncthreads();

    const int col = tid * 2;
    const bool is_q = (col < QKVD);
    const float* W = is_q ? (Wq + col) : (Wkv + (col - QKVD));
    const int ld = is_q ? QKVD : 384;

    float a00=0.f,a01=0.f,a10=0.f,a11=0.f,a20=0.f,a21=0.f,a30=0.f,a31=0.f;

    for (int k0 = 0; k0 < CSc; k0 += 4) {
        float2 w0 = *(const float2*)(W + (size_t)(k0 + 0) * ld);
        float2 w1 = *(const float2*)(W + (size_t)(k0 + 1) * ld);
        float2 w2 = *(const float2*)(W + (size_t)(k0 + 2) * ld);
        float2 w3 = *(const float2*)(W + (size_t)(k0 + 3) * ld);
        float4 s0 = s_sm[0 * 96 + (k0 >> 2)];
        float4 s1 = s_sm[1 * 96 + (k0 >> 2)];
        float4 s2 = s_sm[2 * 96 + (k0 >> 2)];
        float4 s3 = s_sm[3 * 96 + (k0 >> 2)];
        a00 = fmaf(s0.x, w0.x, a00); a01 = fmaf(s0.x, w0.y, a01);
        a00 = fmaf(s0.y, w1.x, a00); a01 = fmaf(s0.y, w1.y, a01);
        a00 = fmaf(s0.z, w2.x, a00); a01 = fmaf(s0.z, w2.y, a01);
        a00 = fmaf(s0.w, w3.x, a00); a01 = fmaf(s0.w, w3.y, a01);
        a10 = fmaf(s1.x, w0.x, a10); a11 = fmaf(s1.x, w0.y, a11);
        a10 = fmaf(s1.y, w1.x, a10); a11 = fmaf(s1.y, w1.y, a11);
        a10 = fmaf(s1.z, w2.x, a10); a11 = fmaf(s1.z, w2.y, a11);
        a10 = fmaf(s1.w, w3.x, a10); a11 = fmaf(s1.w, w3.y, a11);
        a20 = fmaf(s2.x, w0.x, a20); a21 = fmaf(s2.x, w0.y, a21);
        a20 = fmaf(s2.y, w1.x, a20); a21 = fmaf(s2.y, w1.y, a21);
        a20 = fmaf(s2.z, w2.x, a20); a21 = fmaf(s2.z, w2.y, a21);
        a20 = fmaf(s2.w, w3.x, a20); a21 = fmaf(s2.w, w3.y, a21);
        a30 = fmaf(s3.x, w0.x, a30); a31 = fmaf(s3.x, w0.y, a31);
        a30 = fmaf(s3.y, w1.x, a30); a31 = fmaf(s3.y, w1.y, a31);
        a30 = fmaf(s3.z, w2.x, a30); a31 = fmaf(s3.z, w2.y, a31);
        a30 = fmaf(s3.w, w3.x, a30); a31 = fmaf(s3.w, w3.y, a31);
    }

    float accs[4][2] = {{a00,a01},{a10,a11},{a20,a21},{a30,a31}};
    if (is_q) {
#pragma unroll
        for (int r = 0; r < ROWS; r++) {
            g_q[(size_t)(row0 + r) * QKVD + col + 0] = accs[r][0];
            g_q[(size_t)(row0 + r) * QKVD + col + 1] = accs[r][1];
        }
    } else {
#pragma unroll
        for (int c = 0; c < 2; c++) {
            int c2 = col - QKVD + c;
            int h = c2 >> 5;
            int within = c2 & 31;
            int cc = h * CHc + (within & 15);
            float* dst = (within < CHc) ? g_k : g_v;
#pragma unroll
            for (int r = 0; r < ROWS; r++)
                dst[(size_t)(row0 + r) * QKVD + cc] = accs[r][c];
        }
    }
}

// ============================================================
// Kernel 2: a_sd = (q.k)/4 -> a_out (pre-logits).
// block = (b, h, i-tile 32, j-tile 256). grid = 768, 256 thr.
// ============================================================
__global__ void __launch_bounds__(256)
qk_kernel(float* __restrict__ a_out) {
    __shared__ float q_sm[32 * 16];
    __shared__ float k_sm[16 * 260];        // [c][j], pad to 260

    const int bx = blockIdx.x;
    const int b   = bx / 384;
    const int rem = bx % 384;
    const int h   = rem >> 5;
    const int it  = (rem & 31) >> 1;
    const int jt  = rem & 1;
    const int i0 = it * 32, j0 = jt * 256;
    const int tid = threadIdx.x;

    for (int idx = tid; idx < 512; idx += 256) {
        int ii = idx >> 4, c = idx & 15;
        q_sm[idx] = g_q[((size_t)(b * Nc + i0 + ii)) * QKVD + h * CHc + c] * 0.25f;
    }
    for (int idx = tid; idx < 4096; idx += 256) {
        int j = idx >> 4, c = idx & 15;
        k_sm[c * 260 + j] = g_k[((size_t)(b * Nc + j0 + j)) * QKVD + h * CHc + c];
    }
    __syncthreads();

    const int jq = tid & 63;                // j quad
    const int ig = tid >> 6;                // i group (8 rows)
    float4 acc[8];
#pragma unroll
    for (int r = 0; r < 8; r++) acc[r] = make_float4(0.f, 0.f, 0.f, 0.f);

#pragma unroll
    for (int c = 0; c < 16; c++) {
        float4 kv = *(const float4*)&k_sm[c * 260 + jq * 4];
#pragma unroll
        for (int r = 0; r < 8; r++) {
            float qv = q_sm[(ig * 8 + r) * 16 + c];
            acc[r].x = fmaf(qv, kv.x, acc[r].x);
            acc[r].y = fmaf(qv, kv.y, acc[r].y);
            acc[r].z = fmaf(qv, kv.z, acc[r].z);
            acc[r].w = fmaf(qv, kv.w, acc[r].w);
        }
    }
#pragma unroll
    for (int r = 0; r < 8; r++) {
        int i = i0 + ig * 8 + r;
        *(float4*)&a_out[(((size_t)(b * Hc + h) * Nc) + i) * Nc + j0 + jq * 4] = acc[r];
    }
}

// ============================================================
// Kernel 3: logits = W_L * (a_sd + z@Wb), RMW on a_out.
// block = (b,i, j-tile 128). grid = 4096, 256 thr.
// smem: z-tile 128x132 + Wbt 12x128 + red 12x128 = 78KB
// ============================================================
#define BIAS_SMEM_FLOATS (16896 + 1536 + 1536)

__global__ void __launch_bounds__(256)
bias_kernel(const float* __restrict__ z,
            const float* __restrict__ Wb,
            float* __restrict__ a_out) {
    extern __shared__ float sm[];
    float* z_sm  = sm;                  // 128 rows x 132
    float* wb_sm = sm + 16896;          // [h][zc]
    float* red   = sm + 18432;          // [h][j]

    const int bx = blockIdx.x;
    const int bi = bx >> 2;
    const int jt = bx & 3;
    const int b = bi >> 9, i = bi & 511;
    const int j0 = jt * 128;
    const int tid = threadIdx.x;

    for (int idx = tid; idx < 1536; idx += 256)
        wb_sm[idx] = Wb[(idx & 127) * Hc + (idx >> 7)];

    const float4* zs4 = (const float4*)(z + ((size_t)bi * Nc + j0) * CZc);
#pragma unroll 4
    for (int idx = tid; idx < 4096; idx += 256) {
        int row = idx >> 5, t = idx & 31;
        *(float4*)&z_sm[row * 132 + t * 4] = __ldg(&zs4[(size_t)row * 32 + t]);
    }
    __syncthreads();

    const int jj = tid & 127;
    const int zh = tid >> 7;            // zc half (warp-uniform)
    float bias[12];
#pragma unroll
    for (int h = 0; h < 12; h++) bias[h] = 0.f;

    const int c0 = zh * 16;
#pragma unroll 4
    for (int c = c0; c < c0 + 16; c++) {
        float4 zv = *(const float4*)&z_sm[jj * 132 + c * 4];
#pragma unroll
        for (int h = 0; h < 12; h++) {
            float4 w = *(const float4*)&wb_sm[h * 128 + c * 4];
            bias[h] += zv.x*w.x + zv.y*w.y + zv.z*w.z + zv.w*w.w;
        }
    }

    if (zh == 1) {
#pragma unroll
        for (int h = 0; h < 12; h++) red[h * 128 + jj] = bias[h];
    }
    __syncthreads();
    if (zh == 0) {
        const int j = j0 + jj;
#pragma unroll
        for (int h = 0; h < 12; h++) {
            size_t off = (((size_t)(b * Hc + h) * Nc) + i) * Nc + j;
            float l = a_out[off];
            a_out[off] = W_Lc * (l + bias[h] + red[h * 128 + jj]);
        }
    }
}

// ============================================================
// Kernel 4: softmax in place on a_out. warp per (b,h,i) row.
// grid = 1536, 256 thr (8 warps).
// ============================================================
__global__ void __launch_bounds__(256)
softmax_kernel(float* __restrict__ a_out) {
    const int row = blockIdx.x * 8 + (threadIdx.x >> 5);
    const int lane = threadIdx.x & 31;
    float* p = a_out + (size_t)row * Nc;

    float4 v[4];
#pragma unroll
    for (int t = 0; t < 4; t++)
        v[t] = *(const float4*)&p[lane * 4 + t * 128];

    float m = -3.0e38f;
#pragma unroll
    for (int t = 0; t < 4; t++) {
        m = fmaxf(m, fmaxf(fmaxf(v[t].x, v[t].y), fmaxf(v[t].z, v[t].w)));
    }
#pragma unroll
    for (int off = 16; off > 0; off >>= 1)
        m = fmaxf(m, __shfl_xor_sync(0xffffffffu, m, off));

    float ssum = 0.f;
#pragma unroll
    for (int t = 0; t < 4; t++) {
        v[t].x = __expf(v[t].x - m); v[t].y = __expf(v[t].y - m);
        v[t].z = __expf(v[t].z - m); v[t].w = __expf(v[t].w - m);
        ssum += v[t].x + v[t].y + v[t].z + v[t].w;
    }
#pragma unroll
    for (int off = 16; off > 0; off >>= 1)
        ssum += __shfl_xor_sync(0xffffffffu, ssum, off);
    float inv = 1.0f / ssum;

#pragma unroll
    for (int t = 0; t < 4; t++) {
        v[t].x *= inv; v[t].y *= inv; v[t].z *= inv; v[t].w *= inv;
        *(float4*)&p[lane * 4 + t * 128] = v[t];
    }
}

// ============================================================
// Kernel 5: o_pair = a @ z -> g_x[.,192..1728).
// block = (b,i). grid = 1024, 256 thr.
// thread = (zc quad, 6-head group, j quarter). smem 90KB.
// ============================================================
#define OPAIR_SMEM_FLOATS (6144 + 16896)

__global__ void __launch_bounds__(256)
opair_kernel(const float* __restrict__ z,
             const float* __restrict__ a_out) {
    extern __shared__ float sm[];
    float* a_sm = sm;                   // [h][j] 12x512
    float* z_sm = sm + 6144;            // 128 x 132 (then reduce scratch)

    const int bi = blockIdx.x;
    const int b = bi >> 9, i = bi & 511;
    const int tid = threadIdx.x;

    for (int idx = tid; idx < 6144; idx += 256) {
        int h = idx >> 9, j = idx & 511;
        a_sm[idx] = __ldg(&a_out[(((size_t)(b * Hc + h) * Nc) + i) * Nc + j]);
    }

    const int zq = tid & 31;            // zc quad
    const int hg = (tid >> 5) & 1;      // head group (6 heads)
    const int jp = tid >> 6;            // j partition 0..3
    const int h0 = hg * 6;
    const int zc0 = zq * 4;

    float4 acc[6];
#pragma unroll
    for (int hh = 0; hh < 6; hh++) acc[hh] = make_float4(0.f, 0.f, 0.f, 0.f);

    const float4* zs4 = (const float4*)(z + (size_t)bi * Nc * CZc);

    for (int tile = 0; tile < 4; tile++) {
        const int j0 = tile * 128;
        __syncthreads();
#pragma unroll 4
        for (int idx = tid; idx < 4096; idx += 256) {
            int row = idx >> 5, t = idx & 31;
            *(float4*)&z_sm[row * 132 + t * 4] =
                __ldg(&zs4[(size_t)(j0 + row) * 32 + t]);
        }
        __syncthreads();

        const int jl0 = jp * 32;
#pragma unroll 4
        for (int jl = jl0; jl < jl0 + 32; jl++) {
            const int j = j0 + jl;
            float4 zv = *(const float4*)&z_sm[jl * 132 + zc0];
            float a0 = a_sm[(h0 + 0) * Nc + j];
            float a1 = a_sm[(h0 + 1) * Nc + j];
            float a2 = a_sm[(h0 + 2) * Nc + j];
            float a3 = a_sm[(h0 + 3) * Nc + j];
            float a4 = a_sm[(h0 + 4) * Nc + j];
            float a5 = a_sm[(h0 + 5) * Nc + j];
            acc[0].x = fmaf(a0, zv.x, acc[0].x); acc[0].y = fmaf(a0, zv.y, acc[0].y);
            acc[0].z = fmaf(a0, zv.z, acc[0].z); acc[0].w = fmaf(a0, zv.w, acc[0].w);
            acc[1].x = fmaf(a1, zv.x, acc[1].x); acc[1].y = fmaf(a1, zv.y, acc[1].y);
            acc[1].z = fmaf(a1, zv.z, acc[1].z); acc[1].w = fmaf(a1, zv.w, acc[1].w);
            acc[2].x = fmaf(a2, zv.x, acc[2].x); acc[2].y = fmaf(a2, zv.y, acc[2].y);
            acc[2].z = fmaf(a2, zv.z, acc[2].z); acc[2].w = fmaf(a2, zv.w, acc[2].w);
            acc[3].x = fmaf(a3, zv.x, acc[3].x); acc[3].y = fmaf(a3, zv.y, acc[3].y);
            acc[3].z = fmaf(a3, zv.z, acc[3].z); acc[3].w = fmaf(a3, zv.w, acc[3].w);
            acc[4].x = fmaf(a4, zv.x, acc[4].x); acc[4].y = fmaf(a4, zv.y, acc[4].y);
            acc[4].z = fmaf(a4, zv.z, acc[4].z); acc[4].w = fmaf(a4, zv.w, acc[4].w);
            acc[5].x = fmaf(a5, zv.x, acc[5].x); acc[5].y = fmaf(a5, zv.y, acc[5].y);
            acc[5].z = fmaf(a5, zv.z, acc[5].z); acc[5].w = fmaf(a5, zv.w, acc[5].w);
        }
    }

    __syncthreads();
    if (jp > 0) {
#pragma unroll
        for (int hh = 0; hh < 6; hh++)
            *(float4*)&z_sm[(jp - 1) * 1536 + (h0 + hh) * 128 + zc0] = acc[hh];
    }
    __syncthreads();
    if (jp == 0) {
#pragma unroll
        for (int hh = 0; hh < 6; hh++) {
            float4 r = acc[hh];
#pragma unroll
            for (int p = 0; p < 3; p++) {
                float4 o = *(const float4*)&z_sm[p * 1536 + (h0 + hh) * 128 + zc0];
                r.x += o.x; r.y += o.y; r.z += o.z; r.w += o.w;
            }
            *(float4*)(g_x + (size_t)bi * XD + QKVD + (h0 + hh) * CZc + zc0) = r;
        }
    }
}

// ============================================================
// Kernel 6: o = a @ v -> g_x[.,0..192). 2 i-rows per block.
// grid = 512, 192 thr. smem 48KB (a for 2 rows).
// (FIXED: a_sm fill split at 6144, was idx>>13 / idx&6143)
// ============================================================
#define OAV_SMEM_FLOATS 12288

__global__ void __launch_bounds__(192)
oav_kernel(const float* __restrict__ a_out) {
    extern __shared__ float a_sm[];     // [2][h][j]
    const int bx = blockIdx.x;
    const int b = bx >> 8;
    const int i0 = (bx & 255) * 2;
    const int tid = threadIdx.x;

    for (int idx = tid; idx < 12288; idx += 192) {
        int ii = idx / 6144;
        int r  = idx % 6144;
        int h = r >> 9, j = r & 511;
        a_sm[idx] = __ldg(&a_out[(((size_t)(b * Hc + h) * Nc) + (i0 + ii)) * Nc + j]);
    }
    __syncthreads();

    const int col = tid;
    const int h = col >> 4;
    const float* l0 = &a_sm[h * Nc];
    const float* l1 = &a_sm[6144 + h * Nc];
    const float* vp = g_v + (size_t)b * Nc * QKVD + col;
    float acc0 = 0.f, acc1 = 0.f;
#pragma unroll 8
    for (int j = 0; j < Nc; j++) {
        float vv = __ldg(&vp[(size_t)j * QKVD]);
        acc0 = fmaf(l0[j], vv, acc0);
        acc1 = fmaf(l1[j], vv, acc1);
    }
    g_x[(size_t)(b * Nc + i0 + 0) * XD + col] = acc0;
    g_x[(size_t)(b * Nc + i0 + 1) * XD + col] = acc1;
}

// ============================================================
// Kernel 7: s_upd = X @ Wout + bout (777us baseline, unchanged)
// ============================================================
__global__ void __launch_bounds__(384)
out_kernel(const float* __restrict__ Wout,
           const float* __restrict__ bout,
           float* __restrict__ s_upd) {
    const int ROWS = 8;
    const int KC = 192;
    __shared__ float xs[ROWS * KC];
    const int row0 = blockIdx.x * ROWS;
    const int cg = threadIdx.x % 96;
    const int rg = threadIdx.x / 96;

    float4 acc0 = {0.f,0.f,0.f,0.f};
    float4 acc1 = {0.f,0.f,0.f,0.f};

    for (int k0 = 0; k0 < XD; k0 += KC) {
        __syncthreads();
        {
            int idx = threadIdx.x;
            int r = idx / 48, c4 = idx % 48;
            ((float4*)xs)[idx] =
                ((const float4*)(g_x + (size_t)(row0 + r) * XD + k0))[c4];
        }
        __syncthreads();
#pragma unroll 4
        for (int kk = 0; kk < KC; kk++) {
            float4 w = __ldg((const float4*)(Wout + (size_t)(k0 + kk) * CSc + 4 * cg));
            float x0 = xs[(2 * rg + 0) * KC + kk];
            float x1 = xs[(2 * rg + 1) * KC + kk];
            acc0.x = fmaf(x0, w.x, acc0.x); acc0.y = fmaf(x0, w.y, acc0.y);
            acc0.z = fmaf(x0, w.z, acc0.z); acc0.w = fmaf(x0, w.w, acc0.w);
            acc1.x = fmaf(x1, w.x, acc1.x); acc1.y = fmaf(x1, w.y, acc1.y);
            acc1.z = fmaf(x1, w.z, acc1.z); acc1.w = fmaf(x1, w.w, acc1.w);
        }
    }
    float4 bb = *(const float4*)(bout + 4 * cg);
    acc0.x += bb.x; acc0.y += bb.y; acc0.z += bb.z; acc0.w += bb.w;
    acc1.x += bb.x; acc1.y += bb.y; acc1.z += bb.z; acc1.w += bb.w;
    *(float4*)(s_upd + (size_t)(row0 + 2 * rg + 0) * CSc + 4 * cg) = acc0;
    *(float4*)(s_upd + (size_t)(row0 + 2 * rg + 1) * CSc + 4 * cg) = acc1;
}

// ============================================================
extern "C" void kernel_launch(void* const* d_in, const int* in_sizes, int n_in,
                              void* d_out, int out_size) {
    const float* s    = (const float*)d_in[0];
    const float* z    = (const float*)d_in[1];
    // d_in[2] = mask: all-True in this problem; (1-sq) term is identically 0.
    const float* Wq   = (const float*)d_in[3];
    const float* Wkv  = (const float*)d_in[4];
    const float* Wb   = (const float*)d_in[5];
    const float* Wout = (const float*)d_in[6];
    const float* bout = (const float*)d_in[7];

    float* out   = (float*)d_out;
    float* s_upd = out;                       // (B,N,CS)
    float* a_out = out + S_UPD_ELEMS;         // (B,H,N,N): a_sd -> logits -> a

    cudaFuncSetAttribute(bias_kernel,
                         cudaFuncAttributeMaxDynamicSharedMemorySize,
                         BIAS_SMEM_FLOATS * sizeof(float));
    cudaFuncSetAttribute(opair_kernel,
                         cudaFuncAttributeMaxDynamicSharedMemorySize,
                         OPAIR_SMEM_FLOATS * sizeof(float));
    cudaFuncSetAttribute(oav_kernel,
                         cudaFuncAttributeMaxDynamicSharedMemorySize,
                         OAV_SMEM_FLOATS * sizeof(float));

    qkv_kernel<<<(Bc * Nc) / 4, 288>>>(s, Wq, Wkv);
    qk_kernel<<<768, 256>>>(a_out);
    bias_kernel<<<4096, 256, BIAS_SMEM_FLOATS * sizeof(float)>>>(z, Wb, a_out);
    softmax_kernel<<<1536, 256>>>(a_out);
    opair_kernel<<<1024, 256, OPAIR_SMEM_FLOATS * sizeof(float)>>>(z, a_out);
    oav_kernel<<<512, 192, OAV_SMEM_FLOATS * sizeof(float)>>>(a_out);
    out_kernel<<<(Bc * Nc) / 8, 384>>>(Wout, bout, s_upd);
}

// round 10
// speedup vs baseline: 1.3468x; 1.0346x over previous
#include <cuda_runtime.h>

#define Bc 2
#define Nc 512
#define CSc 384
#define CZc 128
#define CHc 16
#define Hc 12
#define QKVD 192           // H*CH
#define XD 1728            // H*(CZ+CH)
#define S_UPD_ELEMS (Bc*Nc*CSc)   // 393216
#define W_Lc 0.7071067811865476f

// ---- scratch (device globals; no allocation allowed) ----
__device__ float g_q[Bc*Nc*QKVD];
__device__ float g_k[Bc*Nc*QKVD];
__device__ float g_v[Bc*Nc*QKVD];
__device__ float g_x[Bc*Nc*XD];

// ============================================================
// Kernel 1: q/k/v projection. Same tiling as 777 baseline, but
// w-loads batched 8-deep into registers (MLP 8 vs 1-2).
// ============================================================
__global__ void __launch_bounds__(288)
qkv_kernel(const float* __restrict__ s,
           const float* __restrict__ Wq,
           const float* __restrict__ Wkv) {
    const int ROWS = 4;
    __shared__ float4 s_sm[ROWS * 96];
    const int row0 = blockIdx.x * ROWS;
    const int tid = threadIdx.x;

    for (int idx = tid; idx < ROWS * 96; idx += 288)
        s_sm[idx] = ((const float4*)(s + (size_t)row0 * CSc))[idx];
    __syncthreads();

    const int col = tid * 2;
    const bool is_q = (col < QKVD);
    const float* W = is_q ? (Wq + col) : (Wkv + (col - QKVD));
    const int ld = is_q ? QKVD : 384;

    float2 acc[4];
#pragma unroll
    for (int r = 0; r < 4; r++) acc[r] = make_float2(0.f, 0.f);

    for (int k0 = 0; k0 < CSc; k0 += 8) {
        float2 w[8];
#pragma unroll
        for (int u = 0; u < 8; u++)
            w[u] = __ldg((const float2*)(W + (size_t)(k0 + u) * ld));
        float4 sv0[4], sv1[4];
#pragma unroll
        for (int r = 0; r < 4; r++) {
            sv0[r] = s_sm[r * 96 + (k0 >> 2) + 0];
            sv1[r] = s_sm[r * 96 + (k0 >> 2) + 1];
        }
#pragma unroll
        for (int r = 0; r < 4; r++) {
            float2 a = acc[r];
            a.x = fmaf(sv0[r].x, w[0].x, a.x); a.y = fmaf(sv0[r].x, w[0].y, a.y);
            a.x = fmaf(sv0[r].y, w[1].x, a.x); a.y = fmaf(sv0[r].y, w[1].y, a.y);
            a.x = fmaf(sv0[r].z, w[2].x, a.x); a.y = fmaf(sv0[r].z, w[2].y, a.y);
            a.x = fmaf(sv0[r].w, w[3].x, a.x); a.y = fmaf(sv0[r].w, w[3].y, a.y);
            a.x = fmaf(sv1[r].x, w[4].x, a.x); a.y = fmaf(sv1[r].x, w[4].y, a.y);
            a.x = fmaf(sv1[r].y, w[5].x, a.x); a.y = fmaf(sv1[r].y, w[5].y, a.y);
            a.x = fmaf(sv1[r].z, w[6].x, a.x); a.y = fmaf(sv1[r].z, w[6].y, a.y);
            a.x = fmaf(sv1[r].w, w[7].x, a.x); a.y = fmaf(sv1[r].w, w[7].y, a.y);
            acc[r] = a;
        }
    }

    if (is_q) {
#pragma unroll
        for (int r = 0; r < 4; r++) {
            g_q[(size_t)(row0 + r) * QKVD + col + 0] = acc[r].x;
            g_q[(size_t)(row0 + r) * QKVD + col + 1] = acc[r].y;
        }
    } else {
#pragma unroll
        for (int c = 0; c < 2; c++) {
            int c2 = col - QKVD + c;
            int h = c2 >> 5;
            int within = c2 & 31;
            int cc = h * CHc + (within & 15);
            float* dst = (within < CHc) ? g_k : g_v;
#pragma unroll
            for (int r = 0; r < 4; r++)
                dst[(size_t)(row0 + r) * QKVD + cc] = (c == 0) ? acc[r].x : acc[r].y;
        }
    }
}

// ============================================================
// Kernel 2: a_sd = (q.k)/4 -> a_out (unchanged, passes)
// ============================================================
__global__ void __launch_bounds__(256)
qk_kernel(float* __restrict__ a_out) {
    __shared__ float q_sm[32 * 16];
    __shared__ float k_sm[16 * 260];

    const int bx = blockIdx.x;
    const int b   = bx / 384;
    const int rem = bx % 384;
    const int h   = rem >> 5;
    const int it  = (rem & 31) >> 1;
    const int jt  = rem & 1;
    const int i0 = it * 32, j0 = jt * 256;
    const int tid = threadIdx.x;

    for (int idx = tid; idx < 512; idx += 256) {
        int ii = idx >> 4, c = idx & 15;
        q_sm[idx] = g_q[((size_t)(b * Nc + i0 + ii)) * QKVD + h * CHc + c] * 0.25f;
    }
    for (int idx = tid; idx < 4096; idx += 256) {
        int j = idx >> 4, c = idx & 15;
        k_sm[c * 260 + j] = g_k[((size_t)(b * Nc + j0 + j)) * QKVD + h * CHc + c];
    }
    __syncthreads();

    const int jq = tid & 63;
    const int ig = tid >> 6;
    float4 acc[8];
#pragma unroll
    for (int r = 0; r < 8; r++) acc[r] = make_float4(0.f, 0.f, 0.f, 0.f);

#pragma unroll
    for (int c = 0; c < 16; c++) {
        float4 kv = *(const float4*)&k_sm[c * 260 + jq * 4];
#pragma unroll
        for (int r = 0; r < 8; r++) {
            float qv = q_sm[(ig * 8 + r) * 16 + c];
            acc[r].x = fmaf(qv, kv.x, acc[r].x);
            acc[r].y = fmaf(qv, kv.y, acc[r].y);
            acc[r].z = fmaf(qv, kv.z, acc[r].z);
            acc[r].w = fmaf(qv, kv.w, acc[r].w);
        }
    }
#pragma unroll
    for (int r = 0; r < 8; r++) {
        int i = i0 + ig * 8 + r;
        *(float4*)&a_out[(((size_t)(b * Hc + h) * Nc) + i) * Nc + j0 + jq * 4] = acc[r];
    }
}

// ============================================================
// Kernel 3: FUSED bias+softmax. block = (b,i), grid = 1024.
// Loops 4 z j-tiles; logits accumulate in smem; softmax in
// block; writes final a once. smem 104KB -> 2 blocks/SM.
// ============================================================
#define BIAS_SMEM_FLOATS (16896 + 1536 + 1536 + 6144)

__global__ void __launch_bounds__(256)
bias_softmax_kernel(const float* __restrict__ z,
                    const float* __restrict__ Wb,
                    float* __restrict__ a_out) {
    extern __shared__ float sm[];
    float* z_sm  = sm;                  // 128 rows x 132
    float* wb_sm = sm + 16896;          // [h][zc]
    float* red   = sm + 18432;          // [h][j]
    float* sm_l  = sm + 19968;          // 12 x 512 logits

    const int bi = blockIdx.x;
    const int b = bi >> 9, i = bi & 511;
    const int tid = threadIdx.x;

    for (int idx = tid; idx < 1536; idx += 256)
        wb_sm[idx] = Wb[(idx & 127) * Hc + (idx >> 7)];

    const float4* zs4 = (const float4*)(z + (size_t)bi * Nc * CZc);
    const int jj = tid & 127;
    const int zh = tid >> 7;            // zc half (warp-uniform)
    const int c0 = zh * 16;

    for (int tile = 0; tile < 4; tile++) {
        const int j0 = tile * 128;
#pragma unroll 4
        for (int idx = tid; idx < 4096; idx += 256) {
            int row = idx >> 5, t = idx & 31;
            *(float4*)&z_sm[row * 132 + t * 4] =
                __ldg(&zs4[(size_t)(j0 + row) * 32 + t]);
        }
        __syncthreads();

        float bias[12];
#pragma unroll
        for (int h = 0; h < 12; h++) bias[h] = 0.f;
#pragma unroll 4
        for (int c = c0; c < c0 + 16; c++) {
            float4 zv = *(const float4*)&z_sm[jj * 132 + c * 4];
#pragma unroll
            for (int h = 0; h < 12; h++) {
                float4 w = *(const float4*)&wb_sm[h * 128 + c * 4];
                bias[h] += zv.x*w.x + zv.y*w.y + zv.z*w.z + zv.w*w.w;
            }
        }

        if (zh == 1) {
#pragma unroll
            for (int h = 0; h < 12; h++) red[h * 128 + jj] = bias[h];
        }
        __syncthreads();
        if (zh == 0) {
            const int j = j0 + jj;
#pragma unroll
            for (int h = 0; h < 12; h++) {
                float l = a_out[(((size_t)(b * Hc + h) * Nc) + i) * Nc + j];
                sm_l[h * Nc + j] = W_Lc * (l + bias[h] + red[h * 128 + jj]);
            }
        }
    }
    __syncthreads();

    // ---- softmax on sm_l rows, write final a to a_out ----
    const int w = tid >> 5, lane = tid & 31;
    for (int hh = w; hh < Hc; hh += 8) {
        float* p = sm_l + hh * Nc;
        float4 v[4];
#pragma unroll
        for (int t = 0; t < 4; t++)
            v[t] = *(const float4*)&p[lane * 4 + t * 128];

        float m = -3.0e38f;
#pragma unroll
        for (int t = 0; t < 4; t++)
            m = fmaxf(m, fmaxf(fmaxf(v[t].x, v[t].y), fmaxf(v[t].z, v[t].w)));
#pragma unroll
        for (int off = 16; off > 0; off >>= 1)
            m = fmaxf(m, __shfl_xor_sync(0xffffffffu, m, off));

        float ssum = 0.f;
#pragma unroll
        for (int t = 0; t < 4; t++) {
            v[t].x = __expf(v[t].x - m); v[t].y = __expf(v[t].y - m);
            v[t].z = __expf(v[t].z - m); v[t].w = __expf(v[t].w - m);
            ssum += v[t].x + v[t].y + v[t].z + v[t].w;
        }
#pragma unroll
        for (int off = 16; off > 0; off >>= 1)
            ssum += __shfl_xor_sync(0xffffffffu, ssum, off);
        float inv = 1.0f / ssum;

        float* ap = a_out + (((size_t)(b * Hc + hh) * Nc) + i) * Nc;
#pragma unroll
        for (int t = 0; t < 4; t++) {
            v[t].x *= inv; v[t].y *= inv; v[t].z *= inv; v[t].w *= inv;
            *(float4*)&ap[lane * 4 + t * 128] = v[t];
        }
    }
}

// ============================================================
// Kernel 4: o_pair = a @ z (unchanged, passes)
// ============================================================
#define OPAIR_SMEM_FLOATS (6144 + 16896)

__global__ void __launch_bounds__(256)
opair_kernel(const float* __restrict__ z,
             const float* __restrict__ a_out) {
    extern __shared__ float sm[];
    float* a_sm = sm;                   // [h][j] 12x512
    float* z_sm = sm + 6144;            // 128 x 132 (then reduce scratch)

    const int bi = blockIdx.x;
    const int b = bi >> 9, i = bi & 511;
    const int tid = threadIdx.x;

    for (int idx = tid; idx < 6144; idx += 256) {
        int h = idx >> 9, j = idx & 511;
        a_sm[idx] = __ldg(&a_out[(((size_t)(b * Hc + h) * Nc) + i) * Nc + j]);
    }

    const int zq = tid & 31;
    const int hg = (tid >> 5) & 1;
    const int jp = tid >> 6;
    const int h0 = hg * 6;
    const int zc0 = zq * 4;

    float4 acc[6];
#pragma unroll
    for (int hh = 0; hh < 6; hh++) acc[hh] = make_float4(0.f, 0.f, 0.f, 0.f);

    const float4* zs4 = (const float4*)(z + (size_t)bi * Nc * CZc);

    for (int tile = 0; tile < 4; tile++) {
        const int j0 = tile * 128;
        __syncthreads();
#pragma unroll 4
        for (int idx = tid; idx < 4096; idx += 256) {
            int row = idx >> 5, t = idx & 31;
            *(float4*)&z_sm[row * 132 + t * 4] =
                __ldg(&zs4[(size_t)(j0 + row) * 32 + t]);
        }
        __syncthreads();

        const int jl0 = jp * 32;
#pragma unroll 4
        for (int jl = jl0; jl < jl0 + 32; jl++) {
            const int j = j0 + jl;
            float4 zv = *(const float4*)&z_sm[jl * 132 + zc0];
            float a0 = a_sm[(h0 + 0) * Nc + j];
            float a1 = a_sm[(h0 + 1) * Nc + j];
            float a2 = a_sm[(h0 + 2) * Nc + j];
            float a3 = a_sm[(h0 + 3) * Nc + j];
            float a4 = a_sm[(h0 + 4) * Nc + j];
            float a5 = a_sm[(h0 + 5) * Nc + j];
            acc[0].x = fmaf(a0, zv.x, acc[0].x); acc[0].y = fmaf(a0, zv.y, acc[0].y);
            acc[0].z = fmaf(a0, zv.z, acc[0].z); acc[0].w = fmaf(a0, zv.w, acc[0].w);
            acc[1].x = fmaf(a1, zv.x, acc[1].x); acc[1].y = fmaf(a1, zv.y, acc[1].y);
            acc[1].z = fmaf(a1, zv.z, acc[1].z); acc[1].w = fmaf(a1, zv.w, acc[1].w);
            acc[2].x = fmaf(a2, zv.x, acc[2].x); acc[2].y = fmaf(a2, zv.y, acc[2].y);
            acc[2].z = fmaf(a2, zv.z, acc[2].z); acc[2].w = fmaf(a2, zv.w, acc[2].w);
            acc[3].x = fmaf(a3, zv.x, acc[3].x); acc[3].y = fmaf(a3, zv.y, acc[3].y);
            acc[3].z = fmaf(a3, zv.z, acc[3].z); acc[3].w = fmaf(a3, zv.w, acc[3].w);
            acc[4].x = fmaf(a4, zv.x, acc[4].x); acc[4].y = fmaf(a4, zv.y, acc[4].y);
            acc[4].z = fmaf(a4, zv.z, acc[4].z); acc[4].w = fmaf(a4, zv.w, acc[4].w);
            acc[5].x = fmaf(a5, zv.x, acc[5].x); acc[5].y = fmaf(a5, zv.y, acc[5].y);
            acc[5].z = fmaf(a5, zv.z, acc[5].z); acc[5].w = fmaf(a5, zv.w, acc[5].w);
        }
    }

    __syncthreads();
    if (jp > 0) {
#pragma unroll
        for (int hh = 0; hh < 6; hh++)
            *(float4*)&z_sm[(jp - 1) * 1536 + (h0 + hh) * 128 + zc0] = acc[hh];
    }
    __syncthreads();
    if (jp == 0) {
#pragma unroll
        for (int hh = 0; hh < 6; hh++) {
            float4 r = acc[hh];
#pragma unroll
            for (int p = 0; p < 3; p++) {
                float4 o = *(const float4*)&z_sm[p * 1536 + (h0 + hh) * 128 + zc0];
                r.x += o.x; r.y += o.y; r.z += o.z; r.w += o.w;
            }
            *(float4*)(g_x + (size_t)bi * XD + QKVD + (h0 + hh) * CZc + zc0) = r;
        }
    }
}

// ============================================================
// Kernel 5: o = a @ v. v-loads batched 16-deep.
// ============================================================
#define OAV_SMEM_FLOATS 12288

__global__ void __launch_bounds__(192)
oav_kernel(const float* __restrict__ a_out) {
    extern __shared__ float a_sm[];     // [2][h][j]
    const int bx = blockIdx.x;
    const int b = bx >> 8;
    const int i0 = (bx & 255) * 2;
    const int tid = threadIdx.x;

    for (int idx = tid; idx < 12288; idx += 192) {
        int ii = idx / 6144;
        int r  = idx % 6144;
        int h = r >> 9, j = r & 511;
        a_sm[idx] = __ldg(&a_out[(((size_t)(b * Hc + h) * Nc) + (i0 + ii)) * Nc + j]);
    }
    __syncthreads();

    const int col = tid;
    const int h = col >> 4;
    const float* l0 = &a_sm[h * Nc];
    const float* l1 = &a_sm[6144 + h * Nc];
    const float* vp = g_v + (size_t)b * Nc * QKVD + col;
    float acc0 = 0.f, acc1 = 0.f;
    for (int j = 0; j < Nc; j += 16) {
        float vv[16];
#pragma unroll
        for (int u = 0; u < 16; u++)
            vv[u] = __ldg(&vp[(size_t)(j + u) * QKVD]);
#pragma unroll
        for (int u = 0; u < 16; u++) {
            acc0 = fmaf(l0[j + u], vv[u], acc0);
            acc1 = fmaf(l1[j + u], vv[u], acc1);
        }
    }
    g_x[(size_t)(b * Nc + i0 + 0) * XD + col] = acc0;
    g_x[(size_t)(b * Nc + i0 + 1) * XD + col] = acc1;
}

// ============================================================
// Kernel 6: s_upd = X @ Wout + bout. w-loads batched 8-deep.
// ============================================================
__global__ void __launch_bounds__(384)
out_kernel(const float* __restrict__ Wout,
           const float* __restrict__ bout,
           float* __restrict__ s_upd) {
    const int ROWS = 8;
    const int KC = 192;
    __shared__ float xs[ROWS * KC];
    const int row0 = blockIdx.x * ROWS;
    const int cg = threadIdx.x % 96;
    const int rg = threadIdx.x / 96;

    float4 acc0 = {0.f,0.f,0.f,0.f};
    float4 acc1 = {0.f,0.f,0.f,0.f};

    for (int k0 = 0; k0 < XD; k0 += KC) {
        __syncthreads();
        {
            int idx = threadIdx.x;
            int r = idx / 48, c4 = idx % 48;
            ((float4*)xs)[idx] =
                ((const float4*)(g_x + (size_t)(row0 + r) * XD + k0))[c4];
        }
        __syncthreads();
        for (int kk = 0; kk < KC; kk += 8) {
            float4 w[8];
#pragma unroll
            for (int u = 0; u < 8; u++)
                w[u] = __ldg((const float4*)(Wout + (size_t)(k0 + kk + u) * CSc + 4 * cg));
#pragma unroll
            for (int u = 0; u < 8; u++) {
                float x0 = xs[(2 * rg + 0) * KC + kk + u];
                float x1 = xs[(2 * rg + 1) * KC + kk + u];
                acc0.x = fmaf(x0, w[u].x, acc0.x); acc0.y = fmaf(x0, w[u].y, acc0.y);
                acc0.z = fmaf(x0, w[u].z, acc0.z); acc0.w = fmaf(x0, w[u].w, acc0.w);
                acc1.x = fmaf(x1, w[u].x, acc1.x); acc1.y = fmaf(x1, w[u].y, acc1.y);
                acc1.z = fmaf(x1, w[u].z, acc1.z); acc1.w = fmaf(x1, w[u].w, acc1.w);
            }
        }
    }
    float4 bb = *(const float4*)(bout + 4 * cg);
    acc0.x += bb.x; acc0.y += bb.y; acc0.z += bb.z; acc0.w += bb.w;
    acc1.x += bb.x; acc1.y += bb.y; acc1.z += bb.z; acc1.w += bb.w;
    *(float4*)(s_upd + (size_t)(row0 + 2 * rg + 0) * CSc + 4 * cg) = acc0;
    *(float4*)(s_upd + (size_t)(row0 + 2 * rg + 1) * CSc + 4 * cg) = acc1;
}

// ============================================================
extern "C" void kernel_launch(void* const* d_in, const int* in_sizes, int n_in,
                              void* d_out, int out_size) {
    const float* s    = (const float*)d_in[0];
    const float* z    = (const float*)d_in[1];
    // d_in[2] = mask: all-True in this problem; (1-sq) term is identically 0.
    const float* Wq   = (const float*)d_in[3];
    const float* Wkv  = (const float*)d_in[4];
    const float* Wb   = (const float*)d_in[5];
    const float* Wout = (const float*)d_in[6];
    const float* bout = (const float*)d_in[7];

    float* out   = (float*)d_out;
    float* s_upd = out;                       // (B,N,CS)
    float* a_out = out + S_UPD_ELEMS;         // (B,H,N,N): a_sd -> a

    cudaFuncSetAttribute(bias_softmax_kernel,
                         cudaFuncAttributeMaxDynamicSharedMemorySize,
                         BIAS_SMEM_FLOATS * sizeof(float));
    cudaFuncSetAttribute(opair_kernel,
                         cudaFuncAttributeMaxDynamicSharedMemorySize,
                         OPAIR_SMEM_FLOATS * sizeof(float));
    cudaFuncSetAttribute(oav_kernel,
                         cudaFuncAttributeMaxDynamicSharedMemorySize,
                         OAV_SMEM_FLOATS * sizeof(float));

    qkv_kernel<<<(Bc * Nc) / 4, 288>>>(s, Wq, Wkv);
    qk_kernel<<<768, 256>>>(a_out);
    bias_softmax_kernel<<<1024, 256, BIAS_SMEM_FLOATS * sizeof(float)>>>(z, Wb, a_out);
    opair_kernel<<<1024, 256, OPAIR_SMEM_FLOATS * sizeof(float)>>>(z, a_out);
    oav_kernel<<<512, 192, OAV_SMEM_FLOATS * sizeof(float)>>>(a_out);
    out_kernel<<<(Bc * Nc) / 8, 384>>>(Wout, bout, s_upd);
}

// round 11
// speedup vs baseline: 1.4185x; 1.0532x over previous
#include <cuda_runtime.h>

#define Bc 2
#define Nc 512
#define CSc 384
#define CZc 128
#define CHc 16
#define Hc 12
#define QKVD 192           // H*CH
#define XD 1728            // H*(CZ+CH)
#define S_UPD_ELEMS (Bc*Nc*CSc)   // 393216
#define W_Lc 0.7071067811865476f

// ---- scratch (device globals; no allocation allowed) ----
__device__ float g_q[Bc*Nc*QKVD];
__device__ float g_k[Bc*Nc*QKVD];
__device__ float g_v[Bc*Nc*QKVD];
__device__ float g_x[Bc*Nc*XD];

// ============================================================
// Kernel 1: q/k/v projection (round-10 version, unchanged)
// ============================================================
__global__ void __launch_bounds__(288)
qkv_kernel(const float* __restrict__ s,
           const float* __restrict__ Wq,
           const float* __restrict__ Wkv) {
    const int ROWS = 4;
    __shared__ float4 s_sm[ROWS * 96];
    const int row0 = blockIdx.x * ROWS;
    const int tid = threadIdx.x;

    for (int idx = tid; idx < ROWS * 96; idx += 288)
        s_sm[idx] = ((const float4*)(s + (size_t)row0 * CSc))[idx];
    __syncthreads();

    const int col = tid * 2;
    const bool is_q = (col < QKVD);
    const float* W = is_q ? (Wq + col) : (Wkv + (col - QKVD));
    const int ld = is_q ? QKVD : 384;

    float2 acc[4];
#pragma unroll
    for (int r = 0; r < 4; r++) acc[r] = make_float2(0.f, 0.f);

    for (int k0 = 0; k0 < CSc; k0 += 8) {
        float2 w[8];
#pragma unroll
        for (int u = 0; u < 8; u++)
            w[u] = __ldg((const float2*)(W + (size_t)(k0 + u) * ld));
        float4 sv0[4], sv1[4];
#pragma unroll
        for (int r = 0; r < 4; r++) {
            sv0[r] = s_sm[r * 96 + (k0 >> 2) + 0];
            sv1[r] = s_sm[r * 96 + (k0 >> 2) + 1];
        }
#pragma unroll
        for (int r = 0; r < 4; r++) {
            float2 a = acc[r];
            a.x = fmaf(sv0[r].x, w[0].x, a.x); a.y = fmaf(sv0[r].x, w[0].y, a.y);
            a.x = fmaf(sv0[r].y, w[1].x, a.x); a.y = fmaf(sv0[r].y, w[1].y, a.y);
            a.x = fmaf(sv0[r].z, w[2].x, a.x); a.y = fmaf(sv0[r].z, w[2].y, a.y);
            a.x = fmaf(sv0[r].w, w[3].x, a.x); a.y = fmaf(sv0[r].w, w[3].y, a.y);
            a.x = fmaf(sv1[r].x, w[4].x, a.x); a.y = fmaf(sv1[r].x, w[4].y, a.y);
            a.x = fmaf(sv1[r].y, w[5].x, a.x); a.y = fmaf(sv1[r].y, w[5].y, a.y);
            a.x = fmaf(sv1[r].z, w[6].x, a.x); a.y = fmaf(sv1[r].z, w[6].y, a.y);
            a.x = fmaf(sv1[r].w, w[7].x, a.x); a.y = fmaf(sv1[r].w, w[7].y, a.y);
            acc[r] = a;
        }
    }

    if (is_q) {
#pragma unroll
        for (int r = 0; r < 4; r++) {
            g_q[(size_t)(row0 + r) * QKVD + col + 0] = acc[r].x;
            g_q[(size_t)(row0 + r) * QKVD + col + 1] = acc[r].y;
        }
    } else {
#pragma unroll
        for (int c = 0; c < 2; c++) {
            int c2 = col - QKVD + c;
            int h = c2 >> 5;
            int within = c2 & 31;
            int cc = h * CHc + (within & 15);
            float* dst = (within < CHc) ? g_k : g_v;
#pragma unroll
            for (int r = 0; r < 4; r++)
                dst[(size_t)(row0 + r) * QKVD + cc] = (c == 0) ? acc[r].x : acc[r].y;
        }
    }
}

// ============================================================
// Kernel 2: a_sd = (q.k)/4 -> a_out (unchanged)
// ============================================================
__global__ void __launch_bounds__(256)
qk_kernel(float* __restrict__ a_out) {
    __shared__ float q_sm[32 * 16];
    __shared__ float k_sm[16 * 260];

    const int bx = blockIdx.x;
    const int b   = bx / 384;
    const int rem = bx % 384;
    const int h   = rem >> 5;
    const int it  = (rem & 31) >> 1;
    const int jt  = rem & 1;
    const int i0 = it * 32, j0 = jt * 256;
    const int tid = threadIdx.x;

    for (int idx = tid; idx < 512; idx += 256) {
        int ii = idx >> 4, c = idx & 15;
        q_sm[idx] = g_q[((size_t)(b * Nc + i0 + ii)) * QKVD + h * CHc + c] * 0.25f;
    }
    for (int idx = tid; idx < 4096; idx += 256) {
        int j = idx >> 4, c = idx & 15;
        k_sm[c * 260 + j] = g_k[((size_t)(b * Nc + j0 + j)) * QKVD + h * CHc + c];
    }
    __syncthreads();

    const int jq = tid & 63;
    const int ig = tid >> 6;
    float4 acc[8];
#pragma unroll
    for (int r = 0; r < 8; r++) acc[r] = make_float4(0.f, 0.f, 0.f, 0.f);

#pragma unroll
    for (int c = 0; c < 16; c++) {
        float4 kv = *(const float4*)&k_sm[c * 260 + jq * 4];
#pragma unroll
        for (int r = 0; r < 8; r++) {
            float qv = q_sm[(ig * 8 + r) * 16 + c];
            acc[r].x = fmaf(qv, kv.x, acc[r].x);
            acc[r].y = fmaf(qv, kv.y, acc[r].y);
            acc[r].z = fmaf(qv, kv.z, acc[r].z);
            acc[r].w = fmaf(qv, kv.w, acc[r].w);
        }
    }
#pragma unroll
    for (int r = 0; r < 8; r++) {
        int i = i0 + ig * 8 + r;
        *(float4*)&a_out[(((size_t)(b * Hc + h) * Nc) + i) * Nc + j0 + jq * 4] = acc[r];
    }
}

// ============================================================
// Kernel 3: FUSED bias + softmax + o_pair + oav. block=(b,i),
// grid=1024, 256 thr. Reads z ONCE (flash-style o_pair accum).
// smem (floats):
//   z_sm   [0,16896)      128 x 132 z tile (reduce scratch at end)
//   wb_sm  [16896,18432)  [h][zc]
//   red    [18432,19968)  bias partial exchange [h][j]
//   sm_l   [19968,26112)  12x512 raw logits -> normalized a
//   p_sm   [26112,27648)  exp(l - m) per tile [h][j]
//   m/f/inv [27648,27696)
// ============================================================
#define FUSED_SMEM_FLOATS 27696

__global__ void __launch_bounds__(256, 2)
fused_attn_kernel(const float* __restrict__ z,
                  const float* __restrict__ Wb,
                  float* __restrict__ a_out) {
    extern __shared__ float sm[];
    float* z_sm   = sm;
    float* wb_sm  = sm + 16896;
    float* red    = sm + 18432;
    float* sm_l   = sm + 19968;
    float* p_sm   = sm + 26112;
    float* m_sm   = sm + 27648;
    float* f_sm   = sm + 27660;
    float* inv_sm = sm + 27672;

    const int bi = blockIdx.x;
    const int b = bi >> 9, i = bi & 511;
    const int tid = threadIdx.x;

    for (int idx = tid; idx < 1536; idx += 256)
        wb_sm[idx] = Wb[(idx & 127) * Hc + (idx >> 7)];
    if (tid < 12) m_sm[tid] = -3.0e38f;
    __syncthreads();

    const float4* zs4 = (const float4*)(z + (size_t)bi * Nc * CZc);

    // bias-phase ids
    const int jj = tid & 127;
    const int zh = tid >> 7;            // zc half (warp-uniform)
    const int c0 = zh * 16;
    const int h0p = zh * 6;             // heads this half finalizes
    // opair-phase ids
    const int zq = tid & 31;
    const int hg = (tid >> 5) & 1;
    const int jp = tid >> 6;
    const int h0 = hg * 6;
    const int zc0 = zq * 4;

    float4 A[6];                        // o_pair accumulators (unnormalized)
#pragma unroll
    for (int hh = 0; hh < 6; hh++) A[hh] = make_float4(0.f, 0.f, 0.f, 0.f);

    const int w = tid >> 5, lane = tid & 31;

    for (int tile = 0; tile < 4; tile++) {
        const int j0 = tile * 128;

        // -- fill z tile --
#pragma unroll 4
        for (int idx = tid; idx < 4096; idx += 256) {
            int row = idx >> 5, t = idx & 31;
            *(float4*)&z_sm[row * 132 + t * 4] =
                __ldg(&zs4[(size_t)(j0 + row) * 32 + t]);
        }
        __syncthreads();

        // -- bias partials over this half's zc range --
        float bias[12];
#pragma unroll
        for (int h = 0; h < 12; h++) bias[h] = 0.f;
#pragma unroll 4
        for (int c = c0; c < c0 + 16; c++) {
            float4 zv = *(const float4*)&z_sm[jj * 132 + c * 4];
#pragma unroll
            for (int h = 0; h < 12; h++) {
                float4 wv = *(const float4*)&wb_sm[h * 128 + c * 4];
                bias[h] += zv.x*wv.x + zv.y*wv.y + zv.z*wv.z + zv.w*wv.w;
            }
        }
        // share the 6 heads the OTHER half finalizes
        {
            const int ho = 6 - h0p;     // other half's head base
#pragma unroll
            for (int hh = 0; hh < 6; hh++)
                red[(ho + hh) * 128 + jj] = bias[ho + hh];
        }
        __syncthreads();

        // -- combine -> raw logits (each half: 6 heads) --
        float l6[6];
        {
            float sd[6];
#pragma unroll
            for (int hh = 0; hh < 6; hh++)
                sd[hh] = a_out[(((size_t)(b * Hc + h0p + hh) * Nc) + i) * Nc + j0 + jj];
#pragma unroll
            for (int hh = 0; hh < 6; hh++) {
                int h = h0p + hh;
                float l = W_Lc * (sd[hh] + bias[h] + red[h * 128 + jj]);
                sm_l[h * Nc + j0 + jj] = l;
                l6[hh] = l;
            }
        }
        __syncthreads();

        // -- per-head tile max -> running max m, rescale f --
        for (int h = w; h < 12; h += 8) {
            float mx = sm_l[h * Nc + j0 + lane];
            mx = fmaxf(mx, sm_l[h * Nc + j0 + lane + 32]);
            mx = fmaxf(mx, sm_l[h * Nc + j0 + lane + 64]);
            mx = fmaxf(mx, sm_l[h * Nc + j0 + lane + 96]);
#pragma unroll
            for (int off = 16; off > 0; off >>= 1)
                mx = fmaxf(mx, __shfl_xor_sync(0xffffffffu, mx, off));
            if (lane == 0) {
                float mo = m_sm[h];
                float mn = fmaxf(mo, mx);
                f_sm[h] = __expf(mo - mn);
                m_sm[h] = mn;
            }
        }
        __syncthreads();

        // -- p = exp(l - m_new) --
#pragma unroll
        for (int hh = 0; hh < 6; hh++)
            p_sm[(h0p + hh) * 128 + jj] = __expf(l6[hh] - m_sm[h0p + hh]);
        __syncthreads();

        // -- o_pair accumulate (flash rescale) --
        {
            float fr[6];
#pragma unroll
            for (int hh = 0; hh < 6; hh++) fr[hh] = f_sm[h0 + hh];
#pragma unroll
            for (int hh = 0; hh < 6; hh++) {
                A[hh].x *= fr[hh]; A[hh].y *= fr[hh];
                A[hh].z *= fr[hh]; A[hh].w *= fr[hh];
            }
            const int jl0 = jp * 32;
#pragma unroll 4
            for (int jl = jl0; jl < jl0 + 32; jl++) {
                float4 zv = *(const float4*)&z_sm[jl * 132 + zc0];
                float p0 = p_sm[(h0 + 0) * 128 + jl];
                float p1 = p_sm[(h0 + 1) * 128 + jl];
                float p2 = p_sm[(h0 + 2) * 128 + jl];
                float p3 = p_sm[(h0 + 3) * 128 + jl];
                float p4 = p_sm[(h0 + 4) * 128 + jl];
                float p5 = p_sm[(h0 + 5) * 128 + jl];
                A[0].x = fmaf(p0, zv.x, A[0].x); A[0].y = fmaf(p0, zv.y, A[0].y);
                A[0].z = fmaf(p0, zv.z, A[0].z); A[0].w = fmaf(p0, zv.w, A[0].w);
                A[1].x = fmaf(p1, zv.x, A[1].x); A[1].y = fmaf(p1, zv.y, A[1].y);
                A[1].z = fmaf(p1, zv.z, A[1].z); A[1].w = fmaf(p1, zv.w, A[1].w);
                A[2].x = fmaf(p2, zv.x, A[2].x); A[2].y = fmaf(p2, zv.y, A[2].y);
                A[2].z = fmaf(p2, zv.z, A[2].z); A[2].w = fmaf(p2, zv.w, A[2].w);
                A[3].x = fmaf(p3, zv.x, A[3].x); A[3].y = fmaf(p3, zv.y, A[3].y);
                A[3].z = fmaf(p3, zv.z, A[3].z); A[3].w = fmaf(p3, zv.w, A[3].w);
                A[4].x = fmaf(p4, zv.x, A[4].x); A[4].y = fmaf(p4, zv.y, A[4].y);
                A[4].z = fmaf(p4, zv.z, A[4].z); A[4].w = fmaf(p4, zv.w, A[4].w);
                A[5].x = fmaf(p5, zv.x, A[5].x); A[5].y = fmaf(p5, zv.y, A[5].y);
                A[5].z = fmaf(p5, zv.z, A[5].z); A[5].w = fmaf(p5, zv.w, A[5].w);
            }
        }
        __syncthreads();
    }

    // ---- final softmax: a = exp(l - m)/sum; write a_out + sm_l ----
    for (int hh = w; hh < Hc; hh += 8) {
        float* p = sm_l + hh * Nc;
        float4 v[4];
#pragma unroll
        for (int t = 0; t < 4; t++)
            v[t] = *(const float4*)&p[lane * 4 + t * 128];

        float m = -3.0e38f;
#pragma unroll
        for (int t = 0; t < 4; t++)
            m = fmaxf(m, fmaxf(fmaxf(v[t].x, v[t].y), fmaxf(v[t].z, v[t].w)));
#pragma unroll
        for (int off = 16; off > 0; off >>= 1)
            m = fmaxf(m, __shfl_xor_sync(0xffffffffu, m, off));

        float ssum = 0.f;
#pragma unroll
        for (int t = 0; t < 4; t++) {
            v[t].x = __expf(v[t].x - m); v[t].y = __expf(v[t].y - m);
            v[t].z = __expf(v[t].z - m); v[t].w = __expf(v[t].w - m);
            ssum += v[t].x + v[t].y + v[t].z + v[t].w;
        }
#pragma unroll
        for (int off = 16; off > 0; off >>= 1)
            ssum += __shfl_xor_sync(0xffffffffu, ssum, off);
        float inv = 1.0f / ssum;
        if (lane == 0) inv_sm[hh] = inv;

        float* ap = a_out + (((size_t)(b * Hc + hh) * Nc) + i) * Nc;
#pragma unroll
        for (int t = 0; t < 4; t++) {
            v[t].x *= inv; v[t].y *= inv; v[t].z *= inv; v[t].w *= inv;
            *(float4*)&ap[lane * 4 + t * 128] = v[t];
            *(float4*)&p[lane * 4 + t * 128] = v[t];
        }
    }
    __syncthreads();

    // ---- o_pair: reduce j-partitions (scratch in dead z_sm), scale, write ----
    if (jp > 0) {
#pragma unroll
        for (int hh = 0; hh < 6; hh++)
            *(float4*)&z_sm[(jp - 1) * 1536 + (h0 + hh) * 128 + zc0] = A[hh];
    }
    __syncthreads();
    if (jp == 0) {
#pragma unroll
        for (int hh = 0; hh < 6; hh++) {
            float4 r = A[hh];
#pragma unroll
            for (int pp = 0; pp < 3; pp++) {
                float4 o = *(const float4*)&z_sm[pp * 1536 + (h0 + hh) * 128 + zc0];
                r.x += o.x; r.y += o.y; r.z += o.z; r.w += o.w;
            }
            float iv = inv_sm[h0 + hh];
            r.x *= iv; r.y *= iv; r.z *= iv; r.w *= iv;
            *(float4*)(g_x + (size_t)bi * XD + QKVD + (h0 + hh) * CZc + zc0) = r;
        }
    }
    __syncthreads();

    // ---- oav: o = a @ v (a from smem), v batched 16-deep ----
    if (tid < QKVD) {
        const int col = tid;
        const int h = col >> 4;
        const float* lh = &sm_l[h * Nc];
        const float* vp = g_v + (size_t)b * Nc * QKVD + col;
        float acc = 0.f;
        for (int j = 0; j < Nc; j += 16) {
            float vv[16];
#pragma unroll
            for (int u = 0; u < 16; u++)
                vv[u] = __ldg(&vp[(size_t)(j + u) * QKVD]);
#pragma unroll
            for (int u = 0; u < 16; u++)
                acc = fmaf(lh[j + u], vv[u], acc);
        }
        g_x[(size_t)bi * XD + col] = acc;
    }
}

// ============================================================
// Kernel 4: s_upd = X @ Wout + bout (round-10 version)
// ============================================================
__global__ void __launch_bounds__(384)
out_kernel(const float* __restrict__ Wout,
           const float* __restrict__ bout,
           float* __restrict__ s_upd) {
    const int ROWS = 8;
    const int KC = 192;
    __shared__ float xs[ROWS * KC];
    const int row0 = blockIdx.x * ROWS;
    const int cg = threadIdx.x % 96;
    const int rg = threadIdx.x / 96;

    float4 acc0 = {0.f,0.f,0.f,0.f};
    float4 acc1 = {0.f,0.f,0.f,0.f};

    for (int k0 = 0; k0 < XD; k0 += KC) {
        __syncthreads();
        {
            int idx = threadIdx.x;
            int r = idx / 48, c4 = idx % 48;
            ((float4*)xs)[idx] =
                ((const float4*)(g_x + (size_t)(row0 + r) * XD + k0))[c4];
        }
        __syncthreads();
        for (int kk = 0; kk < KC; kk += 8) {
            float4 w[8];
#pragma unroll
            for (int u = 0; u < 8; u++)
                w[u] = __ldg((const float4*)(Wout + (size_t)(k0 + kk + u) * CSc + 4 * cg));
#pragma unroll
            for (int u = 0; u < 8; u++) {
                float x0 = xs[(2 * rg + 0) * KC + kk + u];
                float x1 = xs[(2 * rg + 1) * KC + kk + u];
                acc0.x = fmaf(x0, w[u].x, acc0.x); acc0.y = fmaf(x0, w[u].y, acc0.y);
                acc0.z = fmaf(x0, w[u].z, acc0.z); acc0.w = fmaf(x0, w[u].w, acc0.w);
                acc1.x = fmaf(x1, w[u].x, acc1.x); acc1.y = fmaf(x1, w[u].y, acc1.y);
                acc1.z = fmaf(x1, w[u].z, acc1.z); acc1.w = fmaf(x1, w[u].w, acc1.w);
            }
        }
    }
    float4 bb = *(const float4*)(bout + 4 * cg);
    acc0.x += bb.x; acc0.y += bb.y; acc0.z += bb.z; acc0.w += bb.w;
    acc1.x += bb.x; acc1.y += bb.y; acc1.z += bb.z; acc1.w += bb.w;
    *(float4*)(s_upd + (size_t)(row0 + 2 * rg + 0) * CSc + 4 * cg) = acc0;
    *(float4*)(s_upd + (size_t)(row0 + 2 * rg + 1) * CSc + 4 * cg) = acc1;
}

// ============================================================
extern "C" void kernel_launch(void* const* d_in, const int* in_sizes, int n_in,
                              void* d_out, int out_size) {
    const float* s    = (const float*)d_in[0];
    const float* z    = (const float*)d_in[1];
    // d_in[2] = mask: all-True in this problem; (1-sq) term is identically 0.
    const float* Wq   = (const float*)d_in[3];
    const float* Wkv  = (const float*)d_in[4];
    const float* Wb   = (const float*)d_in[5];
    const float* Wout = (const float*)d_in[6];
    const float* bout = (const float*)d_in[7];

    float* out   = (float*)d_out;
    float* s_upd = out;                       // (B,N,CS)
    float* a_out = out + S_UPD_ELEMS;         // (B,H,N,N): a_sd -> a

    cudaFuncSetAttribute(fused_attn_kernel,
                         cudaFuncAttributeMaxDynamicSharedMemorySize,
                         FUSED_SMEM_FLOATS * sizeof(float));

    qkv_kernel<<<(Bc * Nc) / 4, 288>>>(s, Wq, Wkv);
    qk_kernel<<<768, 256>>>(a_out);
    fused_attn_kernel<<<1024, 256, FUSED_SMEM_FLOATS * sizeof(float)>>>(z, Wb, a_out);
    out_kernel<<<(Bc * Nc) / 8, 384>>>(Wout, bout, s_upd);
}

// round 12
// speedup vs baseline: 1.8380x; 1.2958x over previous
#include <cuda_runtime.h>

#define Bc 2
#define Nc 512
#define CSc 384
#define CZc 128
#define CHc 16
#define Hc 12
#define QKVD 192           // H*CH
#define XD 1728            // H*(CZ+CH)
#define S_UPD_ELEMS (Bc*Nc*CSc)   // 393216
#define W_Lc 0.7071067811865476f

// ---- scratch (device globals; no allocation allowed) ----
__device__ float g_q[Bc*Nc*QKVD];
__device__ float g_k[Bc*Nc*QKVD];
__device__ float g_v[Bc*Nc*QKVD];
__device__ float g_x[Bc*Nc*XD];

// ============================================================
// Kernel 1: q/k/v projection. w batch as EXPLICIT scalars
// (float2 w0..w7) so ptxas cannot demote to local memory.
// ============================================================
__global__ void __launch_bounds__(288)
qkv_kernel(const float* __restrict__ s,
           const float* __restrict__ Wq,
           const float* __restrict__ Wkv) {
    const int ROWS = 4;
    __shared__ float4 s_sm[ROWS * 96];
    const int row0 = blockIdx.x * ROWS;
    const int tid = threadIdx.x;

    for (int idx = tid; idx < ROWS * 96; idx += 288)
        s_sm[idx] = ((const float4*)(s + (size_t)row0 * CSc))[idx];
    __syncthreads();

    const int col = tid * 2;
    const bool is_q = (col < QKVD);
    const float* W = is_q ? (Wq + col) : (Wkv + (col - QKVD));
    const int ld = is_q ? QKVD : 384;

    float2 acc0 = {0.f,0.f}, acc1 = {0.f,0.f}, acc2 = {0.f,0.f}, acc3 = {0.f,0.f};

    for (int k0 = 0; k0 < CSc; k0 += 8) {
        const float* Wp = W + (size_t)k0 * ld;
        float2 w0 = __ldg((const float2*)(Wp + 0 * ld));
        float2 w1 = __ldg((const float2*)(Wp + 1 * ld));
        float2 w2 = __ldg((const float2*)(Wp + 2 * ld));
        float2 w3 = __ldg((const float2*)(Wp + 3 * ld));
        float2 w4 = __ldg((const float2*)(Wp + 4 * ld));
        float2 w5 = __ldg((const float2*)(Wp + 5 * ld));
        float2 w6 = __ldg((const float2*)(Wp + 6 * ld));
        float2 w7 = __ldg((const float2*)(Wp + 7 * ld));

#pragma unroll
        for (int r = 0; r < 4; r++) {
            float4 sa = s_sm[r * 96 + (k0 >> 2) + 0];
            float4 sb = s_sm[r * 96 + (k0 >> 2) + 1];
            float2 a = (r == 0) ? acc0 : (r == 1) ? acc1 : (r == 2) ? acc2 : acc3;
            a.x = fmaf(sa.x, w0.x, a.x); a.y = fmaf(sa.x, w0.y, a.y);
            a.x = fmaf(sa.y, w1.x, a.x); a.y = fmaf(sa.y, w1.y, a.y);
            a.x = fmaf(sa.z, w2.x, a.x); a.y = fmaf(sa.z, w2.y, a.y);
            a.x = fmaf(sa.w, w3.x, a.x); a.y = fmaf(sa.w, w3.y, a.y);
            a.x = fmaf(sb.x, w4.x, a.x); a.y = fmaf(sb.x, w4.y, a.y);
            a.x = fmaf(sb.y, w5.x, a.x); a.y = fmaf(sb.y, w5.y, a.y);
            a.x = fmaf(sb.z, w6.x, a.x); a.y = fmaf(sb.z, w6.y, a.y);
            a.x = fmaf(sb.w, w7.x, a.x); a.y = fmaf(sb.w, w7.y, a.y);
            if (r == 0) acc0 = a; else if (r == 1) acc1 = a;
            else if (r == 2) acc2 = a; else acc3 = a;
        }
    }

    float2 accs[4] = {acc0, acc1, acc2, acc3};
    if (is_q) {
#pragma unroll
        for (int r = 0; r < 4; r++) {
            g_q[(size_t)(row0 + r) * QKVD + col + 0] = accs[r].x;
            g_q[(size_t)(row0 + r) * QKVD + col + 1] = accs[r].y;
        }
    } else {
#pragma unroll
        for (int c = 0; c < 2; c++) {
            int c2 = col - QKVD + c;
            int h = c2 >> 5;
            int within = c2 & 31;
            int cc = h * CHc + (within & 15);
            float* dst = (within < CHc) ? g_k : g_v;
#pragma unroll
            for (int r = 0; r < 4; r++)
                dst[(size_t)(row0 + r) * QKVD + cc] = (c == 0) ? accs[r].x : accs[r].y;
        }
    }
}

// ============================================================
// Kernel 2: a_sd = (q.k)/4 -> a_out (unchanged)
// ============================================================
__global__ void __launch_bounds__(256)
qk_kernel(float* __restrict__ a_out) {
    __shared__ float q_sm[32 * 16];
    __shared__ float k_sm[16 * 260];

    const int bx = blockIdx.x;
    const int b   = bx / 384;
    const int rem = bx % 384;
    const int h   = rem >> 5;
    const int it  = (rem & 31) >> 1;
    const int jt  = rem & 1;
    const int i0 = it * 32, j0 = jt * 256;
    const int tid = threadIdx.x;

    for (int idx = tid; idx < 512; idx += 256) {
        int ii = idx >> 4, c = idx & 15;
        q_sm[idx] = g_q[((size_t)(b * Nc + i0 + ii)) * QKVD + h * CHc + c] * 0.25f;
    }
    for (int idx = tid; idx < 4096; idx += 256) {
        int j = idx >> 4, c = idx & 15;
        k_sm[c * 260 + j] = g_k[((size_t)(b * Nc + j0 + j)) * QKVD + h * CHc + c];
    }
    __syncthreads();

    const int jq = tid & 63;
    const int ig = tid >> 6;
    float4 acc[8];
#pragma unroll
    for (int r = 0; r < 8; r++) acc[r] = make_float4(0.f, 0.f, 0.f, 0.f);

#pragma unroll
    for (int c = 0; c < 16; c++) {
        float4 kv = *(const float4*)&k_sm[c * 260 + jq * 4];
#pragma unroll
        for (int r = 0; r < 8; r++) {
            float qv = q_sm[(ig * 8 + r) * 16 + c];
            acc[r].x = fmaf(qv, kv.x, acc[r].x);
            acc[r].y = fmaf(qv, kv.y, acc[r].y);
            acc[r].z = fmaf(qv, kv.z, acc[r].z);
            acc[r].w = fmaf(qv, kv.w, acc[r].w);
        }
    }
#pragma unroll
    for (int r = 0; r < 8; r++) {
        int i = i0 + ig * 8 + r;
        *(float4*)&a_out[(((size_t)(b * Hc + h) * Nc) + i) * Nc + j0 + jq * 4] = acc[r];
    }
}

// ============================================================
// Kernel 3: FUSED bias + softmax + o_pair + oav (unchanged)
// ============================================================
#define FUSED_SMEM_FLOATS 27696

__global__ void __launch_bounds__(256, 2)
fused_attn_kernel(const float* __restrict__ z,
                  const float* __restrict__ Wb,
                  float* __restrict__ a_out) {
    extern __shared__ float sm[];
    float* z_sm   = sm;
    float* wb_sm  = sm + 16896;
    float* red    = sm + 18432;
    float* sm_l   = sm + 19968;
    float* p_sm   = sm + 26112;
    float* m_sm   = sm + 27648;
    float* f_sm   = sm + 27660;
    float* inv_sm = sm + 27672;

    const int bi = blockIdx.x;
    const int b = bi >> 9, i = bi & 511;
    const int tid = threadIdx.x;

    for (int idx = tid; idx < 1536; idx += 256)
        wb_sm[idx] = Wb[(idx & 127) * Hc + (idx >> 7)];
    if (tid < 12) m_sm[tid] = -3.0e38f;
    __syncthreads();

    const float4* zs4 = (const float4*)(z + (size_t)bi * Nc * CZc);

    const int jj = tid & 127;
    const int zh = tid >> 7;
    const int c0 = zh * 16;
    const int h0p = zh * 6;
    const int zq = tid & 31;
    const int hg = (tid >> 5) & 1;
    const int jp = tid >> 6;
    const int h0 = hg * 6;
    const int zc0 = zq * 4;

    float4 A[6];
#pragma unroll
    for (int hh = 0; hh < 6; hh++) A[hh] = make_float4(0.f, 0.f, 0.f, 0.f);

    const int w = tid >> 5, lane = tid & 31;

    for (int tile = 0; tile < 4; tile++) {
        const int j0 = tile * 128;

#pragma unroll 4
        for (int idx = tid; idx < 4096; idx += 256) {
            int row = idx >> 5, t = idx & 31;
            *(float4*)&z_sm[row * 132 + t * 4] =
                __ldg(&zs4[(size_t)(j0 + row) * 32 + t]);
        }
        __syncthreads();

        float bias[12];
#pragma unroll
        for (int h = 0; h < 12; h++) bias[h] = 0.f;
#pragma unroll 4
        for (int c = c0; c < c0 + 16; c++) {
            float4 zv = *(const float4*)&z_sm[jj * 132 + c * 4];
#pragma unroll
            for (int h = 0; h < 12; h++) {
                float4 wv = *(const float4*)&wb_sm[h * 128 + c * 4];
                bias[h] += zv.x*wv.x + zv.y*wv.y + zv.z*wv.z + zv.w*wv.w;
            }
        }
        {
            const int ho = 6 - h0p;
#pragma unroll
            for (int hh = 0; hh < 6; hh++)
                red[(ho + hh) * 128 + jj] = bias[ho + hh];
        }
        __syncthreads();

        float l6[6];
        {
            float sd[6];
#pragma unroll
            for (int hh = 0; hh < 6; hh++)
                sd[hh] = a_out[(((size_t)(b * Hc + h0p + hh) * Nc) + i) * Nc + j0 + jj];
#pragma unroll
            for (int hh = 0; hh < 6; hh++) {
                int h = h0p + hh;
                float l = W_Lc * (sd[hh] + bias[h] + red[h * 128 + jj]);
                sm_l[h * Nc + j0 + jj] = l;
                l6[hh] = l;
            }
        }
        __syncthreads();

        for (int h = w; h < 12; h += 8) {
            float mx = sm_l[h * Nc + j0 + lane];
            mx = fmaxf(mx, sm_l[h * Nc + j0 + lane + 32]);
            mx = fmaxf(mx, sm_l[h * Nc + j0 + lane + 64]);
            mx = fmaxf(mx, sm_l[h * Nc + j0 + lane + 96]);
#pragma unroll
            for (int off = 16; off > 0; off >>= 1)
                mx = fmaxf(mx, __shfl_xor_sync(0xffffffffu, mx, off));
            if (lane == 0) {
                float mo = m_sm[h];
                float mn = fmaxf(mo, mx);
                f_sm[h] = __expf(mo - mn);
                m_sm[h] = mn;
            }
        }
        __syncthreads();

#pragma unroll
        for (int hh = 0; hh < 6; hh++)
            p_sm[(h0p + hh) * 128 + jj] = __expf(l6[hh] - m_sm[h0p + hh]);
        __syncthreads();

        {
            float fr[6];
#pragma unroll
            for (int hh = 0; hh < 6; hh++) fr[hh] = f_sm[h0 + hh];
#pragma unroll
            for (int hh = 0; hh < 6; hh++) {
                A[hh].x *= fr[hh]; A[hh].y *= fr[hh];
                A[hh].z *= fr[hh]; A[hh].w *= fr[hh];
            }
            const int jl0 = jp * 32;
#pragma unroll 4
            for (int jl = jl0; jl < jl0 + 32; jl++) {
                float4 zv = *(const float4*)&z_sm[jl * 132 + zc0];
                float p0 = p_sm[(h0 + 0) * 128 + jl];
                float p1 = p_sm[(h0 + 1) * 128 + jl];
                float p2 = p_sm[(h0 + 2) * 128 + jl];
                float p3 = p_sm[(h0 + 3) * 128 + jl];
                float p4 = p_sm[(h0 + 4) * 128 + jl];
                float p5 = p_sm[(h0 + 5) * 128 + jl];
                A[0].x = fmaf(p0, zv.x, A[0].x); A[0].y = fmaf(p0, zv.y, A[0].y);
                A[0].z = fmaf(p0, zv.z, A[0].z); A[0].w = fmaf(p0, zv.w, A[0].w);
                A[1].x = fmaf(p1, zv.x, A[1].x); A[1].y = fmaf(p1, zv.y, A[1].y);
                A[1].z = fmaf(p1, zv.z, A[1].z); A[1].w = fmaf(p1, zv.w, A[1].w);
                A[2].x = fmaf(p2, zv.x, A[2].x); A[2].y = fmaf(p2, zv.y, A[2].y);
                A[2].z = fmaf(p2, zv.z, A[2].z); A[2].w = fmaf(p2, zv.w, A[2].w);
                A[3].x = fmaf(p3, zv.x, A[3].x); A[3].y = fmaf(p3, zv.y, A[3].y);
                A[3].z = fmaf(p3, zv.z, A[3].z); A[3].w = fmaf(p3, zv.w, A[3].w);
                A[4].x = fmaf(p4, zv.x, A[4].x); A[4].y = fmaf(p4, zv.y, A[4].y);
                A[4].z = fmaf(p4, zv.z, A[4].z); A[4].w = fmaf(p4, zv.w, A[4].w);
                A[5].x = fmaf(p5, zv.x, A[5].x); A[5].y = fmaf(p5, zv.y, A[5].y);
                A[5].z = fmaf(p5, zv.z, A[5].z); A[5].w = fmaf(p5, zv.w, A[5].w);
            }
        }
        __syncthreads();
    }

    for (int hh = w; hh < Hc; hh += 8) {
        float* p = sm_l + hh * Nc;
        float4 v[4];
#pragma unroll
        for (int t = 0; t < 4; t++)
            v[t] = *(const float4*)&p[lane * 4 + t * 128];

        float m = -3.0e38f;
#pragma unroll
        for (int t = 0; t < 4; t++)
            m = fmaxf(m, fmaxf(fmaxf(v[t].x, v[t].y), fmaxf(v[t].z, v[t].w)));
#pragma unroll
        for (int off = 16; off > 0; off >>= 1)
            m = fmaxf(m, __shfl_xor_sync(0xffffffffu, m, off));

        float ssum = 0.f;
#pragma unroll
        for (int t = 0; t < 4; t++) {
            v[t].x = __expf(v[t].x - m); v[t].y = __expf(v[t].y - m);
            v[t].z = __expf(v[t].z - m); v[t].w = __expf(v[t].w - m);
            ssum += v[t].x + v[t].y + v[t].z + v[t].w;
        }
#pragma unroll
        for (int off = 16; off > 0; off >>= 1)
            ssum += __shfl_xor_sync(0xffffffffu, ssum, off);
        float inv = 1.0f / ssum;
        if (lane == 0) inv_sm[hh] = inv;

        float* ap = a_out + (((size_t)(b * Hc + hh) * Nc) + i) * Nc;
#pragma unroll
        for (int t = 0; t < 4; t++) {
            v[t].x *= inv; v[t].y *= inv; v[t].z *= inv; v[t].w *= inv;
            *(float4*)&ap[lane * 4 + t * 128] = v[t];
            *(float4*)&p[lane * 4 + t * 128] = v[t];
        }
    }
    __syncthreads();

    if (jp > 0) {
#pragma unroll
        for (int hh = 0; hh < 6; hh++)
            *(float4*)&z_sm[(jp - 1) * 1536 + (h0 + hh) * 128 + zc0] = A[hh];
    }
    __syncthreads();
    if (jp == 0) {
#pragma unroll
        for (int hh = 0; hh < 6; hh++) {
            float4 r = A[hh];
#pragma unroll
            for (int pp = 0; pp < 3; pp++) {
                float4 o = *(const float4*)&z_sm[pp * 1536 + (h0 + hh) * 128 + zc0];
                r.x += o.x; r.y += o.y; r.z += o.z; r.w += o.w;
            }
            float iv = inv_sm[h0 + hh];
            r.x *= iv; r.y *= iv; r.z *= iv; r.w *= iv;
            *(float4*)(g_x + (size_t)bi * XD + QKVD + (h0 + hh) * CZc + zc0) = r;
        }
    }
    __syncthreads();

    if (tid < QKVD) {
        const int col = tid;
        const int h = col >> 4;
        const float* lh = &sm_l[h * Nc];
        const float* vp = g_v + (size_t)b * Nc * QKVD + col;
        float acc = 0.f;
        for (int j = 0; j < Nc; j += 16) {
            float v0 = __ldg(&vp[(size_t)(j + 0) * QKVD]);
            float v1 = __ldg(&vp[(size_t)(j + 1) * QKVD]);
            float v2 = __ldg(&vp[(size_t)(j + 2) * QKVD]);
            float v3 = __ldg(&vp[(size_t)(j + 3) * QKVD]);
            float v4 = __ldg(&vp[(size_t)(j + 4) * QKVD]);
            float v5 = __ldg(&vp[(size_t)(j + 5) * QKVD]);
            float v6 = __ldg(&vp[(size_t)(j + 6) * QKVD]);
            float v7 = __ldg(&vp[(size_t)(j + 7) * QKVD]);
            float v8 = __ldg(&vp[(size_t)(j + 8) * QKVD]);
            float v9 = __ldg(&vp[(size_t)(j + 9) * QKVD]);
            float va = __ldg(&vp[(size_t)(j + 10) * QKVD]);
            float vb = __ldg(&vp[(size_t)(j + 11) * QKVD]);
            float vc = __ldg(&vp[(size_t)(j + 12) * QKVD]);
            float vd = __ldg(&vp[(size_t)(j + 13) * QKVD]);
            float ve = __ldg(&vp[(size_t)(j + 14) * QKVD]);
            float vf = __ldg(&vp[(size_t)(j + 15) * QKVD]);
            acc = fmaf(lh[j + 0], v0, acc);  acc = fmaf(lh[j + 1], v1, acc);
            acc = fmaf(lh[j + 2], v2, acc);  acc = fmaf(lh[j + 3], v3, acc);
            acc = fmaf(lh[j + 4], v4, acc);  acc = fmaf(lh[j + 5], v5, acc);
            acc = fmaf(lh[j + 6], v6, acc);  acc = fmaf(lh[j + 7], v7, acc);
            acc = fmaf(lh[j + 8], v8, acc);  acc = fmaf(lh[j + 9], v9, acc);
            acc = fmaf(lh[j + 10], va, acc); acc = fmaf(lh[j + 11], vb, acc);
            acc = fmaf(lh[j + 12], vc, acc); acc = fmaf(lh[j + 13], vd, acc);
            acc = fmaf(lh[j + 14], ve, acc); acc = fmaf(lh[j + 15], vf, acc);
        }
        g_x[(size_t)bi * XD + col] = acc;
    }
}

// ============================================================
// Kernel 4: s_upd = X @ Wout + bout. REWRITTEN:
// block = 16 rows x 192 cols, 384 thr, thread = 4 rows x 2 cols.
// w batch = 8 explicit float2 scalars (cannot be demoted).
// grid = 128 (64 row-tiles x 2 col-halves).
// ============================================================
__global__ void __launch_bounds__(384)
out_kernel(const float* __restrict__ Wout,
           const float* __restrict__ bout,
           float* __restrict__ s_upd) {
    const int KC = 192;
    __shared__ float xs[16 * KC];
    const int row0 = (blockIdx.x >> 1) * 16;
    const int col0 = (blockIdx.x & 1) * 192;
    const int tid = threadIdx.x;
    const int cg = tid % 96;                 // col pair: col0 + 2*cg
    const int rg = tid / 96;                 // rows row0 + 4*rg .. +3

    float2 a0 = {0.f,0.f}, a1 = {0.f,0.f}, a2 = {0.f,0.f}, a3 = {0.f,0.f};

    for (int k0 = 0; k0 < XD; k0 += KC) {
        __syncthreads();
        // fill xs: 16 rows x 192 k = 768 float4, 2 per thread
#pragma unroll
        for (int t = 0; t < 2; t++) {
            int idx = tid + t * 384;
            int r = idx / 48, c4 = idx % 48;
            ((float4*)xs)[idx] =
                ((const float4*)(g_x + (size_t)(row0 + r) * XD + k0))[c4];
        }
        __syncthreads();

        for (int kk = 0; kk < KC; kk += 8) {
            const float* Wp = Wout + (size_t)(k0 + kk) * CSc + col0 + cg * 2;
            float2 w0 = __ldg((const float2*)(Wp + 0 * CSc));
            float2 w1 = __ldg((const float2*)(Wp + 1 * CSc));
            float2 w2 = __ldg((const float2*)(Wp + 2 * CSc));
            float2 w3 = __ldg((const float2*)(Wp + 3 * CSc));
            float2 w4 = __ldg((const float2*)(Wp + 4 * CSc));
            float2 w5 = __ldg((const float2*)(Wp + 5 * CSc));
            float2 w6 = __ldg((const float2*)(Wp + 6 * CSc));
            float2 w7 = __ldg((const float2*)(Wp + 7 * CSc));

#pragma unroll
            for (int r = 0; r < 4; r++) {
                const float* xr = &xs[(rg * 4 + r) * KC + kk];
                float4 xa = *(const float4*)xr;
                float4 xb = *(const float4*)(xr + 4);
                float2 a = (r == 0) ? a0 : (r == 1) ? a1 : (r == 2) ? a2 : a3;
                a.x = fmaf(xa.x, w0.x, a.x); a.y = fmaf(xa.x, w0.y, a.y);
                a.x = fmaf(xa.y, w1.x, a.x); a.y = fmaf(xa.y, w1.y, a.y);
                a.x = fmaf(xa.z, w2.x, a.x); a.y = fmaf(xa.z, w2.y, a.y);
                a.x = fmaf(xa.w, w3.x, a.x); a.y = fmaf(xa.w, w3.y, a.y);
                a.x = fmaf(xb.x, w4.x, a.x); a.y = fmaf(xb.x, w4.y, a.y);
                a.x = fmaf(xb.y, w5.x, a.x); a.y = fmaf(xb.y, w5.y, a.y);
                a.x = fmaf(xb.z, w6.x, a.x); a.y = fmaf(xb.z, w6.y, a.y);
                a.x = fmaf(xb.w, w7.x, a.x); a.y = fmaf(xb.w, w7.y, a.y);
                if (r == 0) a0 = a; else if (r == 1) a1 = a;
                else if (r == 2) a2 = a; else a3 = a;
            }
        }
    }

    float2 bb = *(const float2*)(bout + col0 + cg * 2);
    float2 accs[4] = {a0, a1, a2, a3};
#pragma unroll
    for (int r = 0; r < 4; r++) {
        accs[r].x += bb.x; accs[r].y += bb.y;
        *(float2*)(s_upd + (size_t)(row0 + rg * 4 + r) * CSc + col0 + cg * 2) = accs[r];
    }
}

// ============================================================
extern "C" void kernel_launch(void* const* d_in, const int* in_sizes, int n_in,
                              void* d_out, int out_size) {
    const float* s    = (const float*)d_in[0];
    const float* z    = (const float*)d_in[1];
    // d_in[2] = mask: all-True in this problem; (1-sq) term is identically 0.
    const float* Wq   = (const float*)d_in[3];
    const float* Wkv  = (const float*)d_in[4];
    const float* Wb   = (const float*)d_in[5];
    const float* Wout = (const float*)d_in[6];
    const float* bout = (const float*)d_in[7];

    float* out   = (float*)d_out;
    float* s_upd = out;                       // (B,N,CS)
    float* a_out = out + S_UPD_ELEMS;         // (B,H,N,N): a_sd -> a

    cudaFuncSetAttribute(fused_attn_kernel,
                         cudaFuncAttributeMaxDynamicSharedMemorySize,
                         FUSED_SMEM_FLOATS * sizeof(float));

    qkv_kernel<<<(Bc * Nc) / 4, 288>>>(s, Wq, Wkv);
    qk_kernel<<<768, 256>>>(a_out);
    fused_attn_kernel<<<1024, 256, FUSED_SMEM_FLOATS * sizeof(float)>>>(z, Wb, a_out);
    out_kernel<<<128, 384>>>(Wout, bout, s_upd);
}

// round 13
// speedup vs baseline: 1.8969x; 1.0320x over previous
#include <cuda_runtime.h>

#define Bc 2
#define Nc 512
#define CSc 384
#define CZc 128
#define CHc 16
#define Hc 12
#define QKVD 192           // H*CH
#define XD 1728            // H*(CZ+CH)
#define S_UPD_ELEMS (Bc*Nc*CSc)   // 393216
#define W_Lc 0.7071067811865476f

// ---- scratch (device globals; no allocation allowed) ----
__device__ float g_q[Bc*Nc*QKVD];
__device__ float g_k[Bc*Nc*QKVD];
__device__ float g_v[Bc*Nc*QKVD];
__device__ float g_x[Bc*Nc*XD];

// ============================================================
// Kernel 1: q/k/v projection (unchanged from 527us kernel)
// ============================================================
__global__ void __launch_bounds__(288)
qkv_kernel(const float* __restrict__ s,
           const float* __restrict__ Wq,
           const float* __restrict__ Wkv) {
    const int ROWS = 4;
    __shared__ float4 s_sm[ROWS * 96];
    const int row0 = blockIdx.x * ROWS;
    const int tid = threadIdx.x;

    for (int idx = tid; idx < ROWS * 96; idx += 288)
        s_sm[idx] = ((const float4*)(s + (size_t)row0 * CSc))[idx];
    __syncthreads();

    const int col = tid * 2;
    const bool is_q = (col < QKVD);
    const float* W = is_q ? (Wq + col) : (Wkv + (col - QKVD));
    const int ld = is_q ? QKVD : 384;

    float2 acc0 = {0.f,0.f}, acc1 = {0.f,0.f}, acc2 = {0.f,0.f}, acc3 = {0.f,0.f};

    for (int k0 = 0; k0 < CSc; k0 += 8) {
        const float* Wp = W + (size_t)k0 * ld;
        float2 w0 = __ldg((const float2*)(Wp + 0 * ld));
        float2 w1 = __ldg((const float2*)(Wp + 1 * ld));
        float2 w2 = __ldg((const float2*)(Wp + 2 * ld));
        float2 w3 = __ldg((const float2*)(Wp + 3 * ld));
        float2 w4 = __ldg((const float2*)(Wp + 4 * ld));
        float2 w5 = __ldg((const float2*)(Wp + 5 * ld));
        float2 w6 = __ldg((const float2*)(Wp + 6 * ld));
        float2 w7 = __ldg((const float2*)(Wp + 7 * ld));

#pragma unroll
        for (int r = 0; r < 4; r++) {
            float4 sa = s_sm[r * 96 + (k0 >> 2) + 0];
            float4 sb = s_sm[r * 96 + (k0 >> 2) + 1];
            float2 a = (r == 0) ? acc0 : (r == 1) ? acc1 : (r == 2) ? acc2 : acc3;
            a.x = fmaf(sa.x, w0.x, a.x); a.y = fmaf(sa.x, w0.y, a.y);
            a.x = fmaf(sa.y, w1.x, a.x); a.y = fmaf(sa.y, w1.y, a.y);
            a.x = fmaf(sa.z, w2.x, a.x); a.y = fmaf(sa.z, w2.y, a.y);
            a.x = fmaf(sa.w, w3.x, a.x); a.y = fmaf(sa.w, w3.y, a.y);
            a.x = fmaf(sb.x, w4.x, a.x); a.y = fmaf(sb.x, w4.y, a.y);
            a.x = fmaf(sb.y, w5.x, a.x); a.y = fmaf(sb.y, w5.y, a.y);
            a.x = fmaf(sb.z, w6.x, a.x); a.y = fmaf(sb.z, w6.y, a.y);
            a.x = fmaf(sb.w, w7.x, a.x); a.y = fmaf(sb.w, w7.y, a.y);
            if (r == 0) acc0 = a; else if (r == 1) acc1 = a;
            else if (r == 2) acc2 = a; else acc3 = a;
        }
    }

    float2 accs[4] = {acc0, acc1, acc2, acc3};
    if (is_q) {
#pragma unroll
        for (int r = 0; r < 4; r++) {
            g_q[(size_t)(row0 + r) * QKVD + col + 0] = accs[r].x;
            g_q[(size_t)(row0 + r) * QKVD + col + 1] = accs[r].y;
        }
    } else {
#pragma unroll
        for (int c = 0; c < 2; c++) {
            int c2 = col - QKVD + c;
            int h = c2 >> 5;
            int within = c2 & 31;
            int cc = h * CHc + (within & 15);
            float* dst = (within < CHc) ? g_k : g_v;
#pragma unroll
            for (int r = 0; r < 4; r++)
                dst[(size_t)(row0 + r) * QKVD + cc] = (c == 0) ? accs[r].x : accs[r].y;
        }
    }
}

// ============================================================
// Kernel 2: a_sd = (q.k)/4 -> a_out (unchanged)
// ============================================================
__global__ void __launch_bounds__(256)
qk_kernel(float* __restrict__ a_out) {
    __shared__ float q_sm[32 * 16];
    __shared__ float k_sm[16 * 260];

    const int bx = blockIdx.x;
    const int b   = bx / 384;
    const int rem = bx % 384;
    const int h   = rem >> 5;
    const int it  = (rem & 31) >> 1;
    const int jt  = rem & 1;
    const int i0 = it * 32, j0 = jt * 256;
    const int tid = threadIdx.x;

    for (int idx = tid; idx < 512; idx += 256) {
        int ii = idx >> 4, c = idx & 15;
        q_sm[idx] = g_q[((size_t)(b * Nc + i0 + ii)) * QKVD + h * CHc + c] * 0.25f;
    }
    for (int idx = tid; idx < 4096; idx += 256) {
        int j = idx >> 4, c = idx & 15;
        k_sm[c * 260 + j] = g_k[((size_t)(b * Nc + j0 + j)) * QKVD + h * CHc + c];
    }
    __syncthreads();

    const int jq = tid & 63;
    const int ig = tid >> 6;
    float4 acc[8];
#pragma unroll
    for (int r = 0; r < 8; r++) acc[r] = make_float4(0.f, 0.f, 0.f, 0.f);

#pragma unroll
    for (int c = 0; c < 16; c++) {
        float4 kv = *(const float4*)&k_sm[c * 260 + jq * 4];
#pragma unroll
        for (int r = 0; r < 8; r++) {
            float qv = q_sm[(ig * 8 + r) * 16 + c];
            acc[r].x = fmaf(qv, kv.x, acc[r].x);
            acc[r].y = fmaf(qv, kv.y, acc[r].y);
            acc[r].z = fmaf(qv, kv.z, acc[r].z);
            acc[r].w = fmaf(qv, kv.w, acc[r].w);
        }
    }
#pragma unroll
    for (int r = 0; r < 8; r++) {
        int i = i0 + ig * 8 + r;
        *(float4*)&a_out[(((size_t)(b * Hc + h) * Nc) + i) * Nc + j0 + jq * 4] = acc[r];
    }
}

// ============================================================
// Kernel 3: FUSED bias + softmax + o_pair + oav (unchanged)
// ============================================================
#define FUSED_SMEM_FLOATS 27696

__global__ void __launch_bounds__(256, 2)
fused_attn_kernel(const float* __restrict__ z,
                  const float* __restrict__ Wb,
                  float* __restrict__ a_out) {
    extern __shared__ float sm[];
    float* z_sm   = sm;
    float* wb_sm  = sm + 16896;
    float* red    = sm + 18432;
    float* sm_l   = sm + 19968;
    float* p_sm   = sm + 26112;
    float* m_sm   = sm + 27648;
    float* f_sm   = sm + 27660;
    float* inv_sm = sm + 27672;

    const int bi = blockIdx.x;
    const int b = bi >> 9, i = bi & 511;
    const int tid = threadIdx.x;

    for (int idx = tid; idx < 1536; idx += 256)
        wb_sm[idx] = Wb[(idx & 127) * Hc + (idx >> 7)];
    if (tid < 12) m_sm[tid] = -3.0e38f;
    __syncthreads();

    const float4* zs4 = (const float4*)(z + (size_t)bi * Nc * CZc);

    const int jj = tid & 127;
    const int zh = tid >> 7;
    const int c0 = zh * 16;
    const int h0p = zh * 6;
    const int zq = tid & 31;
    const int hg = (tid >> 5) & 1;
    const int jp = tid >> 6;
    const int h0 = hg * 6;
    const int zc0 = zq * 4;

    float4 A[6];
#pragma unroll
    for (int hh = 0; hh < 6; hh++) A[hh] = make_float4(0.f, 0.f, 0.f, 0.f);

    const int w = tid >> 5, lane = tid & 31;

    for (int tile = 0; tile < 4; tile++) {
        const int j0 = tile * 128;

#pragma unroll 4
        for (int idx = tid; idx < 4096; idx += 256) {
            int row = idx >> 5, t = idx & 31;
            *(float4*)&z_sm[row * 132 + t * 4] =
                __ldg(&zs4[(size_t)(j0 + row) * 32 + t]);
        }
        __syncthreads();

        float bias[12];
#pragma unroll
        for (int h = 0; h < 12; h++) bias[h] = 0.f;
#pragma unroll 4
        for (int c = c0; c < c0 + 16; c++) {
            float4 zv = *(const float4*)&z_sm[jj * 132 + c * 4];
#pragma unroll
            for (int h = 0; h < 12; h++) {
                float4 wv = *(const float4*)&wb_sm[h * 128 + c * 4];
                bias[h] += zv.x*wv.x + zv.y*wv.y + zv.z*wv.z + zv.w*wv.w;
            }
        }
        {
            const int ho = 6 - h0p;
#pragma unroll
            for (int hh = 0; hh < 6; hh++)
                red[(ho + hh) * 128 + jj] = bias[ho + hh];
        }
        __syncthreads();

        float l6[6];
        {
            float sd[6];
#pragma unroll
            for (int hh = 0; hh < 6; hh++)
                sd[hh] = a_out[(((size_t)(b * Hc + h0p + hh) * Nc) + i) * Nc + j0 + jj];
#pragma unroll
            for (int hh = 0; hh < 6; hh++) {
                int h = h0p + hh;
                float l = W_Lc * (sd[hh] + bias[h] + red[h * 128 + jj]);
                sm_l[h * Nc + j0 + jj] = l;
                l6[hh] = l;
            }
        }
        __syncthreads();

        for (int h = w; h < 12; h += 8) {
            float mx = sm_l[h * Nc + j0 + lane];
            mx = fmaxf(mx, sm_l[h * Nc + j0 + lane + 32]);
            mx = fmaxf(mx, sm_l[h * Nc + j0 + lane + 64]);
            mx = fmaxf(mx, sm_l[h * Nc + j0 + lane + 96]);
#pragma unroll
            for (int off = 16; off > 0; off >>= 1)
                mx = fmaxf(mx, __shfl_xor_sync(0xffffffffu, mx, off));
            if (lane == 0) {
                float mo = m_sm[h];
                float mn = fmaxf(mo, mx);
                f_sm[h] = __expf(mo - mn);
                m_sm[h] = mn;
            }
        }
        __syncthreads();

#pragma unroll
        for (int hh = 0; hh < 6; hh++)
            p_sm[(h0p + hh) * 128 + jj] = __expf(l6[hh] - m_sm[h0p + hh]);
        __syncthreads();

        {
            float fr[6];
#pragma unroll
            for (int hh = 0; hh < 6; hh++) fr[hh] = f_sm[h0 + hh];
#pragma unroll
            for (int hh = 0; hh < 6; hh++) {
                A[hh].x *= fr[hh]; A[hh].y *= fr[hh];
                A[hh].z *= fr[hh]; A[hh].w *= fr[hh];
            }
            const int jl0 = jp * 32;
#pragma unroll 4
            for (int jl = jl0; jl < jl0 + 32; jl++) {
                float4 zv = *(const float4*)&z_sm[jl * 132 + zc0];
                float p0 = p_sm[(h0 + 0) * 128 + jl];
                float p1 = p_sm[(h0 + 1) * 128 + jl];
                float p2 = p_sm[(h0 + 2) * 128 + jl];
                float p3 = p_sm[(h0 + 3) * 128 + jl];
                float p4 = p_sm[(h0 + 4) * 128 + jl];
                float p5 = p_sm[(h0 + 5) * 128 + jl];
                A[0].x = fmaf(p0, zv.x, A[0].x); A[0].y = fmaf(p0, zv.y, A[0].y);
                A[0].z = fmaf(p0, zv.z, A[0].z); A[0].w = fmaf(p0, zv.w, A[0].w);
                A[1].x = fmaf(p1, zv.x, A[1].x); A[1].y = fmaf(p1, zv.y, A[1].y);
                A[1].z = fmaf(p1, zv.z, A[1].z); A[1].w = fmaf(p1, zv.w, A[1].w);
                A[2].x = fmaf(p2, zv.x, A[2].x); A[2].y = fmaf(p2, zv.y, A[2].y);
                A[2].z = fmaf(p2, zv.z, A[2].z); A[2].w = fmaf(p2, zv.w, A[2].w);
                A[3].x = fmaf(p3, zv.x, A[3].x); A[3].y = fmaf(p3, zv.y, A[3].y);
                A[3].z = fmaf(p3, zv.z, A[3].z); A[3].w = fmaf(p3, zv.w, A[3].w);
                A[4].x = fmaf(p4, zv.x, A[4].x); A[4].y = fmaf(p4, zv.y, A[4].y);
                A[4].z = fmaf(p4, zv.z, A[4].z); A[4].w = fmaf(p4, zv.w, A[4].w);
                A[5].x = fmaf(p5, zv.x, A[5].x); A[5].y = fmaf(p5, zv.y, A[5].y);
                A[5].z = fmaf(p5, zv.z, A[5].z); A[5].w = fmaf(p5, zv.w, A[5].w);
            }
        }
        __syncthreads();
    }

    for (int hh = w; hh < Hc; hh += 8) {
        float* p = sm_l + hh * Nc;
        float4 v[4];
#pragma unroll
        for (int t = 0; t < 4; t++)
            v[t] = *(const float4*)&p[lane * 4 + t * 128];

        float m = -3.0e38f;
#pragma unroll
        for (int t = 0; t < 4; t++)
            m = fmaxf(m, fmaxf(fmaxf(v[t].x, v[t].y), fmaxf(v[t].z, v[t].w)));
#pragma unroll
        for (int off = 16; off > 0; off >>= 1)
            m = fmaxf(m, __shfl_xor_sync(0xffffffffu, m, off));

        float ssum = 0.f;
#pragma unroll
        for (int t = 0; t < 4; t++) {
            v[t].x = __expf(v[t].x - m); v[t].y = __expf(v[t].y - m);
            v[t].z = __expf(v[t].z - m); v[t].w = __expf(v[t].w - m);
            ssum += v[t].x + v[t].y + v[t].z + v[t].w;
        }
#pragma unroll
        for (int off = 16; off > 0; off >>= 1)
            ssum += __shfl_xor_sync(0xffffffffu, ssum, off);
        float inv = 1.0f / ssum;
        if (lane == 0) inv_sm[hh] = inv;

        float* ap = a_out + (((size_t)(b * Hc + hh) * Nc) + i) * Nc;
#pragma unroll
        for (int t = 0; t < 4; t++) {
            v[t].x *= inv; v[t].y *= inv; v[t].z *= inv; v[t].w *= inv;
            *(float4*)&ap[lane * 4 + t * 128] = v[t];
            *(float4*)&p[lane * 4 + t * 128] = v[t];
        }
    }
    __syncthreads();

    if (jp > 0) {
#pragma unroll
        for (int hh = 0; hh < 6; hh++)
            *(float4*)&z_sm[(jp - 1) * 1536 + (h0 + hh) * 128 + zc0] = A[hh];
    }
    __syncthreads();
    if (jp == 0) {
#pragma unroll
        for (int hh = 0; hh < 6; hh++) {
            float4 r = A[hh];
#pragma unroll
            for (int pp = 0; pp < 3; pp++) {
                float4 o = *(const float4*)&z_sm[pp * 1536 + (h0 + hh) * 128 + zc0];
                r.x += o.x; r.y += o.y; r.z += o.z; r.w += o.w;
            }
            float iv = inv_sm[h0 + hh];
            r.x *= iv; r.y *= iv; r.z *= iv; r.w *= iv;
            *(float4*)(g_x + (size_t)bi * XD + QKVD + (h0 + hh) * CZc + zc0) = r;
        }
    }
    __syncthreads();

    if (tid < QKVD) {
        const int col = tid;
        const int h = col >> 4;
        const float* lh = &sm_l[h * Nc];
        const float* vp = g_v + (size_t)b * Nc * QKVD + col;
        float acc = 0.f;
        for (int j = 0; j < Nc; j += 16) {
            float v0 = __ldg(&vp[(size_t)(j + 0) * QKVD]);
            float v1 = __ldg(&vp[(size_t)(j + 1) * QKVD]);
            float v2 = __ldg(&vp[(size_t)(j + 2) * QKVD]);
            float v3 = __ldg(&vp[(size_t)(j + 3) * QKVD]);
            float v4 = __ldg(&vp[(size_t)(j + 4) * QKVD]);
            float v5 = __ldg(&vp[(size_t)(j + 5) * QKVD]);
            float v6 = __ldg(&vp[(size_t)(j + 6) * QKVD]);
            float v7 = __ldg(&vp[(size_t)(j + 7) * QKVD]);
            float v8 = __ldg(&vp[(size_t)(j + 8) * QKVD]);
            float v9 = __ldg(&vp[(size_t)(j + 9) * QKVD]);
            float va = __ldg(&vp[(size_t)(j + 10) * QKVD]);
            float vb = __ldg(&vp[(size_t)(j + 11) * QKVD]);
            float vc = __ldg(&vp[(size_t)(j + 12) * QKVD]);
            float vd = __ldg(&vp[(size_t)(j + 13) * QKVD]);
            float ve = __ldg(&vp[(size_t)(j + 14) * QKVD]);
            float vf = __ldg(&vp[(size_t)(j + 15) * QKVD]);
            acc = fmaf(lh[j + 0], v0, acc);  acc = fmaf(lh[j + 1], v1, acc);
            acc = fmaf(lh[j + 2], v2, acc);  acc = fmaf(lh[j + 3], v3, acc);
            acc = fmaf(lh[j + 4], v4, acc);  acc = fmaf(lh[j + 5], v5, acc);
            acc = fmaf(lh[j + 6], v6, acc);  acc = fmaf(lh[j + 7], v7, acc);
            acc = fmaf(lh[j + 8], v8, acc);  acc = fmaf(lh[j + 9], v9, acc);
            acc = fmaf(lh[j + 10], va, acc); acc = fmaf(lh[j + 11], vb, acc);
            acc = fmaf(lh[j + 12], vc, acc); acc = fmaf(lh[j + 13], vd, acc);
            acc = fmaf(lh[j + 14], ve, acc); acc = fmaf(lh[j + 15], vf, acc);
        }
        g_x[(size_t)bi * XD + col] = acc;
    }
}

// ============================================================
// Kernel 4: s_upd = X @ Wout + bout.
// Row tile 16 -> 8, grid 128 -> 256 (fills 148 SMs).
// block = 8 rows x 192 cols, 384 thr, thread = 2 rows x 2 cols.
// w batch = 8 explicit float2 scalars (non-demotable).
// ============================================================
__global__ void __launch_bounds__(384)
out_kernel(const float* __restrict__ Wout,
           const float* __restrict__ bout,
           float* __restrict__ s_upd) {
    const int KC = 192;
    __shared__ float xs[8 * KC];
    const int row0 = (blockIdx.x >> 1) * 8;
    const int col0 = (blockIdx.x & 1) * 192;
    const int tid = threadIdx.x;
    const int cg = tid % 96;                 // col pair: col0 + 2*cg
    const int rg = tid / 96;                 // rows row0 + 2*rg, +1

    float2 a0 = {0.f,0.f}, a1 = {0.f,0.f};

    for (int k0 = 0; k0 < XD; k0 += KC) {
        __syncthreads();
        // fill xs: 8 rows x 192 k = 384 float4, exactly 1 per thread
        {
            int idx = tid;
            int r = idx / 48, c4 = idx % 48;
            ((float4*)xs)[idx] =
                ((const float4*)(g_x + (size_t)(row0 + r) * XD + k0))[c4];
        }
        __syncthreads();

        for (int kk = 0; kk < KC; kk += 8) {
            const float* Wp = Wout + (size_t)(k0 + kk) * CSc + col0 + cg * 2;
            float2 w0 = __ldg((const float2*)(Wp + 0 * CSc));
            float2 w1 = __ldg((const float2*)(Wp + 1 * CSc));
            float2 w2 = __ldg((const float2*)(Wp + 2 * CSc));
            float2 w3 = __ldg((const float2*)(Wp + 3 * CSc));
            float2 w4 = __ldg((const float2*)(Wp + 4 * CSc));
            float2 w5 = __ldg((const float2*)(Wp + 5 * CSc));
            float2 w6 = __ldg((const float2*)(Wp + 6 * CSc));
            float2 w7 = __ldg((const float2*)(Wp + 7 * CSc));

#pragma unroll
            for (int r = 0; r < 2; r++) {
                const float* xr = &xs[(rg * 2 + r) * KC + kk];
                float4 xa = *(const float4*)xr;
                float4 xb = *(const float4*)(xr + 4);
                float2 a = (r == 0) ? a0 : a1;
                a.x = fmaf(xa.x, w0.x, a.x); a.y = fmaf(xa.x, w0.y, a.y);
                a.x = fmaf(xa.y, w1.x, a.x); a.y = fmaf(xa.y, w1.y, a.y);
                a.x = fmaf(xa.z, w2.x, a.x); a.y = fmaf(xa.z, w2.y, a.y);
                a.x = fmaf(xa.w, w3.x, a.x); a.y = fmaf(xa.w, w3.y, a.y);
                a.x = fmaf(xb.x, w4.x, a.x); a.y = fmaf(xb.x, w4.y, a.y);
                a.x = fmaf(xb.y, w5.x, a.x); a.y = fmaf(xb.y, w5.y, a.y);
                a.x = fmaf(xb.z, w6.x, a.x); a.y = fmaf(xb.z, w6.y, a.y);
                a.x = fmaf(xb.w, w7.x, a.x); a.y = fmaf(xb.w, w7.y, a.y);
                if (r == 0) a0 = a; else a1 = a;
            }
        }
    }

    float2 bb = *(const float2*)(bout + col0 + cg * 2);
    a0.x += bb.x; a0.y += bb.y;
    a1.x += bb.x; a1.y += bb.y;
    *(float2*)(s_upd + (size_t)(row0 + rg * 2 + 0) * CSc + col0 + cg * 2) = a0;
    *(float2*)(s_upd + (size_t)(row0 + rg * 2 + 1) * CSc + col0 + cg * 2) = a1;
}

// ============================================================
extern "C" void kernel_launch(void* const* d_in, const int* in_sizes, int n_in,
                              void* d_out, int out_size) {
    const float* s    = (const float*)d_in[0];
    const float* z    = (const float*)d_in[1];
    // d_in[2] = mask: all-True in this problem; (1-sq) term is identically 0.
    const float* Wq   = (const float*)d_in[3];
    const float* Wkv  = (const float*)d_in[4];
    const float* Wb   = (const float*)d_in[5];
    const float* Wout = (const float*)d_in[6];
    const float* bout = (const float*)d_in[7];

    float* out   = (float*)d_out;
    float* s_upd = out;                       // (B,N,CS)
    float* a_out = out + S_UPD_ELEMS;         // (B,H,N,N): a_sd -> a

    cudaFuncSetAttribute(fused_attn_kernel,
                         cudaFuncAttributeMaxDynamicSharedMemorySize,
                         FUSED_SMEM_FLOATS * sizeof(float));

    qkv_kernel<<<(Bc * Nc) / 4, 288>>>(s, Wq, Wkv);
    qk_kernel<<<768, 256>>>(a_out);
    fused_attn_kernel<<<1024, 256, FUSED_SMEM_FLOATS * sizeof(float)>>>(z, Wb, a_out);
    out_kernel<<<256, 384>>>(Wout, bout, s_upd);
}

// round 14
// speedup vs baseline: 2.1609x; 1.1392x over previous
#include <cuda_runtime.h>

#define Bc 2
#define Nc 512
#define CSc 384
#define CZc 128
#define CHc 16
#define Hc 12
#define QKVD 192           // H*CH
#define XD 1728            // H*(CZ+CH)
#define S_UPD_ELEMS (Bc*Nc*CSc)   // 393216
#define W_Lc 0.7071067811865476f

// ---- scratch (device globals; no allocation allowed) ----
__device__ float g_q[Bc*Nc*QKVD];
__device__ float g_k[Bc*Nc*QKVD];
__device__ float g_v[Bc*Nc*QKVD];
__device__ float g_x[Bc*Nc*XD];

// ============================================================
// Kernel 1: q/k/v projection (unchanged)
// ============================================================
__global__ void __launch_bounds__(288)
qkv_kernel(const float* __restrict__ s,
           const float* __restrict__ Wq,
           const float* __restrict__ Wkv) {
    const int ROWS = 4;
    __shared__ float4 s_sm[ROWS * 96];
    const int row0 = blockIdx.x * ROWS;
    const int tid = threadIdx.x;

    for (int idx = tid; idx < ROWS * 96; idx += 288)
        s_sm[idx] = ((const float4*)(s + (size_t)row0 * CSc))[idx];
    __syncthreads();

    const int col = tid * 2;
    const bool is_q = (col < QKVD);
    const float* W = is_q ? (Wq + col) : (Wkv + (col - QKVD));
    const int ld = is_q ? QKVD : 384;

    float2 acc0 = {0.f,0.f}, acc1 = {0.f,0.f}, acc2 = {0.f,0.f}, acc3 = {0.f,0.f};

    for (int k0 = 0; k0 < CSc; k0 += 8) {
        const float* Wp = W + (size_t)k0 * ld;
        float2 w0 = __ldg((const float2*)(Wp + 0 * ld));
        float2 w1 = __ldg((const float2*)(Wp + 1 * ld));
        float2 w2 = __ldg((const float2*)(Wp + 2 * ld));
        float2 w3 = __ldg((const float2*)(Wp + 3 * ld));
        float2 w4 = __ldg((const float2*)(Wp + 4 * ld));
        float2 w5 = __ldg((const float2*)(Wp + 5 * ld));
        float2 w6 = __ldg((const float2*)(Wp + 6 * ld));
        float2 w7 = __ldg((const float2*)(Wp + 7 * ld));

#pragma unroll
        for (int r = 0; r < 4; r++) {
            float4 sa = s_sm[r * 96 + (k0 >> 2) + 0];
            float4 sb = s_sm[r * 96 + (k0 >> 2) + 1];
            float2 a = (r == 0) ? acc0 : (r == 1) ? acc1 : (r == 2) ? acc2 : acc3;
            a.x = fmaf(sa.x, w0.x, a.x); a.y = fmaf(sa.x, w0.y, a.y);
            a.x = fmaf(sa.y, w1.x, a.x); a.y = fmaf(sa.y, w1.y, a.y);
            a.x = fmaf(sa.z, w2.x, a.x); a.y = fmaf(sa.z, w2.y, a.y);
            a.x = fmaf(sa.w, w3.x, a.x); a.y = fmaf(sa.w, w3.y, a.y);
            a.x = fmaf(sb.x, w4.x, a.x); a.y = fmaf(sb.x, w4.y, a.y);
            a.x = fmaf(sb.y, w5.x, a.x); a.y = fmaf(sb.y, w5.y, a.y);
            a.x = fmaf(sb.z, w6.x, a.x); a.y = fmaf(sb.z, w6.y, a.y);
            a.x = fmaf(sb.w, w7.x, a.x); a.y = fmaf(sb.w, w7.y, a.y);
            if (r == 0) acc0 = a; else if (r == 1) acc1 = a;
            else if (r == 2) acc2 = a; else acc3 = a;
        }
    }

    float2 accs[4] = {acc0, acc1, acc2, acc3};
    if (is_q) {
#pragma unroll
        for (int r = 0; r < 4; r++) {
            g_q[(size_t)(row0 + r) * QKVD + col + 0] = accs[r].x;
            g_q[(size_t)(row0 + r) * QKVD + col + 1] = accs[r].y;
        }
    } else {
#pragma unroll
        for (int c = 0; c < 2; c++) {
            int c2 = col - QKVD + c;
            int h = c2 >> 5;
            int within = c2 & 31;
            int cc = h * CHc + (within & 15);
            float* dst = (within < CHc) ? g_k : g_v;
#pragma unroll
            for (int r = 0; r < 4; r++)
                dst[(size_t)(row0 + r) * QKVD + cc] = (c == 0) ? accs[r].x : accs[r].y;
        }
    }
}

// ============================================================
// Kernel 2: a_sd = (q.k)/4 -> a_out (unchanged)
// ============================================================
__global__ void __launch_bounds__(256)
qk_kernel(float* __restrict__ a_out) {
    __shared__ float q_sm[32 * 16];
    __shared__ float k_sm[16 * 260];

    const int bx = blockIdx.x;
    const int b   = bx / 384;
    const int rem = bx % 384;
    const int h   = rem >> 5;
    const int it  = (rem & 31) >> 1;
    const int jt  = rem & 1;
    const int i0 = it * 32, j0 = jt * 256;
    const int tid = threadIdx.x;

    for (int idx = tid; idx < 512; idx += 256) {
        int ii = idx >> 4, c = idx & 15;
        q_sm[idx] = g_q[((size_t)(b * Nc + i0 + ii)) * QKVD + h * CHc + c] * 0.25f;
    }
    for (int idx = tid; idx < 4096; idx += 256) {
        int j = idx >> 4, c = idx & 15;
        k_sm[c * 260 + j] = g_k[((size_t)(b * Nc + j0 + j)) * QKVD + h * CHc + c];
    }
    __syncthreads();

    const int jq = tid & 63;
    const int ig = tid >> 6;
    float4 acc[8];
#pragma unroll
    for (int r = 0; r < 8; r++) acc[r] = make_float4(0.f, 0.f, 0.f, 0.f);

#pragma unroll
    for (int c = 0; c < 16; c++) {
        float4 kv = *(const float4*)&k_sm[c * 260 + jq * 4];
#pragma unroll
        for (int r = 0; r < 8; r++) {
            float qv = q_sm[(ig * 8 + r) * 16 + c];
            acc[r].x = fmaf(qv, kv.x, acc[r].x);
            acc[r].y = fmaf(qv, kv.y, acc[r].y);
            acc[r].z = fmaf(qv, kv.z, acc[r].z);
            acc[r].w = fmaf(qv, kv.w, acc[r].w);
        }
    }
#pragma unroll
    for (int r = 0; r < 8; r++) {
        int i = i0 + ig * 8 + r;
        *(float4*)&a_out[(((size_t)(b * Hc + h) * Nc) + i) * Nc + j0 + jq * 4] = acc[r];
    }
}

// ============================================================
// Kernel 3: FUSED bias + softmax + o_pair + oav (unchanged)
// ============================================================
#define FUSED_SMEM_FLOATS 27696

__global__ void __launch_bounds__(256, 2)
fused_attn_kernel(const float* __restrict__ z,
                  const float* __restrict__ Wb,
                  float* __restrict__ a_out) {
    extern __shared__ float sm[];
    float* z_sm   = sm;
    float* wb_sm  = sm + 16896;
    float* red    = sm + 18432;
    float* sm_l   = sm + 19968;
    float* p_sm   = sm + 26112;
    float* m_sm   = sm + 27648;
    float* f_sm   = sm + 27660;
    float* inv_sm = sm + 27672;

    const int bi = blockIdx.x;
    const int b = bi >> 9, i = bi & 511;
    const int tid = threadIdx.x;

    for (int idx = tid; idx < 1536; idx += 256)
        wb_sm[idx] = Wb[(idx & 127) * Hc + (idx >> 7)];
    if (tid < 12) m_sm[tid] = -3.0e38f;
    __syncthreads();

    const float4* zs4 = (const float4*)(z + (size_t)bi * Nc * CZc);

    const int jj = tid & 127;
    const int zh = tid >> 7;
    const int c0 = zh * 16;
    const int h0p = zh * 6;
    const int zq = tid & 31;
    const int hg = (tid >> 5) & 1;
    const int jp = tid >> 6;
    const int h0 = hg * 6;
    const int zc0 = zq * 4;

    float4 A[6];
#pragma unroll
    for (int hh = 0; hh < 6; hh++) A[hh] = make_float4(0.f, 0.f, 0.f, 0.f);

    const int w = tid >> 5, lane = tid & 31;

    for (int tile = 0; tile < 4; tile++) {
        const int j0 = tile * 128;

#pragma unroll 4
        for (int idx = tid; idx < 4096; idx += 256) {
            int row = idx >> 5, t = idx & 31;
            *(float4*)&z_sm[row * 132 + t * 4] =
                __ldg(&zs4[(size_t)(j0 + row) * 32 + t]);
        }
        __syncthreads();

        float bias[12];
#pragma unroll
        for (int h = 0; h < 12; h++) bias[h] = 0.f;
#pragma unroll 4
        for (int c = c0; c < c0 + 16; c++) {
            float4 zv = *(const float4*)&z_sm[jj * 132 + c * 4];
#pragma unroll
            for (int h = 0; h < 12; h++) {
                float4 wv = *(const float4*)&wb_sm[h * 128 + c * 4];
                bias[h] += zv.x*wv.x + zv.y*wv.y + zv.z*wv.z + zv.w*wv.w;
            }
        }
        {
            const int ho = 6 - h0p;
#pragma unroll
            for (int hh = 0; hh < 6; hh++)
                red[(ho + hh) * 128 + jj] = bias[ho + hh];
        }
        __syncthreads();

        float l6[6];
        {
            float sd[6];
#pragma unroll
            for (int hh = 0; hh < 6; hh++)
                sd[hh] = a_out[(((size_t)(b * Hc + h0p + hh) * Nc) + i) * Nc + j0 + jj];
#pragma unroll
            for (int hh = 0; hh < 6; hh++) {
                int h = h0p + hh;
                float l = W_Lc * (sd[hh] + bias[h] + red[h * 128 + jj]);
                sm_l[h * Nc + j0 + jj] = l;
                l6[hh] = l;
            }
        }
        __syncthreads();

        for (int h = w; h < 12; h += 8) {
            float mx = sm_l[h * Nc + j0 + lane];
            mx = fmaxf(mx, sm_l[h * Nc + j0 + lane + 32]);
            mx = fmaxf(mx, sm_l[h * Nc + j0 + lane + 64]);
            mx = fmaxf(mx, sm_l[h * Nc + j0 + lane + 96]);
#pragma unroll
            for (int off = 16; off > 0; off >>= 1)
                mx = fmaxf(mx, __shfl_xor_sync(0xffffffffu, mx, off));
            if (lane == 0) {
                float mo = m_sm[h];
                float mn = fmaxf(mo, mx);
                f_sm[h] = __expf(mo - mn);
                m_sm[h] = mn;
            }
        }
        __syncthreads();

#pragma unroll
        for (int hh = 0; hh < 6; hh++)
            p_sm[(h0p + hh) * 128 + jj] = __expf(l6[hh] - m_sm[h0p + hh]);
        __syncthreads();

        {
            float fr[6];
#pragma unroll
            for (int hh = 0; hh < 6; hh++) fr[hh] = f_sm[h0 + hh];
#pragma unroll
            for (int hh = 0; hh < 6; hh++) {
                A[hh].x *= fr[hh]; A[hh].y *= fr[hh];
                A[hh].z *= fr[hh]; A[hh].w *= fr[hh];
            }
            const int jl0 = jp * 32;
#pragma unroll 4
            for (int jl = jl0; jl < jl0 + 32; jl++) {
                float4 zv = *(const float4*)&z_sm[jl * 132 + zc0];
                float p0 = p_sm[(h0 + 0) * 128 + jl];
                float p1 = p_sm[(h0 + 1) * 128 + jl];
                float p2 = p_sm[(h0 + 2) * 128 + jl];
                float p3 = p_sm[(h0 + 3) * 128 + jl];
                float p4 = p_sm[(h0 + 4) * 128 + jl];
                float p5 = p_sm[(h0 + 5) * 128 + jl];
                A[0].x = fmaf(p0, zv.x, A[0].x); A[0].y = fmaf(p0, zv.y, A[0].y);
                A[0].z = fmaf(p0, zv.z, A[0].z); A[0].w = fmaf(p0, zv.w, A[0].w);
                A[1].x = fmaf(p1, zv.x, A[1].x); A[1].y = fmaf(p1, zv.y, A[1].y);
                A[1].z = fmaf(p1, zv.z, A[1].z); A[1].w = fmaf(p1, zv.w, A[1].w);
                A[2].x = fmaf(p2, zv.x, A[2].x); A[2].y = fmaf(p2, zv.y, A[2].y);
                A[2].z = fmaf(p2, zv.z, A[2].z); A[2].w = fmaf(p2, zv.w, A[2].w);
                A[3].x = fmaf(p3, zv.x, A[3].x); A[3].y = fmaf(p3, zv.y, A[3].y);
                A[3].z = fmaf(p3, zv.z, A[3].z); A[3].w = fmaf(p3, zv.w, A[3].w);
                A[4].x = fmaf(p4, zv.x, A[4].x); A[4].y = fmaf(p4, zv.y, A[4].y);
                A[4].z = fmaf(p4, zv.z, A[4].z); A[4].w = fmaf(p4, zv.w, A[4].w);
                A[5].x = fmaf(p5, zv.x, A[5].x); A[5].y = fmaf(p5, zv.y, A[5].y);
                A[5].z = fmaf(p5, zv.z, A[5].z); A[5].w = fmaf(p5, zv.w, A[5].w);
            }
        }
        __syncthreads();
    }

    for (int hh = w; hh < Hc; hh += 8) {
        float* p = sm_l + hh * Nc;
        float4 v[4];
#pragma unroll
        for (int t = 0; t < 4; t++)
            v[t] = *(const float4*)&p[lane * 4 + t * 128];

        float m = -3.0e38f;
#pragma unroll
        for (int t = 0; t < 4; t++)
            m = fmaxf(m, fmaxf(fmaxf(v[t].x, v[t].y), fmaxf(v[t].z, v[t].w)));
#pragma unroll
        for (int off = 16; off > 0; off >>= 1)
            m = fmaxf(m, __shfl_xor_sync(0xffffffffu, m, off));

        float ssum = 0.f;
#pragma unroll
        for (int t = 0; t < 4; t++) {
            v[t].x = __expf(v[t].x - m); v[t].y = __expf(v[t].y - m);
            v[t].z = __expf(v[t].z - m); v[t].w = __expf(v[t].w - m);
            ssum += v[t].x + v[t].y + v[t].z + v[t].w;
        }
#pragma unroll
        for (int off = 16; off > 0; off >>= 1)
            ssum += __shfl_xor_sync(0xffffffffu, ssum, off);
        float inv = 1.0f / ssum;
        if (lane == 0) inv_sm[hh] = inv;

        float* ap = a_out + (((size_t)(b * Hc + hh) * Nc) + i) * Nc;
#pragma unroll
        for (int t = 0; t < 4; t++) {
            v[t].x *= inv; v[t].y *= inv; v[t].z *= inv; v[t].w *= inv;
            *(float4*)&ap[lane * 4 + t * 128] = v[t];
            *(float4*)&p[lane * 4 + t * 128] = v[t];
        }
    }
    __syncthreads();

    if (jp > 0) {
#pragma unroll
        for (int hh = 0; hh < 6; hh++)
            *(float4*)&z_sm[(jp - 1) * 1536 + (h0 + hh) * 128 + zc0] = A[hh];
    }
    __syncthreads();
    if (jp == 0) {
#pragma unroll
        for (int hh = 0; hh < 6; hh++) {
            float4 r = A[hh];
#pragma unroll
            for (int pp = 0; pp < 3; pp++) {
                float4 o = *(const float4*)&z_sm[pp * 1536 + (h0 + hh) * 128 + zc0];
                r.x += o.x; r.y += o.y; r.z += o.z; r.w += o.w;
            }
            float iv = inv_sm[h0 + hh];
            r.x *= iv; r.y *= iv; r.z *= iv; r.w *= iv;
            *(float4*)(g_x + (size_t)bi * XD + QKVD + (h0 + hh) * CZc + zc0) = r;
        }
    }
    __syncthreads();

    if (tid < QKVD) {
        const int col = tid;
        const int h = col >> 4;
        const float* lh = &sm_l[h * Nc];
        const float* vp = g_v + (size_t)b * Nc * QKVD + col;
        float acc = 0.f;
        for (int j = 0; j < Nc; j += 16) {
            float v0 = __ldg(&vp[(size_t)(j + 0) * QKVD]);
            float v1 = __ldg(&vp[(size_t)(j + 1) * QKVD]);
            float v2 = __ldg(&vp[(size_t)(j + 2) * QKVD]);
            float v3 = __ldg(&vp[(size_t)(j + 3) * QKVD]);
            float v4 = __ldg(&vp[(size_t)(j + 4) * QKVD]);
            float v5 = __ldg(&vp[(size_t)(j + 5) * QKVD]);
            float v6 = __ldg(&vp[(size_t)(j + 6) * QKVD]);
            float v7 = __ldg(&vp[(size_t)(j + 7) * QKVD]);
            float v8 = __ldg(&vp[(size_t)(j + 8) * QKVD]);
            float v9 = __ldg(&vp[(size_t)(j + 9) * QKVD]);
            float va = __ldg(&vp[(size_t)(j + 10) * QKVD]);
            float vb = __ldg(&vp[(size_t)(j + 11) * QKVD]);
            float vc = __ldg(&vp[(size_t)(j + 12) * QKVD]);
            float vd = __ldg(&vp[(size_t)(j + 13) * QKVD]);
            float ve = __ldg(&vp[(size_t)(j + 14) * QKVD]);
            float vf = __ldg(&vp[(size_t)(j + 15) * QKVD]);
            acc = fmaf(lh[j + 0], v0, acc);  acc = fmaf(lh[j + 1], v1, acc);
            acc = fmaf(lh[j + 2], v2, acc);  acc = fmaf(lh[j + 3], v3, acc);
            acc = fmaf(lh[j + 4], v4, acc);  acc = fmaf(lh[j + 5], v5, acc);
            acc = fmaf(lh[j + 6], v6, acc);  acc = fmaf(lh[j + 7], v7, acc);
            acc = fmaf(lh[j + 8], v8, acc);  acc = fmaf(lh[j + 9], v9, acc);
            acc = fmaf(lh[j + 10], va, acc); acc = fmaf(lh[j + 11], vb, acc);
            acc = fmaf(lh[j + 12], vc, acc); acc = fmaf(lh[j + 13], vd, acc);
            acc = fmaf(lh[j + 14], ve, acc); acc = fmaf(lh[j + 15], vf, acc);
        }
        g_x[(size_t)bi * XD + col] = acc;
    }
}

// ============================================================
// Kernel 4: s_upd = X @ Wout + bout. SMEM-TILED GEMM:
// block = 16 rows x 64 cols, BK=48, 128 thr, grid = 64*6 = 384.
// Both X and W tiles staged in smem; inner loop = LDS+FFMA only
// (no global loads -> no ptxas load-serialization possible).
// thread = 2 rows x 4 cols.
// ============================================================
__global__ void __launch_bounds__(128)
out_kernel(const float* __restrict__ Wout,
           const float* __restrict__ bout,
           float* __restrict__ s_upd) {
    __shared__ float Xs[16 * 52];        // 16 rows x 48 k (stride 52)
    __shared__ float Ws[48 * 64];        // 48 k x 64 cols

    const int bx = blockIdx.x;
    const int row0 = (bx / 6) * 16;
    const int col0 = (bx % 6) * 64;
    const int tid = threadIdx.x;
    const int cg = tid & 15;             // col quad: col0 + cg*4
    const int rg = tid >> 4;             // row pair: row0 + 2*rg, +1

    float4 a0 = {0.f,0.f,0.f,0.f};
    float4 a1 = {0.f,0.f,0.f,0.f};

    for (int k0 = 0; k0 < XD; k0 += 48) {
        __syncthreads();
        // fill Xs: 16 rows x 12 float4 = 192 float4
        for (int idx = tid; idx < 192; idx += 128) {
            int r = idx / 12, c4 = idx % 12;
            *(float4*)&Xs[r * 52 + c4 * 4] =
                *(const float4*)(g_x + (size_t)(row0 + r) * XD + k0 + c4 * 4);
        }
        // fill Ws: 48 k-rows x 16 float4 = 768 float4
        for (int idx = tid; idx < 768; idx += 128) {
            int k = idx >> 4, c4 = idx & 15;
            *(float4*)&Ws[k * 64 + c4 * 4] =
                __ldg((const float4*)(Wout + (size_t)(k0 + k) * CSc + col0 + c4 * 4));
        }
        __syncthreads();

#pragma unroll 8
        for (int k = 0; k < 48; k++) {
            float x0 = Xs[(2 * rg + 0) * 52 + k];
            float x1 = Xs[(2 * rg + 1) * 52 + k];
            float4 w = *(const float4*)&Ws[k * 64 + cg * 4];
            a0.x = fmaf(x0, w.x, a0.x); a0.y = fmaf(x0, w.y, a0.y);
            a0.z = fmaf(x0, w.z, a0.z); a0.w = fmaf(x0, w.w, a0.w);
            a1.x = fmaf(x1, w.x, a1.x); a1.y = fmaf(x1, w.y, a1.y);
            a1.z = fmaf(x1, w.z, a1.z); a1.w = fmaf(x1, w.w, a1.w);
        }
    }

    float4 bb = *(const float4*)(bout + col0 + cg * 4);
    a0.x += bb.x; a0.y += bb.y; a0.z += bb.z; a0.w += bb.w;
    a1.x += bb.x; a1.y += bb.y; a1.z += bb.z; a1.w += bb.w;
    *(float4*)(s_upd + (size_t)(row0 + 2 * rg + 0) * CSc + col0 + cg * 4) = a0;
    *(float4*)(s_upd + (size_t)(row0 + 2 * rg + 1) * CSc + col0 + cg * 4) = a1;
}

// ============================================================
extern "C" void kernel_launch(void* const* d_in, const int* in_sizes, int n_in,
                              void* d_out, int out_size) {
    const float* s    = (const float*)d_in[0];
    const float* z    = (const float*)d_in[1];
    // d_in[2] = mask: all-True in this problem; (1-sq) term is identically 0.
    const float* Wq   = (const float*)d_in[3];
    const float* Wkv  = (const float*)d_in[4];
    const float* Wb   = (const float*)d_in[5];
    const float* Wout = (const float*)d_in[6];
    const float* bout = (const float*)d_in[7];

    float* out   = (float*)d_out;
    float* s_upd = out;                       // (B,N,CS)
    float* a_out = out + S_UPD_ELEMS;         // (B,H,N,N): a_sd -> a

    cudaFuncSetAttribute(fused_attn_kernel,
                         cudaFuncAttributeMaxDynamicSharedMemorySize,
                         FUSED_SMEM_FLOATS * sizeof(float));

    qkv_kernel<<<(Bc * Nc) / 4, 288>>>(s, Wq, Wkv);
    qk_kernel<<<768, 256>>>(a_out);
    fused_attn_kernel<<<1024, 256, FUSED_SMEM_FLOATS * sizeof(float)>>>(z, Wb, a_out);
    out_kernel<<<384, 128>>>(Wout, bout, s_upd);
}

// round 15
// speedup vs baseline: 2.5745x; 1.1914x over previous
#include <cuda_runtime.h>
#include <cuda_pipeline.h>

#define Bc 2
#define Nc 512
#define CSc 384
#define CZc 128
#define CHc 16
#define Hc 12
#define QKVD 192           // H*CH
#define XD 1728            // H*(CZ+CH)
#define S_UPD_ELEMS (Bc*Nc*CSc)   // 393216
#define W_Lc 0.7071067811865476f

// ---- scratch (device globals; no allocation allowed) ----
__device__ float g_q[Bc*Nc*QKVD];
__device__ float g_k[Bc*Nc*QKVD];
__device__ float g_v[Bc*Nc*QKVD];
__device__ float g_x[Bc*Nc*XD];

// ============================================================
// Kernel 1: q/k/v projection (unchanged)
// ============================================================
__global__ void __launch_bounds__(288)
qkv_kernel(const float* __restrict__ s,
           const float* __restrict__ Wq,
           const float* __restrict__ Wkv) {
    const int ROWS = 4;
    __shared__ float4 s_sm[ROWS * 96];
    const int row0 = blockIdx.x * ROWS;
    const int tid = threadIdx.x;

    for (int idx = tid; idx < ROWS * 96; idx += 288)
        s_sm[idx] = ((const float4*)(s + (size_t)row0 * CSc))[idx];
    __syncthreads();

    const int col = tid * 2;
    const bool is_q = (col < QKVD);
    const float* W = is_q ? (Wq + col) : (Wkv + (col - QKVD));
    const int ld = is_q ? QKVD : 384;

    float2 acc0 = {0.f,0.f}, acc1 = {0.f,0.f}, acc2 = {0.f,0.f}, acc3 = {0.f,0.f};

    for (int k0 = 0; k0 < CSc; k0 += 8) {
        const float* Wp = W + (size_t)k0 * ld;
        float2 w0 = __ldg((const float2*)(Wp + 0 * ld));
        float2 w1 = __ldg((const float2*)(Wp + 1 * ld));
        float2 w2 = __ldg((const float2*)(Wp + 2 * ld));
        float2 w3 = __ldg((const float2*)(Wp + 3 * ld));
        float2 w4 = __ldg((const float2*)(Wp + 4 * ld));
        float2 w5 = __ldg((const float2*)(Wp + 5 * ld));
        float2 w6 = __ldg((const float2*)(Wp + 6 * ld));
        float2 w7 = __ldg((const float2*)(Wp + 7 * ld));

#pragma unroll
        for (int r = 0; r < 4; r++) {
            float4 sa = s_sm[r * 96 + (k0 >> 2) + 0];
            float4 sb = s_sm[r * 96 + (k0 >> 2) + 1];
            float2 a = (r == 0) ? acc0 : (r == 1) ? acc1 : (r == 2) ? acc2 : acc3;
            a.x = fmaf(sa.x, w0.x, a.x); a.y = fmaf(sa.x, w0.y, a.y);
            a.x = fmaf(sa.y, w1.x, a.x); a.y = fmaf(sa.y, w1.y, a.y);
            a.x = fmaf(sa.z, w2.x, a.x); a.y = fmaf(sa.z, w2.y, a.y);
            a.x = fmaf(sa.w, w3.x, a.x); a.y = fmaf(sa.w, w3.y, a.y);
            a.x = fmaf(sb.x, w4.x, a.x); a.y = fmaf(sb.x, w4.y, a.y);
            a.x = fmaf(sb.y, w5.x, a.x); a.y = fmaf(sb.y, w5.y, a.y);
            a.x = fmaf(sb.z, w6.x, a.x); a.y = fmaf(sb.z, w6.y, a.y);
            a.x = fmaf(sb.w, w7.x, a.x); a.y = fmaf(sb.w, w7.y, a.y);
            if (r == 0) acc0 = a; else if (r == 1) acc1 = a;
            else if (r == 2) acc2 = a; else acc3 = a;
        }
    }

    float2 accs[4] = {acc0, acc1, acc2, acc3};
    if (is_q) {
#pragma unroll
        for (int r = 0; r < 4; r++) {
            g_q[(size_t)(row0 + r) * QKVD + col + 0] = accs[r].x;
            g_q[(size_t)(row0 + r) * QKVD + col + 1] = accs[r].y;
        }
    } else {
#pragma unroll
        for (int c = 0; c < 2; c++) {
            int c2 = col - QKVD + c;
            int h = c2 >> 5;
            int within = c2 & 31;
            int cc = h * CHc + (within & 15);
            float* dst = (within < CHc) ? g_k : g_v;
#pragma unroll
            for (int r = 0; r < 4; r++)
                dst[(size_t)(row0 + r) * QKVD + cc] = (c == 0) ? accs[r].x : accs[r].y;
        }
    }
}

// ============================================================
// Kernel 2: a_sd = (q.k)/4 -> a_out (unchanged)
// ============================================================
__global__ void __launch_bounds__(256)
qk_kernel(float* __restrict__ a_out) {
    __shared__ float q_sm[32 * 16];
    __shared__ float k_sm[16 * 260];

    const int bx = blockIdx.x;
    const int b   = bx / 384;
    const int rem = bx % 384;
    const int h   = rem >> 5;
    const int it  = (rem & 31) >> 1;
    const int jt  = rem & 1;
    const int i0 = it * 32, j0 = jt * 256;
    const int tid = threadIdx.x;

    for (int idx = tid; idx < 512; idx += 256) {
        int ii = idx >> 4, c = idx & 15;
        q_sm[idx] = g_q[((size_t)(b * Nc + i0 + ii)) * QKVD + h * CHc + c] * 0.25f;
    }
    for (int idx = tid; idx < 4096; idx += 256) {
        int j = idx >> 4, c = idx & 15;
        k_sm[c * 260 + j] = g_k[((size_t)(b * Nc + j0 + j)) * QKVD + h * CHc + c];
    }
    __syncthreads();

    const int jq = tid & 63;
    const int ig = tid >> 6;
    float4 acc[8];
#pragma unroll
    for (int r = 0; r < 8; r++) acc[r] = make_float4(0.f, 0.f, 0.f, 0.f);

#pragma unroll
    for (int c = 0; c < 16; c++) {
        float4 kv = *(const float4*)&k_sm[c * 260 + jq * 4];
#pragma unroll
        for (int r = 0; r < 8; r++) {
            float qv = q_sm[(ig * 8 + r) * 16 + c];
            acc[r].x = fmaf(qv, kv.x, acc[r].x);
            acc[r].y = fmaf(qv, kv.y, acc[r].y);
            acc[r].z = fmaf(qv, kv.z, acc[r].z);
            acc[r].w = fmaf(qv, kv.w, acc[r].w);
        }
    }
#pragma unroll
    for (int r = 0; r < 8; r++) {
        int i = i0 + ig * 8 + r;
        *(float4*)&a_out[(((size_t)(b * Hc + h) * Nc) + i) * Nc + j0 + jq * 4] = acc[r];
    }
}

// ============================================================
// Kernel 3: FUSED bias + softmax + o_pair + oav (unchanged)
// ============================================================
#define FUSED_SMEM_FLOATS 27696

__global__ void __launch_bounds__(256, 2)
fused_attn_kernel(const float* __restrict__ z,
                  const float* __restrict__ Wb,
                  float* __restrict__ a_out) {
    extern __shared__ float sm[];
    float* z_sm   = sm;
    float* wb_sm  = sm + 16896;
    float* red    = sm + 18432;
    float* sm_l   = sm + 19968;
    float* p_sm   = sm + 26112;
    float* m_sm   = sm + 27648;
    float* f_sm   = sm + 27660;
    float* inv_sm = sm + 27672;

    const int bi = blockIdx.x;
    const int b = bi >> 9, i = bi & 511;
    const int tid = threadIdx.x;

    for (int idx = tid; idx < 1536; idx += 256)
        wb_sm[idx] = Wb[(idx & 127) * Hc + (idx >> 7)];
    if (tid < 12) m_sm[tid] = -3.0e38f;
    __syncthreads();

    const float4* zs4 = (const float4*)(z + (size_t)bi * Nc * CZc);

    const int jj = tid & 127;
    const int zh = tid >> 7;
    const int c0 = zh * 16;
    const int h0p = zh * 6;
    const int zq = tid & 31;
    const int hg = (tid >> 5) & 1;
    const int jp = tid >> 6;
    const int h0 = hg * 6;
    const int zc0 = zq * 4;

    float4 A[6];
#pragma unroll
    for (int hh = 0; hh < 6; hh++) A[hh] = make_float4(0.f, 0.f, 0.f, 0.f);

    const int w = tid >> 5, lane = tid & 31;

    for (int tile = 0; tile < 4; tile++) {
        const int j0 = tile * 128;

#pragma unroll 4
        for (int idx = tid; idx < 4096; idx += 256) {
            int row = idx >> 5, t = idx & 31;
            *(float4*)&z_sm[row * 132 + t * 4] =
                __ldg(&zs4[(size_t)(j0 + row) * 32 + t]);
        }
        __syncthreads();

        float bias[12];
#pragma unroll
        for (int h = 0; h < 12; h++) bias[h] = 0.f;
#pragma unroll 4
        for (int c = c0; c < c0 + 16; c++) {
            float4 zv = *(const float4*)&z_sm[jj * 132 + c * 4];
#pragma unroll
            for (int h = 0; h < 12; h++) {
                float4 wv = *(const float4*)&wb_sm[h * 128 + c * 4];
                bias[h] += zv.x*wv.x + zv.y*wv.y + zv.z*wv.z + zv.w*wv.w;
            }
        }
        {
            const int ho = 6 - h0p;
#pragma unroll
            for (int hh = 0; hh < 6; hh++)
                red[(ho + hh) * 128 + jj] = bias[ho + hh];
        }
        __syncthreads();

        float l6[6];
        {
            float sd[6];
#pragma unroll
            for (int hh = 0; hh < 6; hh++)
                sd[hh] = a_out[(((size_t)(b * Hc + h0p + hh) * Nc) + i) * Nc + j0 + jj];
#pragma unroll
            for (int hh = 0; hh < 6; hh++) {
                int h = h0p + hh;
                float l = W_Lc * (sd[hh] + bias[h] + red[h * 128 + jj]);
                sm_l[h * Nc + j0 + jj] = l;
                l6[hh] = l;
            }
        }
        __syncthreads();

        for (int h = w; h < 12; h += 8) {
            float mx = sm_l[h * Nc + j0 + lane];
            mx = fmaxf(mx, sm_l[h * Nc + j0 + lane + 32]);
            mx = fmaxf(mx, sm_l[h * Nc + j0 + lane + 64]);
            mx = fmaxf(mx, sm_l[h * Nc + j0 + lane + 96]);
#pragma unroll
            for (int off = 16; off > 0; off >>= 1)
                mx = fmaxf(mx, __shfl_xor_sync(0xffffffffu, mx, off));
            if (lane == 0) {
                float mo = m_sm[h];
                float mn = fmaxf(mo, mx);
                f_sm[h] = __expf(mo - mn);
                m_sm[h] = mn;
            }
        }
        __syncthreads();

#pragma unroll
        for (int hh = 0; hh < 6; hh++)
            p_sm[(h0p + hh) * 128 + jj] = __expf(l6[hh] - m_sm[h0p + hh]);
        __syncthreads();

        {
            float fr[6];
#pragma unroll
            for (int hh = 0; hh < 6; hh++) fr[hh] = f_sm[h0 + hh];
#pragma unroll
            for (int hh = 0; hh < 6; hh++) {
                A[hh].x *= fr[hh]; A[hh].y *= fr[hh];
                A[hh].z *= fr[hh]; A[hh].w *= fr[hh];
            }
            const int jl0 = jp * 32;
#pragma unroll 4
            for (int jl = jl0; jl < jl0 + 32; jl++) {
                float4 zv = *(const float4*)&z_sm[jl * 132 + zc0];
                float p0 = p_sm[(h0 + 0) * 128 + jl];
                float p1 = p_sm[(h0 + 1) * 128 + jl];
                float p2 = p_sm[(h0 + 2) * 128 + jl];
                float p3 = p_sm[(h0 + 3) * 128 + jl];
                float p4 = p_sm[(h0 + 4) * 128 + jl];
                float p5 = p_sm[(h0 + 5) * 128 + jl];
                A[0].x = fmaf(p0, zv.x, A[0].x); A[0].y = fmaf(p0, zv.y, A[0].y);
                A[0].z = fmaf(p0, zv.z, A[0].z); A[0].w = fmaf(p0, zv.w, A[0].w);
                A[1].x = fmaf(p1, zv.x, A[1].x); A[1].y = fmaf(p1, zv.y, A[1].y);
                A[1].z = fmaf(p1, zv.z, A[1].z); A[1].w = fmaf(p1, zv.w, A[1].w);
                A[2].x = fmaf(p2, zv.x, A[2].x); A[2].y = fmaf(p2, zv.y, A[2].y);
                A[2].z = fmaf(p2, zv.z, A[2].z); A[2].w = fmaf(p2, zv.w, A[2].w);
                A[3].x = fmaf(p3, zv.x, A[3].x); A[3].y = fmaf(p3, zv.y, A[3].y);
                A[3].z = fmaf(p3, zv.z, A[3].z); A[3].w = fmaf(p3, zv.w, A[3].w);
                A[4].x = fmaf(p4, zv.x, A[4].x); A[4].y = fmaf(p4, zv.y, A[4].y);
                A[4].z = fmaf(p4, zv.z, A[4].z); A[4].w = fmaf(p4, zv.w, A[4].w);
                A[5].x = fmaf(p5, zv.x, A[5].x); A[5].y = fmaf(p5, zv.y, A[5].y);
                A[5].z = fmaf(p5, zv.z, A[5].z); A[5].w = fmaf(p5, zv.w, A[5].w);
            }
        }
        __syncthreads();
    }

    for (int hh = w; hh < Hc; hh += 8) {
        float* p = sm_l + hh * Nc;
        float4 v[4];
#pragma unroll
        for (int t = 0; t < 4; t++)
            v[t] = *(const float4*)&p[lane * 4 + t * 128];

        float m = -3.0e38f;
#pragma unroll
        for (int t = 0; t < 4; t++)
            m = fmaxf(m, fmaxf(fmaxf(v[t].x, v[t].y), fmaxf(v[t].z, v[t].w)));
#pragma unroll
        for (int off = 16; off > 0; off >>= 1)
            m = fmaxf(m, __shfl_xor_sync(0xffffffffu, m, off));

        float ssum = 0.f;
#pragma unroll
        for (int t = 0; t < 4; t++) {
            v[t].x = __expf(v[t].x - m); v[t].y = __expf(v[t].y - m);
            v[t].z = __expf(v[t].z - m); v[t].w = __expf(v[t].w - m);
            ssum += v[t].x + v[t].y + v[t].z + v[t].w;
        }
#pragma unroll
        for (int off = 16; off > 0; off >>= 1)
            ssum += __shfl_xor_sync(0xffffffffu, ssum, off);
        float inv = 1.0f / ssum;
        if (lane == 0) inv_sm[hh] = inv;

        float* ap = a_out + (((size_t)(b * Hc + hh) * Nc) + i) * Nc;
#pragma unroll
        for (int t = 0; t < 4; t++) {
            v[t].x *= inv; v[t].y *= inv; v[t].z *= inv; v[t].w *= inv;
            *(float4*)&ap[lane * 4 + t * 128] = v[t];
            *(float4*)&p[lane * 4 + t * 128] = v[t];
        }
    }
    __syncthreads();

    if (jp > 0) {
#pragma unroll
        for (int hh = 0; hh < 6; hh++)
            *(float4*)&z_sm[(jp - 1) * 1536 + (h0 + hh) * 128 + zc0] = A[hh];
    }
    __syncthreads();
    if (jp == 0) {
#pragma unroll
        for (int hh = 0; hh < 6; hh++) {
            float4 r = A[hh];
#pragma unroll
            for (int pp = 0; pp < 3; pp++) {
                float4 o = *(const float4*)&z_sm[pp * 1536 + (h0 + hh) * 128 + zc0];
                r.x += o.x; r.y += o.y; r.z += o.z; r.w += o.w;
            }
            float iv = inv_sm[h0 + hh];
            r.x *= iv; r.y *= iv; r.z *= iv; r.w *= iv;
            *(float4*)(g_x + (size_t)bi * XD + QKVD + (h0 + hh) * CZc + zc0) = r;
        }
    }
    __syncthreads();

    if (tid < QKVD) {
        const int col = tid;
        const int h = col >> 4;
        const float* lh = &sm_l[h * Nc];
        const float* vp = g_v + (size_t)b * Nc * QKVD + col;
        float acc = 0.f;
        for (int j = 0; j < Nc; j += 16) {
            float v0 = __ldg(&vp[(size_t)(j + 0) * QKVD]);
            float v1 = __ldg(&vp[(size_t)(j + 1) * QKVD]);
            float v2 = __ldg(&vp[(size_t)(j + 2) * QKVD]);
            float v3 = __ldg(&vp[(size_t)(j + 3) * QKVD]);
            float v4 = __ldg(&vp[(size_t)(j + 4) * QKVD]);
            float v5 = __ldg(&vp[(size_t)(j + 5) * QKVD]);
            float v6 = __ldg(&vp[(size_t)(j + 6) * QKVD]);
            float v7 = __ldg(&vp[(size_t)(j + 7) * QKVD]);
            float v8 = __ldg(&vp[(size_t)(j + 8) * QKVD]);
            float v9 = __ldg(&vp[(size_t)(j + 9) * QKVD]);
            float va = __ldg(&vp[(size_t)(j + 10) * QKVD]);
            float vb = __ldg(&vp[(size_t)(j + 11) * QKVD]);
            float vc = __ldg(&vp[(size_t)(j + 12) * QKVD]);
            float vd = __ldg(&vp[(size_t)(j + 13) * QKVD]);
            float ve = __ldg(&vp[(size_t)(j + 14) * QKVD]);
            float vf = __ldg(&vp[(size_t)(j + 15) * QKVD]);
            acc = fmaf(lh[j + 0], v0, acc);  acc = fmaf(lh[j + 1], v1, acc);
            acc = fmaf(lh[j + 2], v2, acc);  acc = fmaf(lh[j + 3], v3, acc);
            acc = fmaf(lh[j + 4], v4, acc);  acc = fmaf(lh[j + 5], v5, acc);
            acc = fmaf(lh[j + 6], v6, acc);  acc = fmaf(lh[j + 7], v7, acc);
            acc = fmaf(lh[j + 8], v8, acc);  acc = fmaf(lh[j + 9], v9, acc);
            acc = fmaf(lh[j + 10], va, acc); acc = fmaf(lh[j + 11], vb, acc);
            acc = fmaf(lh[j + 12], vc, acc); acc = fmaf(lh[j + 13], vd, acc);
            acc = fmaf(lh[j + 14], ve, acc); acc = fmaf(lh[j + 15], vf, acc);
        }
        g_x[(size_t)bi * XD + col] = acc;
    }
}

// ============================================================
// Kernel 4: s_upd = X @ Wout + bout. cp.async DOUBLE-BUFFERED
// smem GEMM. block = 16 rows x 64 cols, BK=48, 128 thr,
// grid = 384. Tile t+1 prefetched (LDGSTS, no registers)
// while tile t computes; inner loop pure LDS+FFMA.
// ============================================================
#define OUT_NT (XD / 48)      // 36 k-tiles

__global__ void __launch_bounds__(128)
out_kernel(const float* __restrict__ Wout,
           const float* __restrict__ bout,
           float* __restrict__ s_upd) {
    __shared__ float Xs[2][16 * 52];     // 16 rows x 48 k (stride 52)
    __shared__ float Ws[2][48 * 64];     // 48 k x 64 cols

    const int bx = blockIdx.x;
    const int row0 = (bx / 6) * 16;
    const int col0 = (bx % 6) * 64;
    const int tid = threadIdx.x;
    const int cg = tid & 15;             // col quad: col0 + cg*4
    const int rg = tid >> 4;             // row pair: row0 + 2*rg, +1

    // per-thread prefetch shares (fixed indices)
    // Xs: 192 float4 -> idx = tid + {0,128} (second bounded)
    // Ws: 768 float4 -> idx = tid + {0,128,...,640}
    auto prefetch = [&](int t, int bufi) {
        const int k0 = t * 48;
        float* xs = Xs[bufi];
        float* ws = Ws[bufi];
#pragma unroll
        for (int u = 0; u < 2; u++) {
            int idx = tid + u * 128;
            if (idx < 192) {
                int r = idx / 12, c4 = idx % 12;
                __pipeline_memcpy_async(
                    &xs[r * 52 + c4 * 4],
                    g_x + (size_t)(row0 + r) * XD + k0 + c4 * 4, 16);
            }
        }
#pragma unroll
        for (int u = 0; u < 6; u++) {
            int idx = tid + u * 128;
            int k = idx >> 4, c4 = idx & 15;
            __pipeline_memcpy_async(
                &ws[k * 64 + c4 * 4],
                Wout + (size_t)(k0 + k) * CSc + col0 + c4 * 4, 16);
        }
    };

    float4 a0 = {0.f,0.f,0.f,0.f};
    float4 a1 = {0.f,0.f,0.f,0.f};

    prefetch(0, 0);
    __pipeline_commit();

    for (int t = 0; t < OUT_NT; t++) {
        if (t + 1 < OUT_NT) {
            prefetch(t + 1, (t + 1) & 1);
            __pipeline_commit();
            __pipeline_wait_prior(1);
        } else {
            __pipeline_wait_prior(0);
        }
        __syncthreads();

        const float* xs = Xs[t & 1];
        const float* ws = Ws[t & 1];
#pragma unroll 8
        for (int k = 0; k < 48; k++) {
            float x0 = xs[(2 * rg + 0) * 52 + k];
            float x1 = xs[(2 * rg + 1) * 52 + k];
            float4 w = *(const float4*)&ws[k * 64 + cg * 4];
            a0.x = fmaf(x0, w.x, a0.x); a0.y = fmaf(x0, w.y, a0.y);
            a0.z = fmaf(x0, w.z, a0.z); a0.w = fmaf(x0, w.w, a0.w);
            a1.x = fmaf(x1, w.x, a1.x); a1.y = fmaf(x1, w.y, a1.y);
            a1.z = fmaf(x1, w.z, a1.z); a1.w = fmaf(x1, w.w, a1.w);
        }
        __syncthreads();
    }

    float4 bb = *(const float4*)(bout + col0 + cg * 4);
    a0.x += bb.x; a0.y += bb.y; a0.z += bb.z; a0.w += bb.w;
    a1.x += bb.x; a1.y += bb.y; a1.z += bb.z; a1.w += bb.w;
    *(float4*)(s_upd + (size_t)(row0 + 2 * rg + 0) * CSc + col0 + cg * 4) = a0;
    *(float4*)(s_upd + (size_t)(row0 + 2 * rg + 1) * CSc + col0 + cg * 4) = a1;
}

// ============================================================
extern "C" void kernel_launch(void* const* d_in, const int* in_sizes, int n_in,
                              void* d_out, int out_size) {
    const float* s    = (const float*)d_in[0];
    const float* z    = (const float*)d_in[1];
    // d_in[2] = mask: all-True in this problem; (1-sq) term is identically 0.
    const float* Wq   = (const float*)d_in[3];
    const float* Wkv  = (const float*)d_in[4];
    const float* Wb   = (const float*)d_in[5];
    const float* Wout = (const float*)d_in[6];
    const float* bout = (const float*)d_in[7];

    float* out   = (float*)d_out;
    float* s_upd = out;                       // (B,N,CS)
    float* a_out = out + S_UPD_ELEMS;         // (B,H,N,N): a_sd -> a

    cudaFuncSetAttribute(fused_attn_kernel,
                         cudaFuncAttributeMaxDynamicSharedMemorySize,
                         FUSED_SMEM_FLOATS * sizeof(float));

    qkv_kernel<<<(Bc * Nc) / 4, 288>>>(s, Wq, Wkv);
    qk_kernel<<<768, 256>>>(a_out);
    fused_attn_kernel<<<1024, 256, FUSED_SMEM_FLOATS * sizeof(float)>>>(z, Wb, a_out);
    out_kernel<<<384, 128>>>(Wout, bout, s_upd);
}

// round 17
// speedup vs baseline: 2.7814x; 1.0804x over previous
#include <cuda_runtime.h>
#include <cuda_pipeline.h>

#define Bc 2
#define Nc 512
#define CSc 384
#define CZc 128
#define CHc 16
#define Hc 12
#define QKVD 192           // H*CH
#define XD 1728            // H*(CZ+CH)
#define S_UPD_ELEMS (Bc*Nc*CSc)   // 393216
#define W_Lc 0.7071067811865476f

// ---- scratch (device globals; no allocation allowed) ----
__device__ float g_q[Bc*Nc*QKVD];
__device__ float g_k[Bc*Nc*QKVD];
__device__ float g_v[Bc*Nc*QKVD];
__device__ float g_x[Bc*Nc*XD];

// ============================================================
// Kernel 1: q/k/v projection. cp.async double-buffered smem
// GEMM (same template as out_kernel). 1024 x 576 output,
// block = 16 rows x 64 cols, BK=48, 128 thr, grid = 64*9=576.
// Col tiles 0-2 -> Wq (q), 3-8 -> Wkv (k/v scatter).
// ============================================================
#define QKV_NT (CSc / 48)     // 8 k-tiles

__global__ void __launch_bounds__(128)
qkv_kernel(const float* __restrict__ s,
           const float* __restrict__ Wq,
           const float* __restrict__ Wkv) {
    __shared__ float Xs[2][16 * 52];     // 16 rows x 48 k (stride 52)
    __shared__ float Ws[2][48 * 64];     // 48 k x 64 cols

    const int bx = blockIdx.x;
    const int row0 = (bx / 9) * 16;
    const int colt = bx % 9;
    const int col0 = colt * 64;
    const bool is_q = (colt < 3);
    const float* W = is_q ? (Wq + col0) : (Wkv + (col0 - QKVD));
    const int ld = is_q ? QKVD : 384;

    const int tid = threadIdx.x;
    const int cg = tid & 15;             // col quad within 64
    const int rg = tid >> 4;             // row pair: 2*rg, 2*rg+1

    auto prefetch = [&](int t, int bufi) {
        const int k0 = t * 48;
        float* xs = Xs[bufi];
        float* ws = Ws[bufi];
#pragma unroll
        for (int u = 0; u < 2; u++) {
            int idx = tid + u * 128;
            if (idx < 192) {
                int r = idx / 12, c4 = idx % 12;
                __pipeline_memcpy_async(
                    &xs[r * 52 + c4 * 4],
                    s + (size_t)(row0 + r) * CSc + k0 + c4 * 4, 16);
            }
        }
#pragma unroll
        for (int u = 0; u < 6; u++) {
            int idx = tid + u * 128;
            int k = idx >> 4, c4 = idx & 15;
            __pipeline_memcpy_async(
                &ws[k * 64 + c4 * 4],
                W + (size_t)(k0 + k) * ld + c4 * 4, 16);
        }
    };

    float4 a0 = {0.f,0.f,0.f,0.f};
    float4 a1 = {0.f,0.f,0.f,0.f};

    prefetch(0, 0);
    __pipeline_commit();

    for (int t = 0; t < QKV_NT; t++) {
        if (t + 1 < QKV_NT) {
            prefetch(t + 1, (t + 1) & 1);
            __pipeline_commit();
            __pipeline_wait_prior(1);
        } else {
            __pipeline_wait_prior(0);
        }
        __syncthreads();

        const float* xs = Xs[t & 1];
        const float* ws = Ws[t & 1];
#pragma unroll 8
        for (int k = 0; k < 48; k++) {
            float x0 = xs[(2 * rg + 0) * 52 + k];
            float x1 = xs[(2 * rg + 1) * 52 + k];
            float4 w = *(const float4*)&ws[k * 64 + cg * 4];
            a0.x = fmaf(x0, w.x, a0.x); a0.y = fmaf(x0, w.y, a0.y);
            a0.z = fmaf(x0, w.z, a0.z); a0.w = fmaf(x0, w.w, a0.w);
            a1.x = fmaf(x1, w.x, a1.x); a1.y = fmaf(x1, w.y, a1.y);
            a1.z = fmaf(x1, w.z, a1.z); a1.w = fmaf(x1, w.w, a1.w);
        }
        __syncthreads();
    }

    const int r0 = row0 + 2 * rg;
    if (is_q) {
        *(float4*)(g_q + (size_t)(r0 + 0) * QKVD + col0 + cg * 4) = a0;
        *(float4*)(g_q + (size_t)(r0 + 1) * QKVD + col0 + cg * 4) = a1;
    } else {
        int c2 = col0 - QKVD + cg * 4;
        int h = c2 >> 5;
        int within = c2 & 31;
        float* dst = (within < CHc) ? g_k : g_v;
        int cc = h * CHc + (within & 15);
        *(float4*)(dst + (size_t)(r0 + 0) * QKVD + cc) = a0;
        *(float4*)(dst + (size_t)(r0 + 1) * QKVD + cc) = a1;
    }
}

// ============================================================
// Kernel 2: a_sd = (q.k)/4 -> a_out (unchanged)
// ============================================================
__global__ void __launch_bounds__(256)
qk_kernel(float* __restrict__ a_out) {
    __shared__ float q_sm[32 * 16];
    __shared__ float k_sm[16 * 260];

    const int bx = blockIdx.x;
    const int b   = bx / 384;
    const int rem = bx % 384;
    const int h   = rem >> 5;
    const int it  = (rem & 31) >> 1;
    const int jt  = rem & 1;
    const int i0 = it * 32, j0 = jt * 256;
    const int tid = threadIdx.x;

    for (int idx = tid; idx < 512; idx += 256) {
        int ii = idx >> 4, c = idx & 15;
        q_sm[idx] = g_q[((size_t)(b * Nc + i0 + ii)) * QKVD + h * CHc + c] * 0.25f;
    }
    for (int idx = tid; idx < 4096; idx += 256) {
        int j = idx >> 4, c = idx & 15;
        k_sm[c * 260 + j] = g_k[((size_t)(b * Nc + j0 + j)) * QKVD + h * CHc + c];
    }
    __syncthreads();

    const int jq = tid & 63;
    const int ig = tid >> 6;
    float4 acc[8];
#pragma unroll
    for (int r = 0; r < 8; r++) acc[r] = make_float4(0.f, 0.f, 0.f, 0.f);

#pragma unroll
    for (int c = 0; c < 16; c++) {
        float4 kv = *(const float4*)&k_sm[c * 260 + jq * 4];
#pragma unroll
        for (int r = 0; r < 8; r++) {
            float qv = q_sm[(ig * 8 + r) * 16 + c];
            acc[r].x = fmaf(qv, kv.x, acc[r].x);
            acc[r].y = fmaf(qv, kv.y, acc[r].y);
            acc[r].z = fmaf(qv, kv.z, acc[r].z);
            acc[r].w = fmaf(qv, kv.w, acc[r].w);
        }
    }
#pragma unroll
    for (int r = 0; r < 8; r++) {
        int i = i0 + ig * 8 + r;
        *(float4*)&a_out[(((size_t)(b * Hc + h) * Nc) + i) * Nc + j0 + jq * 4] = acc[r];
    }
}

// ============================================================
// Kernel 3: FUSED bias + softmax + o_pair + oav.
// CHANGE: z-tile fills via cp.async (fire-and-forget), tile 0
// issued before Wb staging; next tile issued right after the
// last z_sm reader's barrier.
// ============================================================
#define FUSED_SMEM_FLOATS 27696

__global__ void __launch_bounds__(256, 2)
fused_attn_kernel(const float* __restrict__ z,
                  const float* __restrict__ Wb,
                  float* __restrict__ a_out) {
    extern __shared__ float sm[];
    float* z_sm   = sm;
    float* wb_sm  = sm + 16896;
    float* red    = sm + 18432;
    float* sm_l   = sm + 19968;
    float* p_sm   = sm + 26112;
    float* m_sm   = sm + 27648;
    float* f_sm   = sm + 27660;
    float* inv_sm = sm + 27672;

    const int bi = blockIdx.x;
    const int b = bi >> 9, i = bi & 511;
    const int tid = threadIdx.x;

    const float4* zs4 = (const float4*)(z + (size_t)bi * Nc * CZc);

    auto issue_z = [&](int tile) {
        const int j0 = tile * 128;
        for (int idx = tid; idx < 4096; idx += 256) {
            int row = idx >> 5, t = idx & 31;
            __pipeline_memcpy_async(&z_sm[row * 132 + t * 4],
                                    &zs4[(size_t)(j0 + row) * 32 + t], 16);
        }
        __pipeline_commit();
    };

    issue_z(0);   // overlap tile-0 fill with Wb staging

    for (int idx = tid; idx < 1536; idx += 256)
        wb_sm[idx] = Wb[(idx & 127) * Hc + (idx >> 7)];
    if (tid < 12) m_sm[tid] = -3.0e38f;
    __syncthreads();

    const int jj = tid & 127;
    const int zh = tid >> 7;
    const int c0 = zh * 16;
    const int h0p = zh * 6;
    const int zq = tid & 31;
    const int hg = (tid >> 5) & 1;
    const int jp = tid >> 6;
    const int h0 = hg * 6;
    const int zc0 = zq * 4;

    float4 A[6];
#pragma unroll
    for (int hh = 0; hh < 6; hh++) A[hh] = make_float4(0.f, 0.f, 0.f, 0.f);

    const int w = tid >> 5, lane = tid & 31;

    for (int tile = 0; tile < 4; tile++) {
        const int j0 = tile * 128;

        __pipeline_wait_prior(0);
        __syncthreads();            // z tile visible to all threads

        float bias[12];
#pragma unroll
        for (int h = 0; h < 12; h++) bias[h] = 0.f;
#pragma unroll 4
        for (int c = c0; c < c0 + 16; c++) {
            float4 zv = *(const float4*)&z_sm[jj * 132 + c * 4];
#pragma unroll
            for (int h = 0; h < 12; h++) {
                float4 wv = *(const float4*)&wb_sm[h * 128 + c * 4];
                bias[h] += zv.x*wv.x + zv.y*wv.y + zv.z*wv.z + zv.w*wv.w;
            }
        }
        {
            const int ho = 6 - h0p;
#pragma unroll
            for (int hh = 0; hh < 6; hh++)
                red[(ho + hh) * 128 + jj] = bias[ho + hh];
        }
        __syncthreads();

        float l6[6];
        {
            float sd[6];
#pragma unroll
            for (int hh = 0; hh < 6; hh++)
                sd[hh] = a_out[(((size_t)(b * Hc + h0p + hh) * Nc) + i) * Nc + j0 + jj];
#pragma unroll
            for (int hh = 0; hh < 6; hh++) {
                int h = h0p + hh;
                float l = W_Lc * (sd[hh] + bias[h] + red[h * 128 + jj]);
                sm_l[h * Nc + j0 + jj] = l;
                l6[hh] = l;
            }
        }
        __syncthreads();

        for (int h = w; h < 12; h += 8) {
            float mx = sm_l[h * Nc + j0 + lane];
            mx = fmaxf(mx, sm_l[h * Nc + j0 + lane + 32]);
            mx = fmaxf(mx, sm_l[h * Nc + j0 + lane + 64]);
            mx = fmaxf(mx, sm_l[h * Nc + j0 + lane + 96]);
#pragma unroll
            for (int off = 16; off > 0; off >>= 1)
                mx = fmaxf(mx, __shfl_xor_sync(0xffffffffu, mx, off));
            if (lane == 0) {
                float mo = m_sm[h];
                float mn = fmaxf(mo, mx);
                f_sm[h] = __expf(mo - mn);
                m_sm[h] = mn;
            }
        }
        __syncthreads();

#pragma unroll
        for (int hh = 0; hh < 6; hh++)
            p_sm[(h0p + hh) * 128 + jj] = __expf(l6[hh] - m_sm[h0p + hh]);
        __syncthreads();

        {
            float fr[6];
#pragma unroll
            for (int hh = 0; hh < 6; hh++) fr[hh] = f_sm[h0 + hh];
#pragma unroll
            for (int hh = 0; hh < 6; hh++) {
                A[hh].x *= fr[hh]; A[hh].y *= fr[hh];
                A[hh].z *= fr[hh]; A[hh].w *= fr[hh];
            }
            const int jl0 = jp * 32;
#pragma unroll 4
            for (int jl = jl0; jl < jl0 + 32; jl++) {
                float4 zv = *(const float4*)&z_sm[jl * 132 + zc0];
                float p0 = p_sm[(h0 + 0) * 128 + jl];
                float p1 = p_sm[(h0 + 1) * 128 + jl];
                float p2 = p_sm[(h0 + 2) * 128 + jl];
                float p3 = p_sm[(h0 + 3) * 128 + jl];
                float p4 = p_sm[(h0 + 4) * 128 + jl];
                float p5 = p_sm[(h0 + 5) * 128 + jl];
                A[0].x = fmaf(p0, zv.x, A[0].x); A[0].y = fmaf(p0, zv.y, A[0].y);
                A[0].z = fmaf(p0, zv.z, A[0].z); A[0].w = fmaf(p0, zv.w, A[0].w);
                A[1].x = fmaf(p1, zv.x, A[1].x); A[1].y = fmaf(p1, zv.y, A[1].y);
                A[1].z = fmaf(p1, zv.z, A[1].z); A[1].w = fmaf(p1, zv.w, A[1].w);
                A[2].x = fmaf(p2, zv.x, A[2].x); A[2].y = fmaf(p2, zv.y, A[2].y);
                A[2].z = fmaf(p2, zv.z, A[2].z); A[2].w = fmaf(p2, zv.w, A[2].w);
                A[3].x = fmaf(p3, zv.x, A[3].x); A[3].y = fmaf(p3, zv.y, A[3].y);
                A[3].z = fmaf(p3, zv.z, A[3].z); A[3].w = fmaf(p3, zv.w, A[3].w);
                A[4].x = fmaf(p4, zv.x, A[4].x); A[4].y = fmaf(p4, zv.y, A[4].y);
                A[4].z = fmaf(p4, zv.z, A[4].z); A[4].w = fmaf(p4, zv.w, A[4].w);
                A[5].x = fmaf(p5, zv.x, A[5].x); A[5].y = fmaf(p5, zv.y, A[5].y);
                A[5].z = fmaf(p5, zv.z, A[5].z); A[5].w = fmaf(p5, zv.w, A[5].w);
            }
        }
        __syncthreads();            // all z_sm readers done
        if (tile < 3) issue_z(tile + 1);
    }

    for (int hh = w; hh < Hc; hh += 8) {
        float* p = sm_l + hh * Nc;
        float4 v[4];
#pragma unroll
        for (int t = 0; t < 4; t++)
            v[t] = *(const float4*)&p[lane * 4 + t * 128];

        float m = -3.0e38f;
#pragma unroll
        for (int t = 0; t < 4; t++)
            m = fmaxf(m, fmaxf(fmaxf(v[t].x, v[t].y), fmaxf(v[t].z, v[t].w)));
#pragma unroll
        for (int off = 16; off > 0; off >>= 1)
            m = fmaxf(m, __shfl_xor_sync(0xffffffffu, m, off));

        float ssum = 0.f;
#pragma unroll
        for (int t = 0; t < 4; t++) {
            v[t].x = __expf(v[t].x - m); v[t].y = __expf(v[t].y - m);
            v[t].z = __expf(v[t].z - m); v[t].w = __expf(v[t].w - m);
            ssum += v[t].x + v[t].y + v[t].z + v[t].w;
        }
#pragma unroll
        for (int off = 16; off > 0; off >>= 1)
            ssum += __shfl_xor_sync(0xffffffffu, ssum, off);
        float inv = 1.0f / ssum;
        if (lane == 0) inv_sm[hh] = inv;

        float* ap = a_out + (((size_t)(b * Hc + hh) * Nc) + i) * Nc;
#pragma unroll
        for (int t = 0; t < 4; t++) {
            v[t].x *= inv; v[t].y *= inv; v[t].z *= inv; v[t].w *= inv;
            *(float4*)&ap[lane * 4 + t * 128] = v[t];
            *(float4*)&p[lane * 4 + t * 128] = v[t];
        }
    }
    __syncthreads();

    if (jp > 0) {
#pragma unroll
        for (int hh = 0; hh < 6; hh++)
            *(float4*)&z_sm[(jp - 1) * 1536 + (h0 + hh) * 128 + zc0] = A[hh];
    }
    __syncthreads();
    if (jp == 0) {
#pragma unroll
        for (int hh = 0; hh < 6; hh++) {
            float4 r = A[hh];
#pragma unroll
            for (int pp = 0; pp < 3; pp++) {
                float4 o = *(const float4*)&z_sm[pp * 1536 + (h0 + hh) * 128 + zc0];
                r.x += o.x; r.y += o.y; r.z += o.z; r.w += o.w;
            }
            float iv = inv_sm[h0 + hh];
            r.x *= iv; r.y *= iv; r.z *= iv; r.w *= iv;
            *(float4*)(g_x + (size_t)bi * XD + QKVD + (h0 + hh) * CZc + zc0) = r;
        }
    }
    __syncthreads();

    if (tid < QKVD) {
        const int col = tid;
        const int h = col >> 4;
        const float* lh = &sm_l[h * Nc];
        const float* vp = g_v + (size_t)b * Nc * QKVD + col;
        float acc = 0.f;
        for (int j = 0; j < Nc; j += 16) {
            float v0 = __ldg(&vp[(size_t)(j + 0) * QKVD]);
            float v1 = __ldg(&vp[(size_t)(j + 1) * QKVD]);
            float v2 = __ldg(&vp[(size_t)(j + 2) * QKVD]);
            float v3 = __ldg(&vp[(size_t)(j + 3) * QKVD]);
            float v4 = __ldg(&vp[(size_t)(j + 4) * QKVD]);
            float v5 = __ldg(&vp[(size_t)(j + 5) * QKVD]);
            float v6 = __ldg(&vp[(size_t)(j + 6) * QKVD]);
            float v7 = __ldg(&vp[(size_t)(j + 7) * QKVD]);
            float v8 = __ldg(&vp[(size_t)(j + 8) * QKVD]);
            float v9 = __ldg(&vp[(size_t)(j + 9) * QKVD]);
            float va = __ldg(&vp[(size_t)(j + 10) * QKVD]);
            float vb = __ldg(&vp[(size_t)(j + 11) * QKVD]);
            float vc = __ldg(&vp[(size_t)(j + 12) * QKVD]);
            float vd = __ldg(&vp[(size_t)(j + 13) * QKVD]);
            float ve = __ldg(&vp[(size_t)(j + 14) * QKVD]);
            float vf = __ldg(&vp[(size_t)(j + 15) * QKVD]);
            acc = fmaf(lh[j + 0], v0, acc);  acc = fmaf(lh[j + 1], v1, acc);
            acc = fmaf(lh[j + 2], v2, acc);  acc = fmaf(lh[j + 3], v3, acc);
            acc = fmaf(lh[j + 4], v4, acc);  acc = fmaf(lh[j + 5], v5, acc);
            acc = fmaf(lh[j + 6], v6, acc);  acc = fmaf(lh[j + 7], v7, acc);
            acc = fmaf(lh[j + 8], v8, acc);  acc = fmaf(lh[j + 9], v9, acc);
            acc = fmaf(lh[j + 10], va, acc); acc = fmaf(lh[j + 11], vb, acc);
            acc = fmaf(lh[j + 12], vc, acc); acc = fmaf(lh[j + 13], vd, acc);
            acc = fmaf(lh[j + 14], ve, acc); acc = fmaf(lh[j + 15], vf, acc);
        }
        g_x[(size_t)bi * XD + col] = acc;
    }
}

// ============================================================
// Kernel 4: s_upd = X @ Wout + bout (unchanged, 72us)
// ============================================================
#define OUT_NT (XD / 48)      // 36 k-tiles

__global__ void __launch_bounds__(128)
out_kernel(const float* __restrict__ Wout,
           const float* __restrict__ bout,
           float* __restrict__ s_upd) {
    __shared__ float Xs[2][16 * 52];
    __shared__ float Ws[2][48 * 64];

    const int bx = blockIdx.x;
    const int row0 = (bx / 6) * 16;
    const int col0 = (bx % 6) * 64;
    const int tid = threadIdx.x;
    const int cg = tid & 15;
    const int rg = tid >> 4;

    auto prefetch = [&](int t, int bufi) {
        const int k0 = t * 48;
        float* xs = Xs[bufi];
        float* ws = Ws[bufi];
#pragma unroll
        for (int u = 0; u < 2; u++) {
            int idx = tid + u * 128;
            if (idx < 192) {
                int r = idx / 12, c4 = idx % 12;
                __pipeline_memcpy_async(
                    &xs[r * 52 + c4 * 4],
                    g_x + (size_t)(row0 + r) * XD + k0 + c4 * 4, 16);
            }
        }
#pragma unroll
        for (int u = 0; u < 6; u++) {
            int idx = tid + u * 128;
            int k = idx >> 4, c4 = idx & 15;
            __pipeline_memcpy_async(
                &ws[k * 64 + c4 * 4],
                Wout + (size_t)(k0 + k) * CSc + col0 + c4 * 4, 16);
        }
    };

    float4 a0 = {0.f,0.f,0.f,0.f};
    float4 a1 = {0.f,0.f,0.f,0.f};

    prefetch(0, 0);
    __pipeline_commit();

    for (int t = 0; t < OUT_NT; t++) {
        if (t + 1 < OUT_NT) {
            prefetch(t + 1, (t + 1) & 1);
            __pipeline_commit();
            __pipeline_wait_prior(1);
        } else {
            __pipeline_wait_prior(0);
        }
        __syncthreads();

        const float* xs = Xs[t & 1];
        const float* ws = Ws[t & 1];
#pragma unroll 8
        for (int k = 0; k < 48; k++) {
            float x0 = xs[(2 * rg + 0) * 52 + k];
            float x1 = xs[(2 * rg + 1) * 52 + k];
            float4 w = *(const float4*)&ws[k * 64 + cg * 4];
            a0.x = fmaf(x0, w.x, a0.x); a0.y = fmaf(x0, w.y, a0.y);
            a0.z = fmaf(x0, w.z, a0.z); a0.w = fmaf(x0, w.w, a0.w);
            a1.x = fmaf(x1, w.x, a1.x); a1.y = fmaf(x1, w.y, a1.y);
            a1.z = fmaf(x1, w.z, a1.z); a1.w = fmaf(x1, w.w, a1.w);
        }
        __syncthreads();
    }

    float4 bb = *(const float4*)(bout + col0 + cg * 4);
    a0.x += bb.x; a0.y += bb.y; a0.z += bb.z; a0.w += bb.w;
    a1.x += bb.x; a1.y += bb.y; a1.z += bb.z; a1.w += bb.w;
    *(float4*)(s_upd + (size_t)(row0 + 2 * rg + 0) * CSc + col0 + cg * 4) = a0;
    *(float4*)(s_upd + (size_t)(row0 + 2 * rg + 1) * CSc + col0 + cg * 4) = a1;
}

// ============================================================
extern "C" void kernel_launch(void* const* d_in, const int* in_sizes, int n_in,
                              void* d_out, int out_size) {
    const float* s    = (const float*)d_in[0];
    const float* z    = (const float*)d_in[1];
    // d_in[2] = mask: all-True in this problem; (1-sq) term is identically 0.
    const float* Wq   = (const float*)d_in[3];
    const float* Wkv  = (const float*)d_in[4];
    const float* Wb   = (const float*)d_in[5];
    const float* Wout = (const float*)d_in[6];
    const float* bout = (const float*)d_in[7];

    float* out   = (float*)d_out;
    float* s_upd = out;                       // (B,N,CS)
    float* a_out = out + S_UPD_ELEMS;         // (B,H,N,N): a_sd -> a

    cudaFuncSetAttribute(fused_attn_kernel,
                         cudaFuncAttributeMaxDynamicSharedMemorySize,
                         FUSED_SMEM_FLOATS * sizeof(float));

    qkv_kernel<<<576, 128>>>(s, Wq, Wkv);
    qk_kernel<<<768, 256>>>(a_out);
    fused_attn_kernel<<<1024, 256, FUSED_SMEM_FLOATS * sizeof(float)>>>(z, Wb, a_out);
    out_kernel<<<384, 128>>>(Wout, bout, s_upd);
}